// round 8
// baseline (speedup 1.0000x reference)
#include <cuda_runtime.h>
#include <math.h>
#include <stdint.h>

#define BB 512
#define SS 128
#define EE 300
#define LL 2
#define HH 300
#define FCIN 1800   // E*(1+L)*2
#define CROWS 16

// ---------------- device scratch (no allocation allowed) ----------------
__device__ float g_s1[BB*SS*EE];
__device__ float g_s2[BB*SS*EE];
__device__ float g_f1[BB*SS*EE];
__device__ float g_f2[BB*SS*EE];
__device__ float g_o1[BB*SS*EE];
__device__ float g_o2[BB*SS*EE];
__device__ float g_A [BB*SS*SS];
__device__ float g_w1[BB*SS];
__device__ float g_w2[BB*SS];
__device__ float g_v1[BB*SS];
__device__ float g_v2[BB*SS];
__device__ float g_x [BB*FCIN];
__device__ float g_h [BB*HH];

__device__ __forceinline__ float tanh_fast(float x) {
    float r; asm("tanh.approx.f32 %0, %1;" : "=f"(r) : "f"(x)); return r;
}
__device__ __forceinline__ uint32_t to_tf32(float x) {
    uint32_t r; asm("cvt.rna.tf32.f32 %0, %1;" : "=r"(r) : "f"(x)); return r;
}
#define MMA_TF32(C, A, B) \
    asm volatile("mma.sync.aligned.m16n8k8.row.col.f32.tf32.tf32.f32 " \
        "{%0,%1,%2,%3}, {%4,%5,%6,%7}, {%8,%9}, {%0,%1,%2,%3};" \
        : "+f"((C)[0]), "+f"((C)[1]), "+f"((C)[2]), "+f"((C)[3]) \
        : "r"((A)[0]), "r"((A)[1]), "r"((A)[2]), "r"((A)[3]), \
          "r"((B)[0]), "r"((B)[1]))

// ---------------- embedding gather + masks + fused mean(slot0) ----------------
__global__ __launch_bounds__(256) void k_gather(const int* __restrict__ seq1,
                                                const int* __restrict__ seq2,
                                                const float* __restrict__ emb) {
    __shared__ float msum[2][EE];
    int b = blockIdx.x;
    int tid = threadIdx.x;
    int warp = tid >> 5, lane = tid & 31;
    for (int i = tid; i < 2*EE; i += 256) ((float*)msum)[i] = 0.f;
    for (int i = tid; i < SS; i += 256) {
        g_v1[b*SS+i] = (seq1[b*SS+i] != 0) ? 1.f : 0.f;
        g_v2[b*SS+i] = (seq2[b*SS+i] != 0) ? 1.f : 0.f;
    }
    __syncthreads();
    for (int idx = warp; idx < 2*SS; idx += 8) {
        int s = idx >> 1, sel = idx & 1;
        int tok = sel ? seq2[b*SS+s] : seq1[b*SS+s];
        const float4* src = (const float4*)(emb + (long)tok*EE);
        float4* dst = (float4*)((sel ? g_s2 : g_s1) + (b*SS+s)*EE);
        for (int j = lane; j < EE/4; j += 32) {
            float4 v = src[j];
            dst[j] = v;
            atomicAdd(&msum[sel][4*j+0], v.x);
            atomicAdd(&msum[sel][4*j+1], v.y);
            atomicAdd(&msum[sel][4*j+2], v.z);
            atomicAdd(&msum[sel][4*j+3], v.w);
        }
    }
    __syncthreads();
    for (int e = tid; e < EE; e += 256) {
        g_x[b*FCIN + e]        = msum[0][e]*(1.f/SS);
        g_x[b*FCIN + 3*EE + e] = msum[1][e]*(1.f/SS);
    }
}

// ---------------- zero mean slots for layer l (conv accumulates atomically) ----
__global__ void k_zx(int l) {
    int i = blockIdx.x*256 + threadIdx.x;
    if (i >= BB*2*EE) return;
    int b = i / (2*EE);
    int r = i % (2*EE);
    int half = r / EE, e = r % EE;
    int slot = half ? (4+l) : (1+l);
    g_x[b*FCIN + slot*EE + e] = 0.f;
}

// ---------------- match-score, tensor-core tf32 ----------------
// mode=0: s1/s2 -> store A     mode=1: o1/o2 -> w1 (row sums), w2 (col sums)
#define MPAD 36
#define MCH 10      // ceil(300/32)
__global__ __launch_bounds__(256) void k_match(int mode) {
    extern __shared__ float sm[];
    float* Xs = sm;                       // [2][128][36]
    float* Ys = Xs + 2*SS*MPAD;           // [2][128][36]
    float* n1s = Ys + 2*SS*MPAD;          // [128]
    float* n2s = n1s + SS;                // [128]
    float* rowbuf = n2s + SS;             // [4][128]
    float* colbuf = rowbuf + 4*SS;        // [2][128]

    int b = blockIdx.x;
    const float* X = (mode ? g_o1 : g_s1) + b*SS*EE;
    const float* Y = (mode ? g_o2 : g_s2) + b*SS*EE;
    int tid = threadIdx.x;
    int lane = tid & 31, wid = tid >> 5;
    int g = lane >> 2, tig = lane & 3;
    int wm = wid & 1, wn = wid >> 1;

    int lr = tid >> 1, lh = tid & 1;
    const float* Xr = X + lr*EE + lh*16;
    const float* Yr = Y + lr*EE + lh*16;
    float mvx = g_v1[b*SS + lr];
    float mvy = g_v2[b*SS + lr];
    float nx = 0.f, ny = 0.f;
    float4 vx[4], vy[4];

#define FETCH(c) do { \
    int kb = (c)*32; \
    _Pragma("unroll") for (int j = 0; j < 4; j++) { \
        int k = kb + lh*16 + 4*j; \
        if (k < EE) { vx[j] = *(const float4*)(Xr + kb + 4*j); \
                      vy[j] = *(const float4*)(Yr + kb + 4*j); } \
        else { vx[j] = make_float4(0.f,0.f,0.f,0.f); vy[j] = vx[j]; } \
    } } while(0)

#define STBUF(buf) do { \
    float* xd = Xs + (buf)*SS*MPAD + lr*MPAD + lh*16; \
    float* yd = Ys + (buf)*SS*MPAD + lr*MPAD + lh*16; \
    _Pragma("unroll") for (int j = 0; j < 4; j++) { \
        float x0=vx[j].x*mvx, x1=vx[j].y*mvx, x2=vx[j].z*mvx, x3=vx[j].w*mvx; \
        float y0=vy[j].x*mvy, y1=vy[j].y*mvy, y2=vy[j].z*mvy, y3=vy[j].w*mvy; \
        nx += x0*x0+x1*x1+x2*x2+x3*x3; \
        ny += y0*y0+y1*y1+y2*y2+y3*y3; \
        ((uint32_t*)xd)[4*j+0]=to_tf32(x0); ((uint32_t*)xd)[4*j+1]=to_tf32(x1); \
        ((uint32_t*)xd)[4*j+2]=to_tf32(x2); ((uint32_t*)xd)[4*j+3]=to_tf32(x3); \
        ((uint32_t*)yd)[4*j+0]=to_tf32(y0); ((uint32_t*)yd)[4*j+1]=to_tf32(y1); \
        ((uint32_t*)yd)[4*j+2]=to_tf32(y2); ((uint32_t*)yd)[4*j+3]=to_tf32(y3); \
    } } while(0)

    float acc[4][4][4];
#pragma unroll
    for (int mt = 0; mt < 4; mt++)
#pragma unroll
        for (int nt = 0; nt < 4; nt++)
#pragma unroll
            for (int q = 0; q < 4; q++) acc[mt][nt][q] = 0.f;

    FETCH(0); STBUF(0);
    __syncthreads();

    for (int c = 0; c < MCH; c++) {
        int cur = c & 1;
        if (c + 1 < MCH) FETCH(c+1);
        const uint32_t* xb = (const uint32_t*)(Xs + cur*SS*MPAD);
        const uint32_t* yb = (const uint32_t*)(Ys + cur*SS*MPAD);
#pragma unroll
        for (int ks = 0; ks < 4; ks++) {
            int kk = ks*8;
            uint32_t a[4][4], bf[4][2];
#pragma unroll
            for (int mt = 0; mt < 4; mt++) {
                int row = wm*64 + mt*16 + g;
                a[mt][0] = xb[row*MPAD + kk + tig];
                a[mt][1] = xb[(row+8)*MPAD + kk + tig];
                a[mt][2] = xb[row*MPAD + kk + tig + 4];
                a[mt][3] = xb[(row+8)*MPAD + kk + tig + 4];
            }
#pragma unroll
            for (int nt = 0; nt < 4; nt++) {
                int cr = wn*32 + nt*8 + g;
                bf[nt][0] = yb[cr*MPAD + kk + tig];
                bf[nt][1] = yb[cr*MPAD + kk + tig + 4];
            }
#pragma unroll
            for (int mt = 0; mt < 4; mt++)
#pragma unroll
                for (int nt = 0; nt < 4; nt++)
                    MMA_TF32(acc[mt][nt], a[mt], bf[nt]);
        }
        if (c + 1 < MCH) STBUF(cur ^ 1);
        __syncthreads();
    }

    nx += __shfl_xor_sync(0xffffffffu, nx, 1);
    ny += __shfl_xor_sync(0xffffffffu, ny, 1);
    if (lh == 0) { n1s[lr] = nx; n2s[lr] = ny; }
    __syncthreads();

    if (mode == 0) {
        float* Ao = g_A + b*SS*SS;
#pragma unroll
        for (int mt = 0; mt < 4; mt++) {
            int row = wm*64 + mt*16 + g;
            float nr0 = n1s[row], nr1 = n1s[row+8];
#pragma unroll
            for (int nt = 0; nt < 4; nt++) {
                int col = wn*32 + nt*8 + 2*tig;
                float nc0 = n2s[col], nc1 = n2s[col+1];
                float d00 = sqrtf(fmaxf(nr0 + nc0 - 2.f*acc[mt][nt][0], 0.f));
                float d01 = sqrtf(fmaxf(nr0 + nc1 - 2.f*acc[mt][nt][1], 0.f));
                float d10 = sqrtf(fmaxf(nr1 + nc0 - 2.f*acc[mt][nt][2], 0.f));
                float d11 = sqrtf(fmaxf(nr1 + nc1 - 2.f*acc[mt][nt][3], 0.f));
                *(float2*)(Ao + row*SS + col)     = make_float2(1.f/(1.f+d00), 1.f/(1.f+d01));
                *(float2*)(Ao + (row+8)*SS + col) = make_float2(1.f/(1.f+d10), 1.f/(1.f+d11));
            }
        }
    } else {
        float cs0[4], cs1[4];
#pragma unroll
        for (int nt = 0; nt < 4; nt++) { cs0[nt] = 0.f; cs1[nt] = 0.f; }
#pragma unroll
        for (int mt = 0; mt < 4; mt++) {
            int row = wm*64 + mt*16 + g;
            float nr0 = n1s[row], nr1 = n1s[row+8];
            float rlo = 0.f, rhi = 0.f;
#pragma unroll
            for (int nt = 0; nt < 4; nt++) {
                int col = wn*32 + nt*8 + 2*tig;
                float nc0 = n2s[col], nc1 = n2s[col+1];
                float a00 = 1.f/(1.f + sqrtf(fmaxf(nr0 + nc0 - 2.f*acc[mt][nt][0], 0.f)));
                float a01 = 1.f/(1.f + sqrtf(fmaxf(nr0 + nc1 - 2.f*acc[mt][nt][1], 0.f)));
                float a10 = 1.f/(1.f + sqrtf(fmaxf(nr1 + nc0 - 2.f*acc[mt][nt][2], 0.f)));
                float a11 = 1.f/(1.f + sqrtf(fmaxf(nr1 + nc1 - 2.f*acc[mt][nt][3], 0.f)));
                rlo += a00 + a01;
                rhi += a10 + a11;
                cs0[nt] += a00 + a10;
                cs1[nt] += a01 + a11;
            }
            rlo += __shfl_xor_sync(0xffffffffu, rlo, 1);
            rlo += __shfl_xor_sync(0xffffffffu, rlo, 2);
            rhi += __shfl_xor_sync(0xffffffffu, rhi, 1);
            rhi += __shfl_xor_sync(0xffffffffu, rhi, 2);
            if (tig == 0) {
                rowbuf[wn*SS + row]   = rlo;
                rowbuf[wn*SS + row+8] = rhi;
            }
        }
#pragma unroll
        for (int nt = 0; nt < 4; nt++) {
            float c0 = cs0[nt], c1 = cs1[nt];
            c0 += __shfl_xor_sync(0xffffffffu, c0, 4);
            c0 += __shfl_xor_sync(0xffffffffu, c0, 8);
            c0 += __shfl_xor_sync(0xffffffffu, c0, 16);
            c1 += __shfl_xor_sync(0xffffffffu, c1, 4);
            c1 += __shfl_xor_sync(0xffffffffu, c1, 8);
            c1 += __shfl_xor_sync(0xffffffffu, c1, 16);
            if (g == 0) {
                int col = wn*32 + nt*8 + 2*tig;
                colbuf[wm*SS + col]     = c0;
                colbuf[wm*SS + col + 1] = c1;
            }
        }
        __syncthreads();
        if (tid < SS) {
            g_w1[b*SS + tid] = rowbuf[tid] + rowbuf[SS+tid] + rowbuf[2*SS+tid] + rowbuf[3*SS+tid];
            g_w2[b*SS + tid] = colbuf[tid] + colbuf[SS+tid];
        }
    }
#undef FETCH
#undef STBUF
}

// ---------------- f1 = A@W, f2 = A^T@W in ONE CTA, tensor cores ----------------
// grid (B, 5); 8 warps: warps 0-3 -> f1, warps 4-7 -> f2
// warp tile 64x32 (mt=4, nt=4): 0.75 LDS words per mma (was 1.5)
#define FPAD 132
__global__ __launch_bounds__(256, 2) void k_fgemm(const float* __restrict__ W, int layer) {
    extern __shared__ float sm[];
    uint32_t* As = (uint32_t*)sm;              // [128][132]
    uint32_t* Ws = As + SS*FPAD;               // [64][132] (transposed: Ws[n][k])

    int b = blockIdx.x;
    int n0 = blockIdx.y * 64;
    const float* Ab = g_A + b*SS*SS;
    const float* Wl = W + (size_t)layer*SS*EE;
    int tid = threadIdx.x;
    int lane = tid & 31, wid = tid >> 5;
    int g = lane >> 2, tig = lane & 3;
    int half = wid >> 2;
    int wm = wid & 1;          // row 64-block
    int wn = (wid >> 1) & 1;   // col 32-block

    // load A (128x128) -> tf32 smem
    {
        int r = tid >> 1, h = tid & 1;
        const float* src = Ab + r*SS + h*64;
        uint32_t* dst = As + r*FPAD + h*64;
#pragma unroll
        for (int q = 0; q < 16; q++) {
            float4 v = *(const float4*)(src + 4*q);
            dst[4*q+0] = to_tf32(v.x); dst[4*q+1] = to_tf32(v.y);
            dst[4*q+2] = to_tf32(v.z); dst[4*q+3] = to_tf32(v.w);
        }
    }
    // load W tile transposed: Ws[n][k]
    {
        int k = tid >> 1, h = tid & 1;
#pragma unroll
        for (int q = 0; q < 8; q++) {
            int n = h*32 + 4*q;
            float4 v = make_float4(0.f,0.f,0.f,0.f);
            if (n0 + n < EE) v = *(const float4*)(Wl + k*EE + n0 + n);
            Ws[(n+0)*FPAD + k] = to_tf32(v.x);
            Ws[(n+1)*FPAD + k] = to_tf32(v.y);
            Ws[(n+2)*FPAD + k] = to_tf32(v.z);
            Ws[(n+3)*FPAD + k] = to_tf32(v.w);
        }
    }
    __syncthreads();

    float acc[4][4][4];
#pragma unroll
    for (int mt = 0; mt < 4; mt++)
#pragma unroll
        for (int nt = 0; nt < 4; nt++)
#pragma unroll
            for (int q = 0; q < 4; q++) acc[mt][nt][q] = 0.f;

#pragma unroll 2
    for (int ks = 0; ks < 16; ks++) {
        int kk = ks*8;
        uint32_t a[4][4], bf[4][2];
#pragma unroll
        for (int mt = 0; mt < 4; mt++) {
            int row = wm*64 + mt*16 + g;
            if (half == 0) {
                a[mt][0] = As[row*FPAD + kk + tig];
                a[mt][1] = As[(row+8)*FPAD + kk + tig];
                a[mt][2] = As[row*FPAD + kk + tig + 4];
                a[mt][3] = As[(row+8)*FPAD + kk + tig + 4];
            } else {
                a[mt][0] = As[(kk+tig)*FPAD + row];
                a[mt][1] = As[(kk+tig)*FPAD + row + 8];
                a[mt][2] = As[(kk+tig+4)*FPAD + row];
                a[mt][3] = As[(kk+tig+4)*FPAD + row + 8];
            }
        }
#pragma unroll
        for (int nt = 0; nt < 4; nt++) {
            int cn = wn*32 + nt*8 + g;
            bf[nt][0] = Ws[cn*FPAD + kk + tig];
            bf[nt][1] = Ws[cn*FPAD + kk + tig + 4];
        }
#pragma unroll
        for (int mt = 0; mt < 4; mt++)
#pragma unroll
            for (int nt = 0; nt < 4; nt++)
                MMA_TF32(acc[mt][nt], a[mt], bf[nt]);
    }

    float* out = (half ? g_f2 : g_f1) + b*SS*EE;
#pragma unroll
    for (int mt = 0; mt < 4; mt++) {
        int row = wm*64 + mt*16 + g;
#pragma unroll
        for (int nt = 0; nt < 4; nt++) {
            int col = n0 + wn*32 + nt*8 + 2*tig;
            if (col < EE) {
                *(float2*)(out + row*EE + col)     = make_float2(acc[mt][nt][0], acc[mt][nt][1]);
                *(float2*)(out + (row+8)*EE + col) = make_float2(acc[mt][nt][2], acc[mt][nt][3]);
            }
        }
    }
}

// ---------------- conv 2in->1out 3x3 + tanh + fused mean accumulation ----------
// grid (B, 8, 2), block 256; dynamic smem; store=0 skips global o write (dead)
__global__ __launch_bounds__(256) void k_conv(const float* __restrict__ cw,
                                              const float* __restrict__ cb,
                                              int layer, int store) {
    extern __shared__ float sm[];
    float* xs = sm;                       // [2][18][302]
    float* os = xs + 2*(CROWS+2)*(EE+2);  // [16][300]
    float* w  = os + CROWS*EE;            // [18]

    int b = blockIdx.x, ch = blockIdx.y, pair = blockIdx.z;
    int s0 = ch * CROWS;
    const float* X0 = (pair ? g_s2 : g_s1) + b*SS*EE;
    const float* X1 = (pair ? g_f2 : g_f1) + b*SS*EE;
    float* O = (pair ? g_o2 : g_o1) + b*SS*EE;
    int tid = threadIdx.x;
    if (tid < 18) w[tid] = cw[layer*18 + tid];
    if (tid < 2*(CROWS+2)*2) {
        int c = tid / (2*(CROWS+2));
        int rem = tid % (2*(CROWS+2));
        int j = rem >> 1, side = rem & 1;
        xs[(c*(CROWS+2) + j)*(EE+2) + (side ? EE+1 : 0)] = 0.f;
    }
    for (int i = tid; i < 2*(CROWS+2)*(EE/4); i += 256) {
        int c = i / ((CROWS+2)*(EE/4));
        int rem = i % ((CROWS+2)*(EE/4));
        int j = rem / (EE/4), q = rem % (EE/4);
        int srow = s0 + j - 1;
        float4 val = make_float4(0.f,0.f,0.f,0.f);
        if (srow >= 0 && srow < SS)
            val = *(const float4*)((c ? X1 : X0) + srow*EE + q*4);
        float* dptr = &xs[(c*(CROWS+2) + j)*(EE+2) + q*4 + 1];
        dptr[0]=val.x; dptr[1]=val.y; dptr[2]=val.z; dptr[3]=val.w;
    }
    float bias = cb[layer];
    __syncthreads();
    for (int i = tid; i < CROWS*EE; i += 256) {
        int r = i / EE, e = i % EE;
        float acc = bias;
#pragma unroll
        for (int c = 0; c < 2; c++)
#pragma unroll
            for (int kh = 0; kh < 3; kh++)
#pragma unroll
                for (int kw = 0; kw < 3; kw++)
                    acc += w[c*9 + kh*3 + kw] * xs[(c*(CROWS+2) + r+kh)*(EE+2) + e + kw];
        float t = tanh_fast(acc);
        if (store) O[(s0+r)*EE + e] = t;
        os[r*EE + e] = t;
    }
    __syncthreads();
    int slot = (pair ? 4 : 1) + layer;
    for (int e = tid; e < EE; e += 256) {
        float s = 0.f;
#pragma unroll
        for (int r = 0; r < CROWS; r++) s += os[r*EE + e];
        atomicAdd(&g_x[b*FCIN + slot*EE + e], s*(1.f/SS));
    }
}

// ---------------- weighted avg-pool3 + residual update ----------------
__global__ __launch_bounds__(128) void k_pool() {
    int b = blockIdx.x, ch = blockIdx.y, pair = blockIdx.z;
    int s0 = ch * CROWS;
    const float* O = (pair ? g_o2 : g_o1) + b*SS*EE;
    float* Sx = (pair ? g_s2 : g_s1) + b*SS*EE;
    const float* wv = (pair ? g_w2 : g_w1) + b*SS;
    __shared__ float w[CROWS+2];
    if (threadIdx.x < CROWS+2) {
        int s = s0 + (int)threadIdx.x - 1;
        w[threadIdx.x] = (s >= 0 && s < SS) ? wv[s] : 0.f;
    }
    __syncthreads();
    for (int e = threadIdx.x; e < EE; e += 128) {
        float a = (s0 > 0) ? O[(s0-1)*EE + e] * w[0] : 0.f;
        float bmid = O[s0*EE + e] * w[1];
#pragma unroll
        for (int i = 0; i < CROWS; i++) {
            int s = s0 + i;
            float cnext = (s+1 < SS) ? O[(s+1)*EE + e] * w[i+2] : 0.f;
            Sx[s*EE + e] += (a + bmid + cnext) * (1.f/3.f);
            a = bmid; bmid = cnext;
        }
    }
}

// ---------------- fc1 GEMM: [512,1800] @ [1800,300]^T -> g_h ----------------
__global__ __launch_bounds__(256) void k_fc1(const float* __restrict__ fw) {
    int m0 = blockIdx.x * 64, n0 = blockIdx.y * 64;
    __shared__ float Xs[8][68];
    __shared__ float Ws2[8][68];
    int tid = threadIdx.x, ty = tid >> 4, tx = tid & 15;
    float acc[4][4];
#pragma unroll
    for (int u = 0; u < 4; u++)
#pragma unroll
        for (int v = 0; v < 4; v++) acc[u][v] = 0.f;

    for (int k0 = 0; k0 < FCIN; k0 += 8) {
        __syncthreads();
#pragma unroll 2
        for (int i = tid; i < 512; i += 256) {
            int r = i >> 3, kk = i & 7;
            Xs[kk][r] = g_x[(m0 + r)*FCIN + k0 + kk];
            int n = n0 + r;
            Ws2[kk][r] = (n < HH) ? fw[n*FCIN + k0 + kk] : 0.f;
        }
        __syncthreads();
#pragma unroll
        for (int kk = 0; kk < 8; kk++) {
            float4 xa = *(const float4*)&Xs[kk][ty*4];
            float4 wb = *(const float4*)&Ws2[kk][tx*4];
            float xv[4] = {xa.x, xa.y, xa.z, xa.w};
            float wvv[4] = {wb.x, wb.y, wb.z, wb.w};
#pragma unroll
            for (int u = 0; u < 4; u++)
#pragma unroll
                for (int v = 0; v < 4; v++) acc[u][v] += xv[u]*wvv[v];
        }
    }
#pragma unroll
    for (int u = 0; u < 4; u++) {
        int m = m0 + ty*4 + u;
#pragma unroll
        for (int v = 0; v < 4; v++) {
            int n = n0 + tx*4 + v;
            if (n < HH) g_h[m*HH + n] = acc[u][v];
        }
    }
}

// ---------------- LN + relu + fc2 + softmax ----------------
__device__ __forceinline__ float block_reduce512(float v, float* red) {
    int tid = threadIdx.x;
    red[tid] = v;
    __syncthreads();
    for (int off = 256; off > 0; off >>= 1) {
        if (tid < off) red[tid] += red[tid + off];
        __syncthreads();
    }
    float r = red[0];
    __syncthreads();
    return r;
}

__global__ __launch_bounds__(512) void k_head(const float* __restrict__ fc1b,
                                              const float* __restrict__ lng,
                                              const float* __restrict__ lnb,
                                              const float* __restrict__ fc2w,
                                              const float* __restrict__ fc2b,
                                              float* __restrict__ out) {
    int b = blockIdx.x, tid = threadIdx.x;
    __shared__ float red[512];
    bool act = tid < HH;
    float h = act ? (g_h[b*HH + tid] + fc1b[tid]) : 0.f;
    float mu = block_reduce512(h, red) * (1.f/HH);
    float d = act ? (h - mu) : 0.f;
    float var = block_reduce512(d*d, red) * (1.f/HH);
    float hn = 0.f;
    if (act) {
        hn = d * rsqrtf(var + 1e-5f) * lng[tid] + lnb[tid];
        hn = fmaxf(hn, 0.f);
    }
    float o0 = block_reduce512(act ? hn*fc2w[tid]      : 0.f, red);
    float o1 = block_reduce512(act ? hn*fc2w[HH + tid] : 0.f, red);
    if (tid == 0) {
        o0 += fc2b[0];
        o1 += fc2b[1];
        out[b*2 + 0] = o0;
        out[b*2 + 1] = o1;
        float m = fmaxf(o0, o1);
        float e0 = expf(o0 - m), e1 = expf(o1 - m);
        float inv = 1.f/(e0 + e1);
        out[BB*2 + b*2 + 0] = e0*inv;
        out[BB*2 + b*2 + 1] = e1*inv;
    }
}

// ---------------- launch ----------------
extern "C" void kernel_launch(void* const* d_in, const int* in_sizes, int n_in,
                              void* d_out, int out_size) {
    (void)in_sizes; (void)n_in; (void)out_size;
    const int*   seq1 = (const int*)d_in[0];
    const int*   seq2 = (const int*)d_in[1];
    const float* emb  = (const float*)d_in[2];
    const float* W    = (const float*)d_in[3];
    const float* cw   = (const float*)d_in[4];
    const float* cb   = (const float*)d_in[5];
    const float* fc1w = (const float*)d_in[6];
    const float* fc1b = (const float*)d_in[7];
    const float* lng  = (const float*)d_in[8];
    const float* lnb  = (const float*)d_in[9];
    const float* fc2w = (const float*)d_in[10];
    const float* fc2b = (const float*)d_in[11];
    float* out = (float*)d_out;

    const int SM_MATCH = (2*SS*MPAD*2 + 2*SS + 4*SS + 2*SS) * 4;    // ~77.8KB
    const int SM_FGEMM = (SS*FPAD + 64*FPAD) * 4;                    // ~101.4KB
    const int SM_CONV  = (2*(CROWS+2)*(EE+2) + CROWS*EE + 18) * 4;   // ~62.8KB

    cudaFuncSetAttribute(k_match, cudaFuncAttributeMaxDynamicSharedMemorySize, SM_MATCH);
    cudaFuncSetAttribute(k_fgemm, cudaFuncAttributeMaxDynamicSharedMemorySize, SM_FGEMM);
    cudaFuncSetAttribute(k_conv,  cudaFuncAttributeMaxDynamicSharedMemorySize, SM_CONV);

    k_gather<<<BB, 256>>>(seq1, seq2, emb);
    for (int l = 0; l < LL; l++) {
        int last = (l == LL-1);
        k_match<<<BB, 256, SM_MATCH>>>(0);
        k_zx<<<(BB*2*EE + 255)/256, 256>>>(l);
        k_fgemm<<<dim3(BB, 5), 256, SM_FGEMM>>>(W, l);
        k_conv<<<dim3(BB, 8, 2), 256, SM_CONV>>>(cw, cb, l, last ? 0 : 1);
        if (!last) {
            k_match<<<BB, 256, SM_MATCH>>>(1);
            k_pool<<<dim3(BB, 8, 2), 128>>>();
        }
    }
    k_fc1<<<dim3(8, 5), 256>>>(fc1w);
    k_head<<<BB, 512>>>(fc1b, lng, lnb, fc2w, fc2b, out);
}

// round 9
// speedup vs baseline: 1.0865x; 1.0865x over previous
#include <cuda_runtime.h>
#include <math.h>
#include <stdint.h>

#define BB 512
#define SS 128
#define EE 300
#define LL 2
#define HH 300
#define FCIN 1800   // E*(1+L)*2
#define CROWS 16

// ---------------- device scratch (no allocation allowed) ----------------
__device__ float g_s1[BB*SS*EE];
__device__ float g_s2[BB*SS*EE];
__device__ float g_f1[BB*SS*EE];
__device__ float g_f2[BB*SS*EE];
__device__ float g_o1[BB*SS*EE];
__device__ float g_o2[BB*SS*EE];
__device__ float g_A [BB*SS*SS];
__device__ float g_Wt[LL*320*SS];   // pre-transposed, tf32-rounded W: [l][n][k]
__device__ float g_w1[BB*SS];
__device__ float g_w2[BB*SS];
__device__ float g_v1[BB*SS];
__device__ float g_v2[BB*SS];
__device__ float g_x [BB*FCIN];
__device__ float g_h [BB*HH];

__device__ __forceinline__ float tanh_fast(float x) {
    float r; asm("tanh.approx.f32 %0, %1;" : "=f"(r) : "f"(x)); return r;
}
__device__ __forceinline__ uint32_t to_tf32(float x) {
    uint32_t r; asm("cvt.rna.tf32.f32 %0, %1;" : "=r"(r) : "f"(x)); return r;
}
__device__ __forceinline__ void cpasync16(void* dst, const void* src) {
    uint32_t d = (uint32_t)__cvta_generic_to_shared(dst);
    asm volatile("cp.async.ca.shared.global [%0], [%1], 16;\n" :: "r"(d), "l"(src));
}
#define MMA_TF32(C, A, B) \
    asm volatile("mma.sync.aligned.m16n8k8.row.col.f32.tf32.tf32.f32 " \
        "{%0,%1,%2,%3}, {%4,%5,%6,%7}, {%8,%9}, {%0,%1,%2,%3};" \
        : "+f"((C)[0]), "+f"((C)[1]), "+f"((C)[2]), "+f"((C)[3]) \
        : "r"((A)[0]), "r"((A)[1]), "r"((A)[2]), "r"((A)[3]), \
          "r"((B)[0]), "r"((B)[1]))

// ---------------- W prep: g_Wt[l][n][k] = tf32(W[l][k][n]), zero-pad n>=300 ----
__global__ void k_wprep(const float* __restrict__ W) {
    int n = blockIdx.x, l = blockIdx.y, k = threadIdx.x;
    float v = 0.f;
    if (n < EE) v = W[(size_t)l*SS*EE + k*EE + n];
    g_Wt[(l*320 + n)*SS + k] = __uint_as_float(to_tf32(v));
}

// ---------------- embedding gather + masks + fused mean(slot0) ----------------
__global__ __launch_bounds__(256) void k_gather(const int* __restrict__ seq1,
                                                const int* __restrict__ seq2,
                                                const float* __restrict__ emb) {
    __shared__ float msum[2][EE];
    int b = blockIdx.x;
    int tid = threadIdx.x;
    int warp = tid >> 5, lane = tid & 31;
    for (int i = tid; i < 2*EE; i += 256) ((float*)msum)[i] = 0.f;
    for (int i = tid; i < SS; i += 256) {
        g_v1[b*SS+i] = (seq1[b*SS+i] != 0) ? 1.f : 0.f;
        g_v2[b*SS+i] = (seq2[b*SS+i] != 0) ? 1.f : 0.f;
    }
    __syncthreads();
    for (int idx = warp; idx < 2*SS; idx += 8) {
        int s = idx >> 1, sel = idx & 1;
        int tok = sel ? seq2[b*SS+s] : seq1[b*SS+s];
        const float4* src = (const float4*)(emb + (long)tok*EE);
        float4* dst = (float4*)((sel ? g_s2 : g_s1) + (b*SS+s)*EE);
        for (int j = lane; j < EE/4; j += 32) {
            float4 v = src[j];
            dst[j] = v;
            atomicAdd(&msum[sel][4*j+0], v.x);
            atomicAdd(&msum[sel][4*j+1], v.y);
            atomicAdd(&msum[sel][4*j+2], v.z);
            atomicAdd(&msum[sel][4*j+3], v.w);
        }
    }
    __syncthreads();
    for (int e = tid; e < EE; e += 256) {
        g_x[b*FCIN + e]        = msum[0][e]*(1.f/SS);
        g_x[b*FCIN + 3*EE + e] = msum[1][e]*(1.f/SS);
    }
}

// ---------------- zero mean slots for layer l (conv accumulates atomically) ----
__global__ void k_zx(int l) {
    int i = blockIdx.x*256 + threadIdx.x;
    if (i >= BB*2*EE) return;
    int b = i / (2*EE);
    int r = i % (2*EE);
    int half = r / EE, e = r % EE;
    int slot = half ? (4+l) : (1+l);
    g_x[b*FCIN + slot*EE + e] = 0.f;
}

// ---------------- match-score, tensor-core tf32 ----------------
// mode=0: s1/s2 -> store A (tf32-rounded)   mode=1: o1/o2 -> w1, w2
#define MPAD 36
#define MCH 10      // ceil(300/32)
__global__ __launch_bounds__(256) void k_match(int mode) {
    extern __shared__ float sm[];
    float* Xs = sm;                       // [2][128][36]
    float* Ys = Xs + 2*SS*MPAD;           // [2][128][36]
    float* n1s = Ys + 2*SS*MPAD;          // [128]
    float* n2s = n1s + SS;                // [128]
    float* rowbuf = n2s + SS;             // [4][128]
    float* colbuf = rowbuf + 4*SS;        // [2][128]

    int b = blockIdx.x;
    const float* X = (mode ? g_o1 : g_s1) + b*SS*EE;
    const float* Y = (mode ? g_o2 : g_s2) + b*SS*EE;
    int tid = threadIdx.x;
    int lane = tid & 31, wid = tid >> 5;
    int g = lane >> 2, tig = lane & 3;
    int wm = wid & 1, wn = wid >> 1;

    int lr = tid >> 1, lh = tid & 1;
    const float* Xr = X + lr*EE + lh*16;
    const float* Yr = Y + lr*EE + lh*16;
    float mvx = g_v1[b*SS + lr];
    float mvy = g_v2[b*SS + lr];
    float nx = 0.f, ny = 0.f;
    float4 vx[4], vy[4];

#define FETCH(c) do { \
    int kb = (c)*32; \
    _Pragma("unroll") for (int j = 0; j < 4; j++) { \
        int k = kb + lh*16 + 4*j; \
        if (k < EE) { vx[j] = *(const float4*)(Xr + kb + 4*j); \
                      vy[j] = *(const float4*)(Yr + kb + 4*j); } \
        else { vx[j] = make_float4(0.f,0.f,0.f,0.f); vy[j] = vx[j]; } \
    } } while(0)

#define STBUF(buf) do { \
    float* xd = Xs + (buf)*SS*MPAD + lr*MPAD + lh*16; \
    float* yd = Ys + (buf)*SS*MPAD + lr*MPAD + lh*16; \
    _Pragma("unroll") for (int j = 0; j < 4; j++) { \
        float x0=vx[j].x*mvx, x1=vx[j].y*mvx, x2=vx[j].z*mvx, x3=vx[j].w*mvx; \
        float y0=vy[j].x*mvy, y1=vy[j].y*mvy, y2=vy[j].z*mvy, y3=vy[j].w*mvy; \
        nx += x0*x0+x1*x1+x2*x2+x3*x3; \
        ny += y0*y0+y1*y1+y2*y2+y3*y3; \
        ((uint32_t*)xd)[4*j+0]=to_tf32(x0); ((uint32_t*)xd)[4*j+1]=to_tf32(x1); \
        ((uint32_t*)xd)[4*j+2]=to_tf32(x2); ((uint32_t*)xd)[4*j+3]=to_tf32(x3); \
        ((uint32_t*)yd)[4*j+0]=to_tf32(y0); ((uint32_t*)yd)[4*j+1]=to_tf32(y1); \
        ((uint32_t*)yd)[4*j+2]=to_tf32(y2); ((uint32_t*)yd)[4*j+3]=to_tf32(y3); \
    } } while(0)

    float acc[4][4][4];
#pragma unroll
    for (int mt = 0; mt < 4; mt++)
#pragma unroll
        for (int nt = 0; nt < 4; nt++)
#pragma unroll
            for (int q = 0; q < 4; q++) acc[mt][nt][q] = 0.f;

    FETCH(0); STBUF(0);
    __syncthreads();

    for (int c = 0; c < MCH; c++) {
        int cur = c & 1;
        if (c + 1 < MCH) FETCH(c+1);
        const uint32_t* xb = (const uint32_t*)(Xs + cur*SS*MPAD);
        const uint32_t* yb = (const uint32_t*)(Ys + cur*SS*MPAD);
#pragma unroll
        for (int ks = 0; ks < 4; ks++) {
            int kk = ks*8;
            uint32_t a[4][4], bf[4][2];
#pragma unroll
            for (int mt = 0; mt < 4; mt++) {
                int row = wm*64 + mt*16 + g;
                a[mt][0] = xb[row*MPAD + kk + tig];
                a[mt][1] = xb[(row+8)*MPAD + kk + tig];
                a[mt][2] = xb[row*MPAD + kk + tig + 4];
                a[mt][3] = xb[(row+8)*MPAD + kk + tig + 4];
            }
#pragma unroll
            for (int nt = 0; nt < 4; nt++) {
                int cr = wn*32 + nt*8 + g;
                bf[nt][0] = yb[cr*MPAD + kk + tig];
                bf[nt][1] = yb[cr*MPAD + kk + tig + 4];
            }
#pragma unroll
            for (int mt = 0; mt < 4; mt++)
#pragma unroll
                for (int nt = 0; nt < 4; nt++)
                    MMA_TF32(acc[mt][nt], a[mt], bf[nt]);
        }
        if (c + 1 < MCH) STBUF(cur ^ 1);
        __syncthreads();
    }

    nx += __shfl_xor_sync(0xffffffffu, nx, 1);
    ny += __shfl_xor_sync(0xffffffffu, ny, 1);
    if (lh == 0) { n1s[lr] = nx; n2s[lr] = ny; }
    __syncthreads();

    if (mode == 0) {
        float* Ao = g_A + b*SS*SS;
#pragma unroll
        for (int mt = 0; mt < 4; mt++) {
            int row = wm*64 + mt*16 + g;
            float nr0 = n1s[row], nr1 = n1s[row+8];
#pragma unroll
            for (int nt = 0; nt < 4; nt++) {
                int col = wn*32 + nt*8 + 2*tig;
                float nc0 = n2s[col], nc1 = n2s[col+1];
                float d00 = sqrtf(fmaxf(nr0 + nc0 - 2.f*acc[mt][nt][0], 0.f));
                float d01 = sqrtf(fmaxf(nr0 + nc1 - 2.f*acc[mt][nt][1], 0.f));
                float d10 = sqrtf(fmaxf(nr1 + nc0 - 2.f*acc[mt][nt][2], 0.f));
                float d11 = sqrtf(fmaxf(nr1 + nc1 - 2.f*acc[mt][nt][3], 0.f));
                // store tf32-rounded (identical to fgemm's previous in-kernel cvt)
                *(float2*)(Ao + row*SS + col) = make_float2(
                    __uint_as_float(to_tf32(1.f/(1.f+d00))),
                    __uint_as_float(to_tf32(1.f/(1.f+d01))));
                *(float2*)(Ao + (row+8)*SS + col) = make_float2(
                    __uint_as_float(to_tf32(1.f/(1.f+d10))),
                    __uint_as_float(to_tf32(1.f/(1.f+d11))));
            }
        }
    } else {
        float cs0[4], cs1[4];
#pragma unroll
        for (int nt = 0; nt < 4; nt++) { cs0[nt] = 0.f; cs1[nt] = 0.f; }
#pragma unroll
        for (int mt = 0; mt < 4; mt++) {
            int row = wm*64 + mt*16 + g;
            float nr0 = n1s[row], nr1 = n1s[row+8];
            float rlo = 0.f, rhi = 0.f;
#pragma unroll
            for (int nt = 0; nt < 4; nt++) {
                int col = wn*32 + nt*8 + 2*tig;
                float nc0 = n2s[col], nc1 = n2s[col+1];
                float a00 = 1.f/(1.f + sqrtf(fmaxf(nr0 + nc0 - 2.f*acc[mt][nt][0], 0.f)));
                float a01 = 1.f/(1.f + sqrtf(fmaxf(nr0 + nc1 - 2.f*acc[mt][nt][1], 0.f)));
                float a10 = 1.f/(1.f + sqrtf(fmaxf(nr1 + nc0 - 2.f*acc[mt][nt][2], 0.f)));
                float a11 = 1.f/(1.f + sqrtf(fmaxf(nr1 + nc1 - 2.f*acc[mt][nt][3], 0.f)));
                rlo += a00 + a01;
                rhi += a10 + a11;
                cs0[nt] += a00 + a10;
                cs1[nt] += a01 + a11;
            }
            rlo += __shfl_xor_sync(0xffffffffu, rlo, 1);
            rlo += __shfl_xor_sync(0xffffffffu, rlo, 2);
            rhi += __shfl_xor_sync(0xffffffffu, rhi, 1);
            rhi += __shfl_xor_sync(0xffffffffu, rhi, 2);
            if (tig == 0) {
                rowbuf[wn*SS + row]   = rlo;
                rowbuf[wn*SS + row+8] = rhi;
            }
        }
#pragma unroll
        for (int nt = 0; nt < 4; nt++) {
            float c0 = cs0[nt], c1 = cs1[nt];
            c0 += __shfl_xor_sync(0xffffffffu, c0, 4);
            c0 += __shfl_xor_sync(0xffffffffu, c0, 8);
            c0 += __shfl_xor_sync(0xffffffffu, c0, 16);
            c1 += __shfl_xor_sync(0xffffffffu, c1, 4);
            c1 += __shfl_xor_sync(0xffffffffu, c1, 8);
            c1 += __shfl_xor_sync(0xffffffffu, c1, 16);
            if (g == 0) {
                int col = wn*32 + nt*8 + 2*tig;
                colbuf[wm*SS + col]     = c0;
                colbuf[wm*SS + col + 1] = c1;
            }
        }
        __syncthreads();
        if (tid < SS) {
            g_w1[b*SS + tid] = rowbuf[tid] + rowbuf[SS+tid] + rowbuf[2*SS+tid] + rowbuf[3*SS+tid];
            g_w2[b*SS + tid] = colbuf[tid] + colbuf[SS+tid];
        }
    }
#undef FETCH
#undef STBUF
}

// ---------------- f1=A@W, f2=A^T@W, cp.async double-buffered K-chunks ---------
// grid (B, 5); warps 0-3 -> f1 (32-row tiles), warps 4-7 -> f2
#define APAD 36
#define A2PAD 132
#define FBUF (128*APAD + 32*A2PAD + 64*APAD)   // 11136 words per buffer
__global__ __launch_bounds__(256, 2) void k_fgemm(int layer) {
    extern __shared__ float sm[];
    int b = blockIdx.x;
    int n0 = blockIdx.y * 64;
    const float* Ab = g_A + b*SS*SS;
    const float* Wt = g_Wt + (size_t)layer*320*SS;
    int tid = threadIdx.x;
    int lane = tid & 31, wid = tid >> 5;
    int g = lane >> 2, tig = lane & 3;
    int half = wid >> 2, wm = wid & 3;

    // async-load one K-chunk (32 wide) into buffer `buf`
#define LOADCH(c, buf) do { \
    float* base_ = sm + (buf)*FBUF; \
    float* A1_ = base_; \
    float* A2_ = base_ + 128*APAD; \
    float* Wb_ = A2_ + 32*A2PAD; \
    int k0_ = (c)*32; \
    _Pragma("unroll") for (int j = 0; j < 4; j++) { \
        int i = tid + 256*j; int r = i >> 3, h = i & 7; \
        cpasync16(A1_ + r*APAD + h*4, Ab + r*SS + k0_ + h*4); \
    } \
    _Pragma("unroll") for (int j = 0; j < 4; j++) { \
        int i = tid + 256*j; int kk = i >> 5, c4 = i & 31; \
        cpasync16(A2_ + kk*A2PAD + c4*4, Ab + (k0_+kk)*SS + c4*4); \
    } \
    _Pragma("unroll") for (int j = 0; j < 2; j++) { \
        int i = tid + 256*j; int n = i >> 3, h = i & 7; \
        cpasync16(Wb_ + n*APAD + h*4, Wt + (n0+n)*SS + k0_ + h*4); \
    } \
    asm volatile("cp.async.commit_group;\n" ::); \
} while (0)

    float acc[2][8][4];
#pragma unroll
    for (int mt = 0; mt < 2; mt++)
#pragma unroll
        for (int nt = 0; nt < 8; nt++)
#pragma unroll
            for (int q = 0; q < 4; q++) acc[mt][nt][q] = 0.f;

    LOADCH(0, 0);
    for (int c = 0; c < 4; c++) {
        if (c < 3) {
            LOADCH(c+1, (c+1)&1);
            asm volatile("cp.async.wait_group 1;\n" ::);
        } else {
            asm volatile("cp.async.wait_group 0;\n" ::);
        }
        __syncthreads();
        const uint32_t* base = (const uint32_t*)(sm + (c&1)*FBUF);
        const uint32_t* A1 = base;
        const uint32_t* A2 = base + 128*APAD;
        const uint32_t* Wb = A2 + 32*A2PAD;
#pragma unroll
        for (int ks = 0; ks < 4; ks++) {
            int kk = ks*8;
            uint32_t a[2][4], bf[8][2];
#pragma unroll
            for (int mt = 0; mt < 2; mt++) {
                int row = wm*32 + mt*16 + g;
                if (half == 0) {
                    a[mt][0] = A1[row*APAD + kk + tig];
                    a[mt][1] = A1[(row+8)*APAD + kk + tig];
                    a[mt][2] = A1[row*APAD + kk + tig + 4];
                    a[mt][3] = A1[(row+8)*APAD + kk + tig + 4];
                } else {
                    a[mt][0] = A2[(kk+tig)*A2PAD + row];
                    a[mt][1] = A2[(kk+tig)*A2PAD + row + 8];
                    a[mt][2] = A2[(kk+tig+4)*A2PAD + row];
                    a[mt][3] = A2[(kk+tig+4)*A2PAD + row + 8];
                }
            }
#pragma unroll
            for (int nt = 0; nt < 8; nt++) {
                int cn = nt*8 + g;
                bf[nt][0] = Wb[cn*APAD + kk + tig];
                bf[nt][1] = Wb[cn*APAD + kk + tig + 4];
            }
#pragma unroll
            for (int mt = 0; mt < 2; mt++)
#pragma unroll
                for (int nt = 0; nt < 8; nt++)
                    MMA_TF32(acc[mt][nt], a[mt], bf[nt]);
        }
        __syncthreads();
    }
#undef LOADCH

    float* out = (half ? g_f2 : g_f1) + b*SS*EE;
#pragma unroll
    for (int mt = 0; mt < 2; mt++) {
        int row = wm*32 + mt*16 + g;
#pragma unroll
        for (int nt = 0; nt < 8; nt++) {
            int col = n0 + nt*8 + 2*tig;
            if (col < EE) {
                *(float2*)(out + row*EE + col)     = make_float2(acc[mt][nt][0], acc[mt][nt][1]);
                *(float2*)(out + (row+8)*EE + col) = make_float2(acc[mt][nt][2], acc[mt][nt][3]);
            }
        }
    }
}

// ---------------- conv 2in->1out 3x3 + tanh + fused mean accumulation ----------
__global__ __launch_bounds__(256) void k_conv(const float* __restrict__ cw,
                                              const float* __restrict__ cb,
                                              int layer, int store) {
    extern __shared__ float sm[];
    float* xs = sm;                       // [2][18][302]
    float* os = xs + 2*(CROWS+2)*(EE+2);  // [16][300]
    float* w  = os + CROWS*EE;            // [18]

    int b = blockIdx.x, ch = blockIdx.y, pair = blockIdx.z;
    int s0 = ch * CROWS;
    const float* X0 = (pair ? g_s2 : g_s1) + b*SS*EE;
    const float* X1 = (pair ? g_f2 : g_f1) + b*SS*EE;
    float* O = (pair ? g_o2 : g_o1) + b*SS*EE;
    int tid = threadIdx.x;
    if (tid < 18) w[tid] = cw[layer*18 + tid];
    if (tid < 2*(CROWS+2)*2) {
        int c = tid / (2*(CROWS+2));
        int rem = tid % (2*(CROWS+2));
        int j = rem >> 1, side = rem & 1;
        xs[(c*(CROWS+2) + j)*(EE+2) + (side ? EE+1 : 0)] = 0.f;
    }
    for (int i = tid; i < 2*(CROWS+2)*(EE/4); i += 256) {
        int c = i / ((CROWS+2)*(EE/4));
        int rem = i % ((CROWS+2)*(EE/4));
        int j = rem / (EE/4), q = rem % (EE/4);
        int srow = s0 + j - 1;
        float4 val = make_float4(0.f,0.f,0.f,0.f);
        if (srow >= 0 && srow < SS)
            val = *(const float4*)((c ? X1 : X0) + srow*EE + q*4);
        float* dptr = &xs[(c*(CROWS+2) + j)*(EE+2) + q*4 + 1];
        dptr[0]=val.x; dptr[1]=val.y; dptr[2]=val.z; dptr[3]=val.w;
    }
    float bias = cb[layer];
    __syncthreads();
    for (int i = tid; i < CROWS*EE; i += 256) {
        int r = i / EE, e = i % EE;
        float acc = bias;
#pragma unroll
        for (int c = 0; c < 2; c++)
#pragma unroll
            for (int kh = 0; kh < 3; kh++)
#pragma unroll
                for (int kw = 0; kw < 3; kw++)
                    acc += w[c*9 + kh*3 + kw] * xs[(c*(CROWS+2) + r+kh)*(EE+2) + e + kw];
        float t = tanh_fast(acc);
        if (store) O[(s0+r)*EE + e] = t;
        os[r*EE + e] = t;
    }
    __syncthreads();
    int slot = (pair ? 4 : 1) + layer;
    for (int e = tid; e < EE; e += 256) {
        float s = 0.f;
#pragma unroll
        for (int r = 0; r < CROWS; r++) s += os[r*EE + e];
        atomicAdd(&g_x[b*FCIN + slot*EE + e], s*(1.f/SS));
    }
}

// ---------------- weighted avg-pool3 + residual update ----------------
__global__ __launch_bounds__(128) void k_pool() {
    int b = blockIdx.x, ch = blockIdx.y, pair = blockIdx.z;
    int s0 = ch * CROWS;
    const float* O = (pair ? g_o2 : g_o1) + b*SS*EE;
    float* Sx = (pair ? g_s2 : g_s1) + b*SS*EE;
    const float* wv = (pair ? g_w2 : g_w1) + b*SS;
    __shared__ float w[CROWS+2];
    if (threadIdx.x < CROWS+2) {
        int s = s0 + (int)threadIdx.x - 1;
        w[threadIdx.x] = (s >= 0 && s < SS) ? wv[s] : 0.f;
    }
    __syncthreads();
    for (int e = threadIdx.x; e < EE; e += 128) {
        float a = (s0 > 0) ? O[(s0-1)*EE + e] * w[0] : 0.f;
        float bmid = O[s0*EE + e] * w[1];
#pragma unroll
        for (int i = 0; i < CROWS; i++) {
            int s = s0 + i;
            float cnext = (s+1 < SS) ? O[(s+1)*EE + e] * w[i+2] : 0.f;
            Sx[s*EE + e] += (a + bmid + cnext) * (1.f/3.f);
            a = bmid; bmid = cnext;
        }
    }
}

// ---------------- fc1 GEMM: [512,1800] @ [1800,300]^T -> g_h ----------------
__global__ __launch_bounds__(256) void k_fc1(const float* __restrict__ fw) {
    int m0 = blockIdx.x * 64, n0 = blockIdx.y * 64;
    __shared__ float Xs[8][68];
    __shared__ float Ws2[8][68];
    int tid = threadIdx.x, ty = tid >> 4, tx = tid & 15;
    float acc[4][4];
#pragma unroll
    for (int u = 0; u < 4; u++)
#pragma unroll
        for (int v = 0; v < 4; v++) acc[u][v] = 0.f;

    for (int k0 = 0; k0 < FCIN; k0 += 8) {
        __syncthreads();
#pragma unroll 2
        for (int i = tid; i < 512; i += 256) {
            int r = i >> 3, kk = i & 7;
            Xs[kk][r] = g_x[(m0 + r)*FCIN + k0 + kk];
            int n = n0 + r;
            Ws2[kk][r] = (n < HH) ? fw[n*FCIN + k0 + kk] : 0.f;
        }
        __syncthreads();
#pragma unroll
        for (int kk = 0; kk < 8; kk++) {
            float4 xa = *(const float4*)&Xs[kk][ty*4];
            float4 wb = *(const float4*)&Ws2[kk][tx*4];
            float xv[4] = {xa.x, xa.y, xa.z, xa.w};
            float wvv[4] = {wb.x, wb.y, wb.z, wb.w};
#pragma unroll
            for (int u = 0; u < 4; u++)
#pragma unroll
                for (int v = 0; v < 4; v++) acc[u][v] += xv[u]*wvv[v];
        }
    }
#pragma unroll
    for (int u = 0; u < 4; u++) {
        int m = m0 + ty*4 + u;
#pragma unroll
        for (int v = 0; v < 4; v++) {
            int n = n0 + tx*4 + v;
            if (n < HH) g_h[m*HH + n] = acc[u][v];
        }
    }
}

// ---------------- LN + relu + fc2 + softmax ----------------
__device__ __forceinline__ float block_reduce512(float v, float* red) {
    int tid = threadIdx.x;
    red[tid] = v;
    __syncthreads();
    for (int off = 256; off > 0; off >>= 1) {
        if (tid < off) red[tid] += red[tid + off];
        __syncthreads();
    }
    float r = red[0];
    __syncthreads();
    return r;
}

__global__ __launch_bounds__(512) void k_head(const float* __restrict__ fc1b,
                                              const float* __restrict__ lng,
                                              const float* __restrict__ lnb,
                                              const float* __restrict__ fc2w,
                                              const float* __restrict__ fc2b,
                                              float* __restrict__ out) {
    int b = blockIdx.x, tid = threadIdx.x;
    __shared__ float red[512];
    bool act = tid < HH;
    float h = act ? (g_h[b*HH + tid] + fc1b[tid]) : 0.f;
    float mu = block_reduce512(h, red) * (1.f/HH);
    float d = act ? (h - mu) : 0.f;
    float var = block_reduce512(d*d, red) * (1.f/HH);
    float hn = 0.f;
    if (act) {
        hn = d * rsqrtf(var + 1e-5f) * lng[tid] + lnb[tid];
        hn = fmaxf(hn, 0.f);
    }
    float o0 = block_reduce512(act ? hn*fc2w[tid]      : 0.f, red);
    float o1 = block_reduce512(act ? hn*fc2w[HH + tid] : 0.f, red);
    if (tid == 0) {
        o0 += fc2b[0];
        o1 += fc2b[1];
        out[b*2 + 0] = o0;
        out[b*2 + 1] = o1;
        float m = fmaxf(o0, o1);
        float e0 = expf(o0 - m), e1 = expf(o1 - m);
        float inv = 1.f/(e0 + e1);
        out[BB*2 + b*2 + 0] = e0*inv;
        out[BB*2 + b*2 + 1] = e1*inv;
    }
}

// ---------------- launch ----------------
extern "C" void kernel_launch(void* const* d_in, const int* in_sizes, int n_in,
                              void* d_out, int out_size) {
    (void)in_sizes; (void)n_in; (void)out_size;
    const int*   seq1 = (const int*)d_in[0];
    const int*   seq2 = (const int*)d_in[1];
    const float* emb  = (const float*)d_in[2];
    const float* W    = (const float*)d_in[3];
    const float* cw   = (const float*)d_in[4];
    const float* cb   = (const float*)d_in[5];
    const float* fc1w = (const float*)d_in[6];
    const float* fc1b = (const float*)d_in[7];
    const float* lng  = (const float*)d_in[8];
    const float* lnb  = (const float*)d_in[9];
    const float* fc2w = (const float*)d_in[10];
    const float* fc2b = (const float*)d_in[11];
    float* out = (float*)d_out;

    const int SM_MATCH = (2*SS*MPAD*2 + 2*SS + 4*SS + 2*SS) * 4;    // ~77.8KB
    const int SM_FGEMM = 2*FBUF*4;                                   // ~89.1KB
    const int SM_CONV  = (2*(CROWS+2)*(EE+2) + CROWS*EE + 18) * 4;   // ~62.8KB

    cudaFuncSetAttribute(k_match, cudaFuncAttributeMaxDynamicSharedMemorySize, SM_MATCH);
    cudaFuncSetAttribute(k_fgemm, cudaFuncAttributeMaxDynamicSharedMemorySize, SM_FGEMM);
    cudaFuncSetAttribute(k_conv,  cudaFuncAttributeMaxDynamicSharedMemorySize, SM_CONV);

    k_wprep<<<dim3(320, LL), 128>>>(W);
    k_gather<<<BB, 256>>>(seq1, seq2, emb);
    for (int l = 0; l < LL; l++) {
        int last = (l == LL-1);
        k_match<<<BB, 256, SM_MATCH>>>(0);
        k_zx<<<(BB*2*EE + 255)/256, 256>>>(l);
        k_fgemm<<<dim3(BB, 5), 256, SM_FGEMM>>>(l);
        k_conv<<<dim3(BB, 8, 2), 256, SM_CONV>>>(cw, cb, l, last ? 0 : 1);
        if (!last) {
            k_match<<<BB, 256, SM_MATCH>>>(1);
            k_pool<<<dim3(BB, 8, 2), 128>>>();
        }
    }
    k_fc1<<<dim3(8, 5), 256>>>(fc1w);
    k_head<<<BB, 512>>>(fc1b, lng, lnb, fc2w, fc2b, out);
}

// round 10
// speedup vs baseline: 1.3370x; 1.2305x over previous
#include <cuda_runtime.h>
#include <math.h>
#include <stdint.h>

#define BB 512
#define SS 128
#define EE 300
#define LL 2
#define HH 300
#define FCIN 1800   // E*(1+L)*2
#define CROWS 16

// ---------------- device scratch (no allocation allowed) ----------------
__device__ float g_s1[BB*SS*EE];
__device__ float g_s2[BB*SS*EE];
__device__ float g_f1[BB*SS*EE];
__device__ float g_f2[BB*SS*EE];
__device__ float g_o1[BB*SS*EE];
__device__ float g_o2[BB*SS*EE];
__device__ float g_A [BB*SS*SS];
__device__ float g_Wt[LL*320*SS];   // pre-transposed, tf32-rounded W: [l][n][k]
__device__ float g_w1[BB*SS];
__device__ float g_w2[BB*SS];
__device__ float g_v1[BB*SS];
__device__ float g_v2[BB*SS];
__device__ float g_x [BB*FCIN];
__device__ float g_h [BB*HH];

__device__ __forceinline__ float tanh_fast(float x) {
    float r; asm("tanh.approx.f32 %0, %1;" : "=f"(r) : "f"(x)); return r;
}
__device__ __forceinline__ uint32_t to_tf32(float x) {
    uint32_t r; asm("cvt.rna.tf32.f32 %0, %1;" : "=r"(r) : "f"(x)); return r;
}
__device__ __forceinline__ void cpasync16(void* dst, const void* src) {
    uint32_t d = (uint32_t)__cvta_generic_to_shared(dst);
    asm volatile("cp.async.ca.shared.global [%0], [%1], 16;\n" :: "r"(d), "l"(src));
}
#define MMA_TF32(C, A, B) \
    asm volatile("mma.sync.aligned.m16n8k8.row.col.f32.tf32.tf32.f32 " \
        "{%0,%1,%2,%3}, {%4,%5,%6,%7}, {%8,%9}, {%0,%1,%2,%3};" \
        : "+f"((C)[0]), "+f"((C)[1]), "+f"((C)[2]), "+f"((C)[3]) \
        : "r"((A)[0]), "r"((A)[1]), "r"((A)[2]), "r"((A)[3]), \
          "r"((B)[0]), "r"((B)[1]))

// ---------------- W prep: g_Wt[l][n][k] = tf32(W[l][k][n]), zero-pad n>=300 ----
__global__ void k_wprep(const float* __restrict__ W) {
    int n = blockIdx.x, l = blockIdx.y, k = threadIdx.x;
    float v = 0.f;
    if (n < EE) v = W[(size_t)l*SS*EE + k*EE + n];
    g_Wt[(l*320 + n)*SS + k] = __uint_as_float(to_tf32(v));
}

// ---------------- embedding gather + masks + fused mean(slot0) ----------------
__global__ __launch_bounds__(256) void k_gather(const int* __restrict__ seq1,
                                                const int* __restrict__ seq2,
                                                const float* __restrict__ emb) {
    __shared__ float msum[2][EE];
    int b = blockIdx.x;
    int tid = threadIdx.x;
    int warp = tid >> 5, lane = tid & 31;
    for (int i = tid; i < 2*EE; i += 256) ((float*)msum)[i] = 0.f;
    for (int i = tid; i < SS; i += 256) {
        g_v1[b*SS+i] = (seq1[b*SS+i] != 0) ? 1.f : 0.f;
        g_v2[b*SS+i] = (seq2[b*SS+i] != 0) ? 1.f : 0.f;
    }
    __syncthreads();
    for (int idx = warp; idx < 2*SS; idx += 8) {
        int s = idx >> 1, sel = idx & 1;
        int tok = sel ? seq2[b*SS+s] : seq1[b*SS+s];
        const float4* src = (const float4*)(emb + (long)tok*EE);
        float4* dst = (float4*)((sel ? g_s2 : g_s1) + (b*SS+s)*EE);
        for (int j = lane; j < EE/4; j += 32) {
            float4 v = src[j];
            dst[j] = v;
            atomicAdd(&msum[sel][4*j+0], v.x);
            atomicAdd(&msum[sel][4*j+1], v.y);
            atomicAdd(&msum[sel][4*j+2], v.z);
            atomicAdd(&msum[sel][4*j+3], v.w);
        }
    }
    __syncthreads();
    for (int e = tid; e < EE; e += 256) {
        g_x[b*FCIN + e]        = msum[0][e]*(1.f/SS);
        g_x[b*FCIN + 3*EE + e] = msum[1][e]*(1.f/SS);
    }
}

// ---------------- zero mean slots for layer l (conv accumulates atomically) ----
__global__ void k_zx(int l) {
    int i = blockIdx.x*256 + threadIdx.x;
    if (i >= BB*2*EE) return;
    int b = i / (2*EE);
    int r = i % (2*EE);
    int half = r / EE, e = r % EE;
    int slot = half ? (4+l) : (1+l);
    g_x[b*FCIN + slot*EE + e] = 0.f;
}

// ---------------- match-score, tensor-core tf32 ----------------
// mode=0: s1/s2 -> store A (tf32-rounded)   mode=1: o1/o2 -> w1, w2
#define MPAD 36
#define MCH 10      // ceil(300/32)
__global__ __launch_bounds__(256) void k_match(int mode) {
    extern __shared__ float sm[];
    float* Xs = sm;                       // [2][128][36]
    float* Ys = Xs + 2*SS*MPAD;           // [2][128][36]
    float* n1s = Ys + 2*SS*MPAD;          // [128]
    float* n2s = n1s + SS;                // [128]
    float* rowbuf = n2s + SS;             // [4][128]
    float* colbuf = rowbuf + 4*SS;        // [2][128]

    int b = blockIdx.x;
    const float* X = (mode ? g_o1 : g_s1) + b*SS*EE;
    const float* Y = (mode ? g_o2 : g_s2) + b*SS*EE;
    int tid = threadIdx.x;
    int lane = tid & 31, wid = tid >> 5;
    int g = lane >> 2, tig = lane & 3;
    int wm = wid & 1, wn = wid >> 1;

    int lr = tid >> 1, lh = tid & 1;
    const float* Xr = X + lr*EE + lh*16;
    const float* Yr = Y + lr*EE + lh*16;
    float mvx = g_v1[b*SS + lr];
    float mvy = g_v2[b*SS + lr];
    float nx = 0.f, ny = 0.f;
    float4 vx[4], vy[4];

#define FETCH(c) do { \
    int kb = (c)*32; \
    _Pragma("unroll") for (int j = 0; j < 4; j++) { \
        int k = kb + lh*16 + 4*j; \
        if (k < EE) { vx[j] = *(const float4*)(Xr + kb + 4*j); \
                      vy[j] = *(const float4*)(Yr + kb + 4*j); } \
        else { vx[j] = make_float4(0.f,0.f,0.f,0.f); vy[j] = vx[j]; } \
    } } while(0)

#define STBUF(buf) do { \
    float* xd = Xs + (buf)*SS*MPAD + lr*MPAD + lh*16; \
    float* yd = Ys + (buf)*SS*MPAD + lr*MPAD + lh*16; \
    _Pragma("unroll") for (int j = 0; j < 4; j++) { \
        float x0=vx[j].x*mvx, x1=vx[j].y*mvx, x2=vx[j].z*mvx, x3=vx[j].w*mvx; \
        float y0=vy[j].x*mvy, y1=vy[j].y*mvy, y2=vy[j].z*mvy, y3=vy[j].w*mvy; \
        nx += x0*x0+x1*x1+x2*x2+x3*x3; \
        ny += y0*y0+y1*y1+y2*y2+y3*y3; \
        ((uint32_t*)xd)[4*j+0]=to_tf32(x0); ((uint32_t*)xd)[4*j+1]=to_tf32(x1); \
        ((uint32_t*)xd)[4*j+2]=to_tf32(x2); ((uint32_t*)xd)[4*j+3]=to_tf32(x3); \
        ((uint32_t*)yd)[4*j+0]=to_tf32(y0); ((uint32_t*)yd)[4*j+1]=to_tf32(y1); \
        ((uint32_t*)yd)[4*j+2]=to_tf32(y2); ((uint32_t*)yd)[4*j+3]=to_tf32(y3); \
    } } while(0)

    float acc[4][4][4];
#pragma unroll
    for (int mt = 0; mt < 4; mt++)
#pragma unroll
        for (int nt = 0; nt < 4; nt++)
#pragma unroll
            for (int q = 0; q < 4; q++) acc[mt][nt][q] = 0.f;

    FETCH(0); STBUF(0);
    __syncthreads();

    for (int c = 0; c < MCH; c++) {
        int cur = c & 1;
        if (c + 1 < MCH) FETCH(c+1);
        const uint32_t* xb = (const uint32_t*)(Xs + cur*SS*MPAD);
        const uint32_t* yb = (const uint32_t*)(Ys + cur*SS*MPAD);
#pragma unroll
        for (int ks = 0; ks < 4; ks++) {
            int kk = ks*8;
            uint32_t a[4][4], bf[4][2];
#pragma unroll
            for (int mt = 0; mt < 4; mt++) {
                int row = wm*64 + mt*16 + g;
                a[mt][0] = xb[row*MPAD + kk + tig];
                a[mt][1] = xb[(row+8)*MPAD + kk + tig];
                a[mt][2] = xb[row*MPAD + kk + tig + 4];
                a[mt][3] = xb[(row+8)*MPAD + kk + tig + 4];
            }
#pragma unroll
            for (int nt = 0; nt < 4; nt++) {
                int cr = wn*32 + nt*8 + g;
                bf[nt][0] = yb[cr*MPAD + kk + tig];
                bf[nt][1] = yb[cr*MPAD + kk + tig + 4];
            }
#pragma unroll
            for (int mt = 0; mt < 4; mt++)
#pragma unroll
                for (int nt = 0; nt < 4; nt++)
                    MMA_TF32(acc[mt][nt], a[mt], bf[nt]);
        }
        if (c + 1 < MCH) STBUF(cur ^ 1);
        __syncthreads();
    }

    nx += __shfl_xor_sync(0xffffffffu, nx, 1);
    ny += __shfl_xor_sync(0xffffffffu, ny, 1);
    if (lh == 0) { n1s[lr] = nx; n2s[lr] = ny; }
    __syncthreads();

    if (mode == 0) {
        float* Ao = g_A + b*SS*SS;
#pragma unroll
        for (int mt = 0; mt < 4; mt++) {
            int row = wm*64 + mt*16 + g;
            float nr0 = n1s[row], nr1 = n1s[row+8];
#pragma unroll
            for (int nt = 0; nt < 4; nt++) {
                int col = wn*32 + nt*8 + 2*tig;
                float nc0 = n2s[col], nc1 = n2s[col+1];
                float d00 = sqrtf(fmaxf(nr0 + nc0 - 2.f*acc[mt][nt][0], 0.f));
                float d01 = sqrtf(fmaxf(nr0 + nc1 - 2.f*acc[mt][nt][1], 0.f));
                float d10 = sqrtf(fmaxf(nr1 + nc0 - 2.f*acc[mt][nt][2], 0.f));
                float d11 = sqrtf(fmaxf(nr1 + nc1 - 2.f*acc[mt][nt][3], 0.f));
                *(float2*)(Ao + row*SS + col) = make_float2(
                    __uint_as_float(to_tf32(1.f/(1.f+d00))),
                    __uint_as_float(to_tf32(1.f/(1.f+d01))));
                *(float2*)(Ao + (row+8)*SS + col) = make_float2(
                    __uint_as_float(to_tf32(1.f/(1.f+d10))),
                    __uint_as_float(to_tf32(1.f/(1.f+d11))));
            }
        }
    } else {
        float cs0[4], cs1[4];
#pragma unroll
        for (int nt = 0; nt < 4; nt++) { cs0[nt] = 0.f; cs1[nt] = 0.f; }
#pragma unroll
        for (int mt = 0; mt < 4; mt++) {
            int row = wm*64 + mt*16 + g;
            float nr0 = n1s[row], nr1 = n1s[row+8];
            float rlo = 0.f, rhi = 0.f;
#pragma unroll
            for (int nt = 0; nt < 4; nt++) {
                int col = wn*32 + nt*8 + 2*tig;
                float nc0 = n2s[col], nc1 = n2s[col+1];
                float a00 = 1.f/(1.f + sqrtf(fmaxf(nr0 + nc0 - 2.f*acc[mt][nt][0], 0.f)));
                float a01 = 1.f/(1.f + sqrtf(fmaxf(nr0 + nc1 - 2.f*acc[mt][nt][1], 0.f)));
                float a10 = 1.f/(1.f + sqrtf(fmaxf(nr1 + nc0 - 2.f*acc[mt][nt][2], 0.f)));
                float a11 = 1.f/(1.f + sqrtf(fmaxf(nr1 + nc1 - 2.f*acc[mt][nt][3], 0.f)));
                rlo += a00 + a01;
                rhi += a10 + a11;
                cs0[nt] += a00 + a10;
                cs1[nt] += a01 + a11;
            }
            rlo += __shfl_xor_sync(0xffffffffu, rlo, 1);
            rlo += __shfl_xor_sync(0xffffffffu, rlo, 2);
            rhi += __shfl_xor_sync(0xffffffffu, rhi, 1);
            rhi += __shfl_xor_sync(0xffffffffu, rhi, 2);
            if (tig == 0) {
                rowbuf[wn*SS + row]   = rlo;
                rowbuf[wn*SS + row+8] = rhi;
            }
        }
#pragma unroll
        for (int nt = 0; nt < 4; nt++) {
            float c0 = cs0[nt], c1 = cs1[nt];
            c0 += __shfl_xor_sync(0xffffffffu, c0, 4);
            c0 += __shfl_xor_sync(0xffffffffu, c0, 8);
            c0 += __shfl_xor_sync(0xffffffffu, c0, 16);
            c1 += __shfl_xor_sync(0xffffffffu, c1, 4);
            c1 += __shfl_xor_sync(0xffffffffu, c1, 8);
            c1 += __shfl_xor_sync(0xffffffffu, c1, 16);
            if (g == 0) {
                int col = wn*32 + nt*8 + 2*tig;
                colbuf[wm*SS + col]     = c0;
                colbuf[wm*SS + col + 1] = c1;
            }
        }
        __syncthreads();
        if (tid < SS) {
            g_w1[b*SS + tid] = rowbuf[tid] + rowbuf[SS+tid] + rowbuf[2*SS+tid] + rowbuf[3*SS+tid];
            g_w2[b*SS + tid] = colbuf[tid] + colbuf[SS+tid];
        }
    }
#undef FETCH
#undef STBUF
}

// ---------------- f1=A@W, f2=A^T@W, cp.async double-buffered K-chunks ---------
#define APAD 36
#define A2PAD 132
#define FBUF (128*APAD + 32*A2PAD + 64*APAD)   // 11136 words per buffer
__global__ __launch_bounds__(256, 2) void k_fgemm(int layer) {
    extern __shared__ float sm[];
    int b = blockIdx.x;
    int n0 = blockIdx.y * 64;
    const float* Ab = g_A + b*SS*SS;
    const float* Wt = g_Wt + (size_t)layer*320*SS;
    int tid = threadIdx.x;
    int lane = tid & 31, wid = tid >> 5;
    int g = lane >> 2, tig = lane & 3;
    int half = wid >> 2, wm = wid & 3;

#define LOADCH(c, buf) do { \
    float* base_ = sm + (buf)*FBUF; \
    float* A1_ = base_; \
    float* A2_ = base_ + 128*APAD; \
    float* Wb_ = A2_ + 32*A2PAD; \
    int k0_ = (c)*32; \
    _Pragma("unroll") for (int j = 0; j < 4; j++) { \
        int i = tid + 256*j; int r = i >> 3, h = i & 7; \
        cpasync16(A1_ + r*APAD + h*4, Ab + r*SS + k0_ + h*4); \
    } \
    _Pragma("unroll") for (int j = 0; j < 4; j++) { \
        int i = tid + 256*j; int kk = i >> 5, c4 = i & 31; \
        cpasync16(A2_ + kk*A2PAD + c4*4, Ab + (k0_+kk)*SS + c4*4); \
    } \
    _Pragma("unroll") for (int j = 0; j < 2; j++) { \
        int i = tid + 256*j; int n = i >> 3, h = i & 7; \
        cpasync16(Wb_ + n*APAD + h*4, Wt + (n0+n)*SS + k0_ + h*4); \
    } \
    asm volatile("cp.async.commit_group;\n" ::); \
} while (0)

    float acc[2][8][4];
#pragma unroll
    for (int mt = 0; mt < 2; mt++)
#pragma unroll
        for (int nt = 0; nt < 8; nt++)
#pragma unroll
            for (int q = 0; q < 4; q++) acc[mt][nt][q] = 0.f;

    LOADCH(0, 0);
    for (int c = 0; c < 4; c++) {
        if (c < 3) {
            LOADCH(c+1, (c+1)&1);
            asm volatile("cp.async.wait_group 1;\n" ::);
        } else {
            asm volatile("cp.async.wait_group 0;\n" ::);
        }
        __syncthreads();
        const uint32_t* base = (const uint32_t*)(sm + (c&1)*FBUF);
        const uint32_t* A1 = base;
        const uint32_t* A2 = base + 128*APAD;
        const uint32_t* Wb = A2 + 32*A2PAD;
#pragma unroll
        for (int ks = 0; ks < 4; ks++) {
            int kk = ks*8;
            uint32_t a[2][4], bf[8][2];
#pragma unroll
            for (int mt = 0; mt < 2; mt++) {
                int row = wm*32 + mt*16 + g;
                if (half == 0) {
                    a[mt][0] = A1[row*APAD + kk + tig];
                    a[mt][1] = A1[(row+8)*APAD + kk + tig];
                    a[mt][2] = A1[row*APAD + kk + tig + 4];
                    a[mt][3] = A1[(row+8)*APAD + kk + tig + 4];
                } else {
                    a[mt][0] = A2[(kk+tig)*A2PAD + row];
                    a[mt][1] = A2[(kk+tig)*A2PAD + row + 8];
                    a[mt][2] = A2[(kk+tig+4)*A2PAD + row];
                    a[mt][3] = A2[(kk+tig+4)*A2PAD + row + 8];
                }
            }
#pragma unroll
            for (int nt = 0; nt < 8; nt++) {
                int cn = nt*8 + g;
                bf[nt][0] = Wb[cn*APAD + kk + tig];
                bf[nt][1] = Wb[cn*APAD + kk + tig + 4];
            }
#pragma unroll
            for (int mt = 0; mt < 2; mt++)
#pragma unroll
                for (int nt = 0; nt < 8; nt++)
                    MMA_TF32(acc[mt][nt], a[mt], bf[nt]);
        }
        __syncthreads();
    }
#undef LOADCH

    float* out = (half ? g_f2 : g_f1) + b*SS*EE;
#pragma unroll
    for (int mt = 0; mt < 2; mt++) {
        int row = wm*32 + mt*16 + g;
#pragma unroll
        for (int nt = 0; nt < 8; nt++) {
            int col = n0 + nt*8 + 2*tig;
            if (col < EE) {
                *(float2*)(out + row*EE + col)     = make_float2(acc[mt][nt][0], acc[mt][nt][1]);
                *(float2*)(out + (row+8)*EE + col) = make_float2(acc[mt][nt][2], acc[mt][nt][3]);
            }
        }
    }
}

// ---------------- conv 2in->1out 3x3 + tanh + fused mean: column-per-thread ---
// grid (B, 8, 2), block 320; smem only xs (43.6KB) -> 5 CTAs/SM
__global__ __launch_bounds__(320) void k_conv(const float* __restrict__ cw,
                                              const float* __restrict__ cb,
                                              int layer, int store) {
    extern __shared__ float sm[];
    float* xs = sm;                       // [2][18][302]
    float* w  = xs + 2*(CROWS+2)*(EE+2);  // [18]

    int b = blockIdx.x, ch = blockIdx.y, pair = blockIdx.z;
    int s0 = ch * CROWS;
    const float* X0 = (pair ? g_s2 : g_s1) + b*SS*EE;
    const float* X1 = (pair ? g_f2 : g_f1) + b*SS*EE;
    float* O = (pair ? g_o2 : g_o1) + b*SS*EE;
    int tid = threadIdx.x;
    if (tid < 18) w[tid] = cw[layer*18 + tid];
    if (tid < 2*(CROWS+2)*2) {   // zero side padding
        int c = tid / (2*(CROWS+2));
        int rem = tid % (2*(CROWS+2));
        int j = rem >> 1, side = rem & 1;
        xs[(c*(CROWS+2) + j)*(EE+2) + (side ? EE+1 : 0)] = 0.f;
    }
    for (int i = tid; i < 2*(CROWS+2)*(EE/4); i += 320) {
        int c = i / ((CROWS+2)*(EE/4));
        int rem = i % ((CROWS+2)*(EE/4));
        int j = rem / (EE/4), q = rem % (EE/4);
        int srow = s0 + j - 1;
        float4 val = make_float4(0.f,0.f,0.f,0.f);
        if (srow >= 0 && srow < SS)
            val = *(const float4*)((c ? X1 : X0) + srow*EE + q*4);
        float* dptr = &xs[(c*(CROWS+2) + j)*(EE+2) + q*4 + 1];
        dptr[0]=val.x; dptr[1]=val.y; dptr[2]=val.z; dptr[3]=val.w;
    }
    __syncthreads();
    if (tid < EE) {
        int e = tid;
        float bias = cb[layer];
        const float* xs0 = xs;
        const float* xs1 = xs + (CROWS+2)*(EE+2);
        float sv[3][3], fv[3][3];
#pragma unroll
        for (int kh = 0; kh < 2; kh++)
#pragma unroll
            for (int kw = 0; kw < 3; kw++) {
                sv[kh][kw] = xs0[kh*(EE+2) + e + kw];
                fv[kh][kw] = xs1[kh*(EE+2) + e + kw];
            }
        float colsum = 0.f;
#pragma unroll 4
        for (int r = 0; r < CROWS; r++) {
#pragma unroll
            for (int kw = 0; kw < 3; kw++) {
                sv[2][kw] = xs0[(r+2)*(EE+2) + e + kw];
                fv[2][kw] = xs1[(r+2)*(EE+2) + e + kw];
            }
            float acc = bias;
#pragma unroll
            for (int kh = 0; kh < 3; kh++)
#pragma unroll
                for (int kw = 0; kw < 3; kw++)
                    acc += w[kh*3+kw]*sv[kh][kw] + w[9+kh*3+kw]*fv[kh][kw];
            float t = tanh_fast(acc);
            if (store) O[(s0+r)*EE + e] = t;
            colsum += t;
#pragma unroll
            for (int kw = 0; kw < 3; kw++) {
                sv[0][kw] = sv[1][kw]; sv[1][kw] = sv[2][kw];
                fv[0][kw] = fv[1][kw]; fv[1][kw] = fv[2][kw];
            }
        }
        int slot = (pair ? 4 : 1) + layer;
        atomicAdd(&g_x[b*FCIN + slot*EE + e], colsum*(1.f/SS));
    }
}

// ---------------- weighted avg-pool3 + residual update, float4 ----------------
__global__ __launch_bounds__(96) void k_pool() {
    int b = blockIdx.x, ch = blockIdx.y, pair = blockIdx.z;
    int s0 = ch * CROWS;
    const float* O = (pair ? g_o2 : g_o1) + b*SS*EE;
    float* Sx = (pair ? g_s2 : g_s1) + b*SS*EE;
    const float* wv = (pair ? g_w2 : g_w1) + b*SS;
    __shared__ float w[CROWS+2];
    if (threadIdx.x < CROWS+2) {
        int s = s0 + (int)threadIdx.x - 1;
        w[threadIdx.x] = (s >= 0 && s < SS) ? wv[s] : 0.f;
    }
    __syncthreads();
    int t = threadIdx.x;
    if (t >= 75) return;
    int e = t*4;
    float4 a = make_float4(0.f,0.f,0.f,0.f);
    if (s0 > 0) {
        float4 v = *(const float4*)(O + (s0-1)*EE + e);
        a = make_float4(v.x*w[0], v.y*w[0], v.z*w[0], v.w*w[0]);
    }
    float4 v0 = *(const float4*)(O + s0*EE + e);
    float4 bm = make_float4(v0.x*w[1], v0.y*w[1], v0.z*w[1], v0.w*w[1]);
#pragma unroll
    for (int i = 0; i < CROWS; i++) {
        int s = s0 + i;
        float4 cn = make_float4(0.f,0.f,0.f,0.f);
        if (s+1 < SS) {
            float4 v = *(const float4*)(O + (s+1)*EE + e);
            float ww = w[i+2];
            cn = make_float4(v.x*ww, v.y*ww, v.z*ww, v.w*ww);
        }
        float4 sx = *(float4*)(Sx + s*EE + e);
        sx.x += (a.x + bm.x + cn.x) * (1.f/3.f);
        sx.y += (a.y + bm.y + cn.y) * (1.f/3.f);
        sx.z += (a.z + bm.z + cn.z) * (1.f/3.f);
        sx.w += (a.w + bm.w + cn.w) * (1.f/3.f);
        *(float4*)(Sx + s*EE + e) = sx;
        a = bm; bm = cn;
    }
}

// ---------------- fc1 GEMM: [512,1800] @ [1800,300]^T -> g_h ----------------
__global__ __launch_bounds__(256) void k_fc1(const float* __restrict__ fw) {
    int m0 = blockIdx.x * 64, n0 = blockIdx.y * 64;
    __shared__ float Xs[8][68];
    __shared__ float Ws2[8][68];
    int tid = threadIdx.x, ty = tid >> 4, tx = tid & 15;
    float acc[4][4];
#pragma unroll
    for (int u = 0; u < 4; u++)
#pragma unroll
        for (int v = 0; v < 4; v++) acc[u][v] = 0.f;

    for (int k0 = 0; k0 < FCIN; k0 += 8) {
        __syncthreads();
#pragma unroll 2
        for (int i = tid; i < 512; i += 256) {
            int r = i >> 3, kk = i & 7;
            Xs[kk][r] = g_x[(m0 + r)*FCIN + k0 + kk];
            int n = n0 + r;
            Ws2[kk][r] = (n < HH) ? fw[n*FCIN + k0 + kk] : 0.f;
        }
        __syncthreads();
#pragma unroll
        for (int kk = 0; kk < 8; kk++) {
            float4 xa = *(const float4*)&Xs[kk][ty*4];
            float4 wb = *(const float4*)&Ws2[kk][tx*4];
            float xv[4] = {xa.x, xa.y, xa.z, xa.w};
            float wvv[4] = {wb.x, wb.y, wb.z, wb.w};
#pragma unroll
            for (int u = 0; u < 4; u++)
#pragma unroll
                for (int v = 0; v < 4; v++) acc[u][v] += xv[u]*wvv[v];
        }
    }
#pragma unroll
    for (int u = 0; u < 4; u++) {
        int m = m0 + ty*4 + u;
#pragma unroll
        for (int v = 0; v < 4; v++) {
            int n = n0 + tx*4 + v;
            if (n < HH) g_h[m*HH + n] = acc[u][v];
        }
    }
}

// ---------------- LN + relu + fc2 + softmax ----------------
__device__ __forceinline__ float block_reduce512(float v, float* red) {
    int tid = threadIdx.x;
    red[tid] = v;
    __syncthreads();
    for (int off = 256; off > 0; off >>= 1) {
        if (tid < off) red[tid] += red[tid + off];
        __syncthreads();
    }
    float r = red[0];
    __syncthreads();
    return r;
}

__global__ __launch_bounds__(512) void k_head(const float* __restrict__ fc1b,
                                              const float* __restrict__ lng,
                                              const float* __restrict__ lnb,
                                              const float* __restrict__ fc2w,
                                              const float* __restrict__ fc2b,
                                              float* __restrict__ out) {
    int b = blockIdx.x, tid = threadIdx.x;
    __shared__ float red[512];
    bool act = tid < HH;
    float h = act ? (g_h[b*HH + tid] + fc1b[tid]) : 0.f;
    float mu = block_reduce512(h, red) * (1.f/HH);
    float d = act ? (h - mu) : 0.f;
    float var = block_reduce512(d*d, red) * (1.f/HH);
    float hn = 0.f;
    if (act) {
        hn = d * rsqrtf(var + 1e-5f) * lng[tid] + lnb[tid];
        hn = fmaxf(hn, 0.f);
    }
    float o0 = block_reduce512(act ? hn*fc2w[tid]      : 0.f, red);
    float o1 = block_reduce512(act ? hn*fc2w[HH + tid] : 0.f, red);
    if (tid == 0) {
        o0 += fc2b[0];
        o1 += fc2b[1];
        out[b*2 + 0] = o0;
        out[b*2 + 1] = o1;
        float m = fmaxf(o0, o1);
        float e0 = expf(o0 - m), e1 = expf(o1 - m);
        float inv = 1.f/(e0 + e1);
        out[BB*2 + b*2 + 0] = e0*inv;
        out[BB*2 + b*2 + 1] = e1*inv;
    }
}

// ---------------- launch ----------------
extern "C" void kernel_launch(void* const* d_in, const int* in_sizes, int n_in,
                              void* d_out, int out_size) {
    (void)in_sizes; (void)n_in; (void)out_size;
    const int*   seq1 = (const int*)d_in[0];
    const int*   seq2 = (const int*)d_in[1];
    const float* emb  = (const float*)d_in[2];
    const float* W    = (const float*)d_in[3];
    const float* cw   = (const float*)d_in[4];
    const float* cb   = (const float*)d_in[5];
    const float* fc1w = (const float*)d_in[6];
    const float* fc1b = (const float*)d_in[7];
    const float* lng  = (const float*)d_in[8];
    const float* lnb  = (const float*)d_in[9];
    const float* fc2w = (const float*)d_in[10];
    const float* fc2b = (const float*)d_in[11];
    float* out = (float*)d_out;

    const int SM_MATCH = (2*SS*MPAD*2 + 2*SS + 4*SS + 2*SS) * 4;    // ~77.8KB
    const int SM_FGEMM = 2*FBUF*4;                                   // ~89.1KB
    const int SM_CONV  = (2*(CROWS+2)*(EE+2) + 18) * 4;              // ~43.6KB

    cudaFuncSetAttribute(k_match, cudaFuncAttributeMaxDynamicSharedMemorySize, SM_MATCH);
    cudaFuncSetAttribute(k_fgemm, cudaFuncAttributeMaxDynamicSharedMemorySize, SM_FGEMM);
    cudaFuncSetAttribute(k_conv,  cudaFuncAttributeMaxDynamicSharedMemorySize, SM_CONV);

    k_wprep<<<dim3(320, LL), 128>>>(W);
    k_gather<<<BB, 256>>>(seq1, seq2, emb);
    for (int l = 0; l < LL; l++) {
        int last = (l == LL-1);
        k_match<<<BB, 256, SM_MATCH>>>(0);
        k_zx<<<(BB*2*EE + 255)/256, 256>>>(l);
        k_fgemm<<<dim3(BB, 5), 256, SM_FGEMM>>>(l);
        k_conv<<<dim3(BB, 8, 2), 320, SM_CONV>>>(cw, cb, l, last ? 0 : 1);
        if (!last) {
            k_match<<<BB, 256, SM_MATCH>>>(1);
            k_pool<<<dim3(BB, 8, 2), 96>>>();
        }
    }
    k_fc1<<<dim3(8, 5), 256>>>(fc1w);
    k_head<<<BB, 512>>>(fc1b, lng, lnb, fc2w, fc2b, out);
}

// round 11
// speedup vs baseline: 1.4724x; 1.1013x over previous
#include <cuda_runtime.h>
#include <math.h>
#include <stdint.h>

#define BB 512
#define SS 128
#define EE 300
#define LL 2
#define HH 300
#define FCIN 1800   // E*(1+L)*2
#define CROWS 16

// ---------------- device scratch (no allocation allowed) ----------------
__device__ float g_s1[BB*SS*EE];
__device__ float g_s2[BB*SS*EE];
__device__ float g_f1[BB*SS*EE];
__device__ float g_f2[BB*SS*EE];
__device__ float g_o1[BB*SS*EE];
__device__ float g_o2[BB*SS*EE];
__device__ float g_A [BB*SS*SS];
__device__ float g_Wt[LL*320*SS];   // pre-transposed, tf32-rounded W: [l][n][k]
__device__ float g_w1[BB*SS];
__device__ float g_w2[BB*SS];
__device__ float g_v1[BB*SS];
__device__ float g_v2[BB*SS];
__device__ float g_x [BB*FCIN];
__device__ float g_h [BB*HH];

__device__ __forceinline__ float tanh_fast(float x) {
    float r; asm("tanh.approx.f32 %0, %1;" : "=f"(r) : "f"(x)); return r;
}
__device__ __forceinline__ uint32_t to_tf32(float x) {
    uint32_t r; asm("cvt.rna.tf32.f32 %0, %1;" : "=r"(r) : "f"(x)); return r;
}
__device__ __forceinline__ void cpasync16(void* dst, const void* src) {
    uint32_t d = (uint32_t)__cvta_generic_to_shared(dst);
    asm volatile("cp.async.ca.shared.global [%0], [%1], 16;\n" :: "r"(d), "l"(src));
}
#define MMA_TF32(C, A, B) \
    asm volatile("mma.sync.aligned.m16n8k8.row.col.f32.tf32.tf32.f32 " \
        "{%0,%1,%2,%3}, {%4,%5,%6,%7}, {%8,%9}, {%0,%1,%2,%3};" \
        : "+f"((C)[0]), "+f"((C)[1]), "+f"((C)[2]), "+f"((C)[3]) \
        : "r"((A)[0]), "r"((A)[1]), "r"((A)[2]), "r"((A)[3]), \
          "r"((B)[0]), "r"((B)[1]))

// ---------------- W prep: g_Wt[l][n][k] = tf32(W[l][k][n]), zero-pad n>=300 ----
__global__ void k_wprep(const float* __restrict__ W) {
    int n = blockIdx.x, l = blockIdx.y, k = threadIdx.x;
    float v = 0.f;
    if (n < EE) v = W[(size_t)l*SS*EE + k*EE + n];
    g_Wt[(l*320 + n)*SS + k] = __uint_as_float(to_tf32(v));
}

// ---------------- embedding gather + masks + fused mean(slot0) ----------------
// warp parity == sel parity; per-warp register column accumulators
__global__ __launch_bounds__(256) void k_gather(const int* __restrict__ seq1,
                                                const int* __restrict__ seq2,
                                                const float* __restrict__ emb) {
    __shared__ float msum[2][EE];
    int b = blockIdx.x;
    int tid = threadIdx.x;
    int warp = tid >> 5, lane = tid & 31;
    for (int i = tid; i < 2*EE; i += 256) ((float*)msum)[i] = 0.f;
    for (int i = tid; i < SS; i += 256) {
        g_v1[b*SS+i] = (seq1[b*SS+i] != 0) ? 1.f : 0.f;
        g_v2[b*SS+i] = (seq2[b*SS+i] != 0) ? 1.f : 0.f;
    }
    __syncthreads();
    int sel = warp & 1;
    float4 acc[3];
#pragma unroll
    for (int jj = 0; jj < 3; jj++) acc[jj] = make_float4(0.f,0.f,0.f,0.f);
    for (int idx = warp; idx < 2*SS; idx += 8) {
        int s = idx >> 1;
        int tok = sel ? seq2[b*SS+s] : seq1[b*SS+s];
        const float4* src = (const float4*)(emb + (long)tok*EE);
        float4* dst = (float4*)((sel ? g_s2 : g_s1) + (b*SS+s)*EE);
#pragma unroll
        for (int jj = 0; jj < 3; jj++) {
            int j = lane + 32*jj;
            if (j < EE/4) {
                float4 v = src[j];
                dst[j] = v;
                acc[jj].x += v.x; acc[jj].y += v.y; acc[jj].z += v.z; acc[jj].w += v.w;
            }
        }
    }
#pragma unroll
    for (int jj = 0; jj < 3; jj++) {
        int j = lane + 32*jj;
        if (j < EE/4) {
            atomicAdd(&msum[sel][4*j+0], acc[jj].x);
            atomicAdd(&msum[sel][4*j+1], acc[jj].y);
            atomicAdd(&msum[sel][4*j+2], acc[jj].z);
            atomicAdd(&msum[sel][4*j+3], acc[jj].w);
        }
    }
    __syncthreads();
    for (int e = tid; e < EE; e += 256) {
        g_x[b*FCIN + e]        = msum[0][e]*(1.f/SS);
        g_x[b*FCIN + 3*EE + e] = msum[1][e]*(1.f/SS);
    }
}

// ---------------- zero mean slots + zero g_w2 (match-split uses atomics) ------
__global__ void k_zx(int l) {
    int i = blockIdx.x*256 + threadIdx.x;
    if (i < BB*SS) g_w2[i] = 0.f;
    if (i >= BB*2*EE) return;
    int b = i / (2*EE);
    int r = i % (2*EE);
    int half = r / EE, e = r % EE;
    int slot = half ? (4+l) : (1+l);
    g_x[b*FCIN + slot*EE + e] = 0.f;
}

// ---------------- match-score, tensor-core tf32, SPLIT grid (B,2) -------------
// CTA h owns X rows [64h, 64h+64) vs all 128 Y rows. Warp tile 32x32.
// mode=0: store A slice    mode=1: w1 direct (own rows), w2 atomicAdd (pre-zeroed)
#define MPAD 36
#define MCH 10      // ceil(300/32)
__global__ __launch_bounds__(256, 2) void k_match(int mode) {
    extern __shared__ float sm[];
    float* Xs = sm;                        // [2][64][36]
    float* Ys = Xs + 2*64*MPAD;            // [2][128][36]
    float* n1s = Ys + 2*SS*MPAD;           // [64]
    float* n2s = n1s + 64;                 // [128]
    float* rowbuf = n2s + SS;              // [4][64]
    float* colbuf = rowbuf + 4*64;         // [2][128]

    int b = blockIdx.x, h = blockIdx.y;
    const float* X = (mode ? g_o1 : g_s1) + b*SS*EE + h*64*EE;
    const float* Y = (mode ? g_o2 : g_s2) + b*SS*EE;
    int tid = threadIdx.x;
    int lane = tid & 31, wid = tid >> 5;
    int g = lane >> 2, tig = lane & 3;
    int wm = wid & 1, wn = wid >> 1;   // wm: 32-row block; wn: 32-col block

    int rX = tid >> 2, qx = tid & 3;   // X loader: row 0..63, 8-col quarter
    int rY = tid >> 1, hy = tid & 1;   // Y loader: row 0..127, 16-col half
    const float* Xr = X + rX*EE + qx*8;
    const float* Yr = Y + rY*EE + hy*16;
    float mvx = g_v1[b*SS + h*64 + rX];
    float mvy = g_v2[b*SS + rY];
    float nx = 0.f, ny = 0.f;
    float4 vx[2], vy[4];

#define FETCH(c) do { \
    int kb = (c)*32; \
    _Pragma("unroll") for (int j = 0; j < 2; j++) { \
        int k = kb + qx*8 + 4*j; \
        vx[j] = (k < EE) ? *(const float4*)(Xr + kb + 4*j) : make_float4(0.f,0.f,0.f,0.f); \
    } \
    _Pragma("unroll") for (int j = 0; j < 4; j++) { \
        int k = kb + hy*16 + 4*j; \
        vy[j] = (k < EE) ? *(const float4*)(Yr + kb + 4*j) : make_float4(0.f,0.f,0.f,0.f); \
    } } while(0)

#define STBUF(buf) do { \
    float* xd = Xs + (buf)*64*MPAD + rX*MPAD + qx*8; \
    float* yd = Ys + (buf)*SS*MPAD + rY*MPAD + hy*16; \
    _Pragma("unroll") for (int j = 0; j < 2; j++) { \
        float x0=vx[j].x*mvx, x1=vx[j].y*mvx, x2=vx[j].z*mvx, x3=vx[j].w*mvx; \
        nx += x0*x0+x1*x1+x2*x2+x3*x3; \
        ((uint32_t*)xd)[4*j+0]=to_tf32(x0); ((uint32_t*)xd)[4*j+1]=to_tf32(x1); \
        ((uint32_t*)xd)[4*j+2]=to_tf32(x2); ((uint32_t*)xd)[4*j+3]=to_tf32(x3); \
    } \
    _Pragma("unroll") for (int j = 0; j < 4; j++) { \
        float y0=vy[j].x*mvy, y1=vy[j].y*mvy, y2=vy[j].z*mvy, y3=vy[j].w*mvy; \
        ny += y0*y0+y1*y1+y2*y2+y3*y3; \
        ((uint32_t*)yd)[4*j+0]=to_tf32(y0); ((uint32_t*)yd)[4*j+1]=to_tf32(y1); \
        ((uint32_t*)yd)[4*j+2]=to_tf32(y2); ((uint32_t*)yd)[4*j+3]=to_tf32(y3); \
    } } while(0)

    float acc[2][4][4];
#pragma unroll
    for (int mt = 0; mt < 2; mt++)
#pragma unroll
        for (int nt = 0; nt < 4; nt++)
#pragma unroll
            for (int q = 0; q < 4; q++) acc[mt][nt][q] = 0.f;

    FETCH(0); STBUF(0);
    __syncthreads();

    for (int c = 0; c < MCH; c++) {
        int cur = c & 1;
        if (c + 1 < MCH) FETCH(c+1);
        const uint32_t* xb = (const uint32_t*)(Xs + cur*64*MPAD);
        const uint32_t* yb = (const uint32_t*)(Ys + cur*SS*MPAD);
#pragma unroll
        for (int ks = 0; ks < 4; ks++) {
            int kk = ks*8;
            uint32_t a[2][4], bf[4][2];
#pragma unroll
            for (int mt = 0; mt < 2; mt++) {
                int row = wm*32 + mt*16 + g;
                a[mt][0] = xb[row*MPAD + kk + tig];
                a[mt][1] = xb[(row+8)*MPAD + kk + tig];
                a[mt][2] = xb[row*MPAD + kk + tig + 4];
                a[mt][3] = xb[(row+8)*MPAD + kk + tig + 4];
            }
#pragma unroll
            for (int nt = 0; nt < 4; nt++) {
                int cr = wn*32 + nt*8 + g;
                bf[nt][0] = yb[cr*MPAD + kk + tig];
                bf[nt][1] = yb[cr*MPAD + kk + tig + 4];
            }
#pragma unroll
            for (int mt = 0; mt < 2; mt++)
#pragma unroll
                for (int nt = 0; nt < 4; nt++)
                    MMA_TF32(acc[mt][nt], a[mt], bf[nt]);
        }
        if (c + 1 < MCH) STBUF(cur ^ 1);
        __syncthreads();
    }

    // norms
    nx += __shfl_xor_sync(0xffffffffu, nx, 1);
    nx += __shfl_xor_sync(0xffffffffu, nx, 2);
    if (qx == 0) n1s[rX] = nx;
    ny += __shfl_xor_sync(0xffffffffu, ny, 1);
    if (hy == 0) n2s[rY] = ny;
    __syncthreads();

    if (mode == 0) {
        float* Ao = g_A + b*SS*SS + h*64*SS;
#pragma unroll
        for (int mt = 0; mt < 2; mt++) {
            int row = wm*32 + mt*16 + g;
            float nr0 = n1s[row], nr1 = n1s[row+8];
#pragma unroll
            for (int nt = 0; nt < 4; nt++) {
                int col = wn*32 + nt*8 + 2*tig;
                float nc0 = n2s[col], nc1 = n2s[col+1];
                float d00 = sqrtf(fmaxf(nr0 + nc0 - 2.f*acc[mt][nt][0], 0.f));
                float d01 = sqrtf(fmaxf(nr0 + nc1 - 2.f*acc[mt][nt][1], 0.f));
                float d10 = sqrtf(fmaxf(nr1 + nc0 - 2.f*acc[mt][nt][2], 0.f));
                float d11 = sqrtf(fmaxf(nr1 + nc1 - 2.f*acc[mt][nt][3], 0.f));
                *(float2*)(Ao + row*SS + col) = make_float2(
                    __uint_as_float(to_tf32(1.f/(1.f+d00))),
                    __uint_as_float(to_tf32(1.f/(1.f+d01))));
                *(float2*)(Ao + (row+8)*SS + col) = make_float2(
                    __uint_as_float(to_tf32(1.f/(1.f+d10))),
                    __uint_as_float(to_tf32(1.f/(1.f+d11))));
            }
        }
    } else {
        float cs0[4], cs1[4];
#pragma unroll
        for (int nt = 0; nt < 4; nt++) { cs0[nt] = 0.f; cs1[nt] = 0.f; }
#pragma unroll
        for (int mt = 0; mt < 2; mt++) {
            int row = wm*32 + mt*16 + g;
            float nr0 = n1s[row], nr1 = n1s[row+8];
            float rlo = 0.f, rhi = 0.f;
#pragma unroll
            for (int nt = 0; nt < 4; nt++) {
                int col = wn*32 + nt*8 + 2*tig;
                float nc0 = n2s[col], nc1 = n2s[col+1];
                float a00 = 1.f/(1.f + sqrtf(fmaxf(nr0 + nc0 - 2.f*acc[mt][nt][0], 0.f)));
                float a01 = 1.f/(1.f + sqrtf(fmaxf(nr0 + nc1 - 2.f*acc[mt][nt][1], 0.f)));
                float a10 = 1.f/(1.f + sqrtf(fmaxf(nr1 + nc0 - 2.f*acc[mt][nt][2], 0.f)));
                float a11 = 1.f/(1.f + sqrtf(fmaxf(nr1 + nc1 - 2.f*acc[mt][nt][3], 0.f)));
                rlo += a00 + a01;
                rhi += a10 + a11;
                cs0[nt] += a00 + a10;
                cs1[nt] += a01 + a11;
            }
            rlo += __shfl_xor_sync(0xffffffffu, rlo, 1);
            rlo += __shfl_xor_sync(0xffffffffu, rlo, 2);
            rhi += __shfl_xor_sync(0xffffffffu, rhi, 1);
            rhi += __shfl_xor_sync(0xffffffffu, rhi, 2);
            if (tig == 0) {
                rowbuf[wn*64 + row]   = rlo;
                rowbuf[wn*64 + row+8] = rhi;
            }
        }
#pragma unroll
        for (int nt = 0; nt < 4; nt++) {
            float c0 = cs0[nt], c1 = cs1[nt];
            c0 += __shfl_xor_sync(0xffffffffu, c0, 4);
            c0 += __shfl_xor_sync(0xffffffffu, c0, 8);
            c0 += __shfl_xor_sync(0xffffffffu, c0, 16);
            c1 += __shfl_xor_sync(0xffffffffu, c1, 4);
            c1 += __shfl_xor_sync(0xffffffffu, c1, 8);
            c1 += __shfl_xor_sync(0xffffffffu, c1, 16);
            if (g == 0) {
                int col = wn*32 + nt*8 + 2*tig;
                colbuf[wm*SS + col]     = c0;
                colbuf[wm*SS + col + 1] = c1;
            }
        }
        __syncthreads();
        if (tid < 64)
            g_w1[b*SS + h*64 + tid] = rowbuf[tid] + rowbuf[64+tid] + rowbuf[128+tid] + rowbuf[192+tid];
        if (tid < SS)
            atomicAdd(&g_w2[b*SS + tid], colbuf[tid] + colbuf[SS+tid]);
    }
#undef FETCH
#undef STBUF
}

// ---------------- f1=A@W, f2=A^T@W, cp.async double-buffered K-chunks ---------
#define APAD 36
#define A2PAD 132
#define FBUF (128*APAD + 32*A2PAD + 64*APAD)   // 11136 words per buffer
__global__ __launch_bounds__(256, 2) void k_fgemm(int layer) {
    extern __shared__ float sm[];
    int b = blockIdx.x;
    int n0 = blockIdx.y * 64;
    const float* Ab = g_A + b*SS*SS;
    const float* Wt = g_Wt + (size_t)layer*320*SS;
    int tid = threadIdx.x;
    int lane = tid & 31, wid = tid >> 5;
    int g = lane >> 2, tig = lane & 3;
    int half = wid >> 2, wm = wid & 3;

#define LOADCH(c, buf) do { \
    float* base_ = sm + (buf)*FBUF; \
    float* A1_ = base_; \
    float* A2_ = base_ + 128*APAD; \
    float* Wb_ = A2_ + 32*A2PAD; \
    int k0_ = (c)*32; \
    _Pragma("unroll") for (int j = 0; j < 4; j++) { \
        int i = tid + 256*j; int r = i >> 3, h = i & 7; \
        cpasync16(A1_ + r*APAD + h*4, Ab + r*SS + k0_ + h*4); \
    } \
    _Pragma("unroll") for (int j = 0; j < 4; j++) { \
        int i = tid + 256*j; int kk = i >> 5, c4 = i & 31; \
        cpasync16(A2_ + kk*A2PAD + c4*4, Ab + (k0_+kk)*SS + c4*4); \
    } \
    _Pragma("unroll") for (int j = 0; j < 2; j++) { \
        int i = tid + 256*j; int n = i >> 3, h = i & 7; \
        cpasync16(Wb_ + n*APAD + h*4, Wt + (n0+n)*SS + k0_ + h*4); \
    } \
    asm volatile("cp.async.commit_group;\n" ::); \
} while (0)

    float acc[2][8][4];
#pragma unroll
    for (int mt = 0; mt < 2; mt++)
#pragma unroll
        for (int nt = 0; nt < 8; nt++)
#pragma unroll
            for (int q = 0; q < 4; q++) acc[mt][nt][q] = 0.f;

    LOADCH(0, 0);
    for (int c = 0; c < 4; c++) {
        if (c < 3) {
            LOADCH(c+1, (c+1)&1);
            asm volatile("cp.async.wait_group 1;\n" ::);
        } else {
            asm volatile("cp.async.wait_group 0;\n" ::);
        }
        __syncthreads();
        const uint32_t* base = (const uint32_t*)(sm + (c&1)*FBUF);
        const uint32_t* A1 = base;
        const uint32_t* A2 = base + 128*APAD;
        const uint32_t* Wb = A2 + 32*A2PAD;
#pragma unroll
        for (int ks = 0; ks < 4; ks++) {
            int kk = ks*8;
            uint32_t a[2][4], bf[8][2];
#pragma unroll
            for (int mt = 0; mt < 2; mt++) {
                int row = wm*32 + mt*16 + g;
                if (half == 0) {
                    a[mt][0] = A1[row*APAD + kk + tig];
                    a[mt][1] = A1[(row+8)*APAD + kk + tig];
                    a[mt][2] = A1[row*APAD + kk + tig + 4];
                    a[mt][3] = A1[(row+8)*APAD + kk + tig + 4];
                } else {
                    a[mt][0] = A2[(kk+tig)*A2PAD + row];
                    a[mt][1] = A2[(kk+tig)*A2PAD + row + 8];
                    a[mt][2] = A2[(kk+tig+4)*A2PAD + row];
                    a[mt][3] = A2[(kk+tig+4)*A2PAD + row + 8];
                }
            }
#pragma unroll
            for (int nt = 0; nt < 8; nt++) {
                int cn = nt*8 + g;
                bf[nt][0] = Wb[cn*APAD + kk + tig];
                bf[nt][1] = Wb[cn*APAD + kk + tig + 4];
            }
#pragma unroll
            for (int mt = 0; mt < 2; mt++)
#pragma unroll
                for (int nt = 0; nt < 8; nt++)
                    MMA_TF32(acc[mt][nt], a[mt], bf[nt]);
        }
        __syncthreads();
    }
#undef LOADCH

    float* out = (half ? g_f2 : g_f1) + b*SS*EE;
#pragma unroll
    for (int mt = 0; mt < 2; mt++) {
        int row = wm*32 + mt*16 + g;
#pragma unroll
        for (int nt = 0; nt < 8; nt++) {
            int col = n0 + nt*8 + 2*tig;
            if (col < EE) {
                *(float2*)(out + row*EE + col)     = make_float2(acc[mt][nt][0], acc[mt][nt][1]);
                *(float2*)(out + (row+8)*EE + col) = make_float2(acc[mt][nt][2], acc[mt][nt][3]);
            }
        }
    }
}

// ---------------- conv 2in->1out 3x3 + tanh + fused mean: column-per-thread ---
__global__ __launch_bounds__(320) void k_conv(const float* __restrict__ cw,
                                              const float* __restrict__ cb,
                                              int layer, int store) {
    extern __shared__ float sm[];
    float* xs = sm;                       // [2][18][302]
    float* w  = xs + 2*(CROWS+2)*(EE+2);  // [18]

    int b = blockIdx.x, ch = blockIdx.y, pair = blockIdx.z;
    int s0 = ch * CROWS;
    const float* X0 = (pair ? g_s2 : g_s1) + b*SS*EE;
    const float* X1 = (pair ? g_f2 : g_f1) + b*SS*EE;
    float* O = (pair ? g_o2 : g_o1) + b*SS*EE;
    int tid = threadIdx.x;
    if (tid < 18) w[tid] = cw[layer*18 + tid];
    if (tid < 2*(CROWS+2)*2) {
        int c = tid / (2*(CROWS+2));
        int rem = tid % (2*(CROWS+2));
        int j = rem >> 1, side = rem & 1;
        xs[(c*(CROWS+2) + j)*(EE+2) + (side ? EE+1 : 0)] = 0.f;
    }
    for (int i = tid; i < 2*(CROWS+2)*(EE/4); i += 320) {
        int c = i / ((CROWS+2)*(EE/4));
        int rem = i % ((CROWS+2)*(EE/4));
        int j = rem / (EE/4), q = rem % (EE/4);
        int srow = s0 + j - 1;
        float4 val = make_float4(0.f,0.f,0.f,0.f);
        if (srow >= 0 && srow < SS)
            val = *(const float4*)((c ? X1 : X0) + srow*EE + q*4);
        float* dptr = &xs[(c*(CROWS+2) + j)*(EE+2) + q*4 + 1];
        dptr[0]=val.x; dptr[1]=val.y; dptr[2]=val.z; dptr[3]=val.w;
    }
    __syncthreads();
    if (tid < EE) {
        int e = tid;
        float bias = cb[layer];
        const float* xs0 = xs;
        const float* xs1 = xs + (CROWS+2)*(EE+2);
        float sv[3][3], fv[3][3];
#pragma unroll
        for (int kh = 0; kh < 2; kh++)
#pragma unroll
            for (int kw = 0; kw < 3; kw++) {
                sv[kh][kw] = xs0[kh*(EE+2) + e + kw];
                fv[kh][kw] = xs1[kh*(EE+2) + e + kw];
            }
        float colsum = 0.f;
#pragma unroll 4
        for (int r = 0; r < CROWS; r++) {
#pragma unroll
            for (int kw = 0; kw < 3; kw++) {
                sv[2][kw] = xs0[(r+2)*(EE+2) + e + kw];
                fv[2][kw] = xs1[(r+2)*(EE+2) + e + kw];
            }
            float acc = bias;
#pragma unroll
            for (int kh = 0; kh < 3; kh++)
#pragma unroll
                for (int kw = 0; kw < 3; kw++)
                    acc += w[kh*3+kw]*sv[kh][kw] + w[9+kh*3+kw]*fv[kh][kw];
            float t = tanh_fast(acc);
            if (store) O[(s0+r)*EE + e] = t;
            colsum += t;
#pragma unroll
            for (int kw = 0; kw < 3; kw++) {
                sv[0][kw] = sv[1][kw]; sv[1][kw] = sv[2][kw];
                fv[0][kw] = fv[1][kw]; fv[1][kw] = fv[2][kw];
            }
        }
        int slot = (pair ? 4 : 1) + layer;
        atomicAdd(&g_x[b*FCIN + slot*EE + e], colsum*(1.f/SS));
    }
}

// ---------------- weighted avg-pool3 + residual update, float4 ----------------
__global__ __launch_bounds__(96) void k_pool() {
    int b = blockIdx.x, ch = blockIdx.y, pair = blockIdx.z;
    int s0 = ch * CROWS;
    const float* O = (pair ? g_o2 : g_o1) + b*SS*EE;
    float* Sx = (pair ? g_s2 : g_s1) + b*SS*EE;
    const float* wv = (pair ? g_w2 : g_w1) + b*SS;
    __shared__ float w[CROWS+2];
    if (threadIdx.x < CROWS+2) {
        int s = s0 + (int)threadIdx.x - 1;
        w[threadIdx.x] = (s >= 0 && s < SS) ? wv[s] : 0.f;
    }
    __syncthreads();
    int t = threadIdx.x;
    if (t >= 75) return;
    int e = t*4;
    float4 a = make_float4(0.f,0.f,0.f,0.f);
    if (s0 > 0) {
        float4 v = *(const float4*)(O + (s0-1)*EE + e);
        a = make_float4(v.x*w[0], v.y*w[0], v.z*w[0], v.w*w[0]);
    }
    float4 v0 = *(const float4*)(O + s0*EE + e);
    float4 bm = make_float4(v0.x*w[1], v0.y*w[1], v0.z*w[1], v0.w*w[1]);
#pragma unroll
    for (int i = 0; i < CROWS; i++) {
        int s = s0 + i;
        float4 cn = make_float4(0.f,0.f,0.f,0.f);
        if (s+1 < SS) {
            float4 v = *(const float4*)(O + (s+1)*EE + e);
            float ww = w[i+2];
            cn = make_float4(v.x*ww, v.y*ww, v.z*ww, v.w*ww);
        }
        float4 sx = *(float4*)(Sx + s*EE + e);
        sx.x += (a.x + bm.x + cn.x) * (1.f/3.f);
        sx.y += (a.y + bm.y + cn.y) * (1.f/3.f);
        sx.z += (a.z + bm.z + cn.z) * (1.f/3.f);
        sx.w += (a.w + bm.w + cn.w) * (1.f/3.f);
        *(float4*)(Sx + s*EE + e) = sx;
        a = bm; bm = cn;
    }
}

// ---------------- fc1 GEMM: [512,1800] @ [1800,300]^T -> g_h ----------------
__global__ __launch_bounds__(256) void k_fc1(const float* __restrict__ fw) {
    int m0 = blockIdx.x * 64, n0 = blockIdx.y * 64;
    __shared__ float Xs[8][68];
    __shared__ float Ws2[8][68];
    int tid = threadIdx.x, ty = tid >> 4, tx = tid & 15;
    float acc[4][4];
#pragma unroll
    for (int u = 0; u < 4; u++)
#pragma unroll
        for (int v = 0; v < 4; v++) acc[u][v] = 0.f;

    for (int k0 = 0; k0 < FCIN; k0 += 8) {
        __syncthreads();
#pragma unroll 2
        for (int i = tid; i < 512; i += 256) {
            int r = i >> 3, kk = i & 7;
            Xs[kk][r] = g_x[(m0 + r)*FCIN + k0 + kk];
            int n = n0 + r;
            Ws2[kk][r] = (n < HH) ? fw[n*FCIN + k0 + kk] : 0.f;
        }
        __syncthreads();
#pragma unroll
        for (int kk = 0; kk < 8; kk++) {
            float4 xa = *(const float4*)&Xs[kk][ty*4];
            float4 wb = *(const float4*)&Ws2[kk][tx*4];
            float xv[4] = {xa.x, xa.y, xa.z, xa.w};
            float wvv[4] = {wb.x, wb.y, wb.z, wb.w};
#pragma unroll
            for (int u = 0; u < 4; u++)
#pragma unroll
                for (int v = 0; v < 4; v++) acc[u][v] += xv[u]*wvv[v];
        }
    }
#pragma unroll
    for (int u = 0; u < 4; u++) {
        int m = m0 + ty*4 + u;
#pragma unroll
        for (int v = 0; v < 4; v++) {
            int n = n0 + tx*4 + v;
            if (n < HH) g_h[m*HH + n] = acc[u][v];
        }
    }
}

// ---------------- LN + relu + fc2 + softmax ----------------
__device__ __forceinline__ float block_reduce512(float v, float* red) {
    int tid = threadIdx.x;
    red[tid] = v;
    __syncthreads();
    for (int off = 256; off > 0; off >>= 1) {
        if (tid < off) red[tid] += red[tid + off];
        __syncthreads();
    }
    float r = red[0];
    __syncthreads();
    return r;
}

__global__ __launch_bounds__(512) void k_head(const float* __restrict__ fc1b,
                                              const float* __restrict__ lng,
                                              const float* __restrict__ lnb,
                                              const float* __restrict__ fc2w,
                                              const float* __restrict__ fc2b,
                                              float* __restrict__ out) {
    int b = blockIdx.x, tid = threadIdx.x;
    __shared__ float red[512];
    bool act = tid < HH;
    float h = act ? (g_h[b*HH + tid] + fc1b[tid]) : 0.f;
    float mu = block_reduce512(h, red) * (1.f/HH);
    float d = act ? (h - mu) : 0.f;
    float var = block_reduce512(d*d, red) * (1.f/HH);
    float hn = 0.f;
    if (act) {
        hn = d * rsqrtf(var + 1e-5f) * lng[tid] + lnb[tid];
        hn = fmaxf(hn, 0.f);
    }
    float o0 = block_reduce512(act ? hn*fc2w[tid]      : 0.f, red);
    float o1 = block_reduce512(act ? hn*fc2w[HH + tid] : 0.f, red);
    if (tid == 0) {
        o0 += fc2b[0];
        o1 += fc2b[1];
        out[b*2 + 0] = o0;
        out[b*2 + 1] = o1;
        float m = fmaxf(o0, o1);
        float e0 = expf(o0 - m), e1 = expf(o1 - m);
        float inv = 1.f/(e0 + e1);
        out[BB*2 + b*2 + 0] = e0*inv;
        out[BB*2 + b*2 + 1] = e1*inv;
    }
}

// ---------------- launch ----------------
extern "C" void kernel_launch(void* const* d_in, const int* in_sizes, int n_in,
                              void* d_out, int out_size) {
    (void)in_sizes; (void)n_in; (void)out_size;
    const int*   seq1 = (const int*)d_in[0];
    const int*   seq2 = (const int*)d_in[1];
    const float* emb  = (const float*)d_in[2];
    const float* W    = (const float*)d_in[3];
    const float* cw   = (const float*)d_in[4];
    const float* cb   = (const float*)d_in[5];
    const float* fc1w = (const float*)d_in[6];
    const float* fc1b = (const float*)d_in[7];
    const float* lng  = (const float*)d_in[8];
    const float* lnb  = (const float*)d_in[9];
    const float* fc2w = (const float*)d_in[10];
    const float* fc2b = (const float*)d_in[11];
    float* out = (float*)d_out;

    const int SM_MATCH = (2*64*MPAD + 2*SS*MPAD + 64 + SS + 4*64 + 2*SS) * 4;  // ~58.1KB
    const int SM_FGEMM = 2*FBUF*4;                                              // ~89.1KB
    const int SM_CONV  = (2*(CROWS+2)*(EE+2) + 18) * 4;                         // ~43.6KB

    cudaFuncSetAttribute(k_match, cudaFuncAttributeMaxDynamicSharedMemorySize, SM_MATCH);
    cudaFuncSetAttribute(k_fgemm, cudaFuncAttributeMaxDynamicSharedMemorySize, SM_FGEMM);
    cudaFuncSetAttribute(k_conv,  cudaFuncAttributeMaxDynamicSharedMemorySize, SM_CONV);

    k_wprep<<<dim3(320, LL), 128>>>(W);
    k_gather<<<BB, 256>>>(seq1, seq2, emb);
    for (int l = 0; l < LL; l++) {
        int last = (l == LL-1);
        k_match<<<dim3(BB, 2), 256, SM_MATCH>>>(0);
        k_zx<<<(BB*2*EE + 255)/256, 256>>>(l);
        k_fgemm<<<dim3(BB, 5), 256, SM_FGEMM>>>(l);
        k_conv<<<dim3(BB, 8, 2), 320, SM_CONV>>>(cw, cb, l, last ? 0 : 1);
        if (!last) {
            k_match<<<dim3(BB, 2), 256, SM_MATCH>>>(1);
            k_pool<<<dim3(BB, 8, 2), 96>>>();
        }
    }
    k_fc1<<<dim3(8, 5), 256>>>(fc1w);
    k_head<<<BB, 512>>>(fc1b, lng, lnb, fc2w, fc2b, out);
}

// round 12
// speedup vs baseline: 1.4766x; 1.0028x over previous
#include <cuda_runtime.h>
#include <cuda_fp16.h>
#include <math.h>
#include <stdint.h>

#define BB 512
#define SS 128
#define EE 300
#define LL 2
#define HH 300
#define FCIN 1800   // E*(1+L)*2
#define CROWS 16

// ---------------- device scratch (no allocation allowed) ----------------
__device__ float g_s1[BB*SS*EE];
__device__ float g_s2[BB*SS*EE];
__device__ float g_f1[BB*SS*EE];
__device__ float g_f2[BB*SS*EE];
__device__ float g_o1[BB*SS*EE];
__device__ float g_o2[BB*SS*EE];
__device__ float g_A [BB*SS*SS];
__device__ float g_Wt[LL*320*SS];   // pre-transposed, tf32-rounded W: [l][n][k]
__device__ float g_w1[BB*SS];
__device__ float g_w2[BB*SS];
__device__ float g_v1[BB*SS];
__device__ float g_v2[BB*SS];
__device__ float g_x [BB*FCIN];
__device__ float g_h [BB*HH];

__device__ __forceinline__ float tanh_fast(float x) {
    float r; asm("tanh.approx.f32 %0, %1;" : "=f"(r) : "f"(x)); return r;
}
__device__ __forceinline__ uint32_t to_tf32(float x) {
    uint32_t r; asm("cvt.rna.tf32.f32 %0, %1;" : "=r"(r) : "f"(x)); return r;
}
__device__ __forceinline__ uint32_t pack_h2(float a, float b) {
    __half2 h = __floats2half2_rn(a, b);
    return *(uint32_t*)&h;
}
__device__ __forceinline__ void cpasync16(void* dst, const void* src) {
    uint32_t d = (uint32_t)__cvta_generic_to_shared(dst);
    asm volatile("cp.async.ca.shared.global [%0], [%1], 16;\n" :: "r"(d), "l"(src));
}
#define MMA_TF32(C, A, B) \
    asm volatile("mma.sync.aligned.m16n8k8.row.col.f32.tf32.tf32.f32 " \
        "{%0,%1,%2,%3}, {%4,%5,%6,%7}, {%8,%9}, {%0,%1,%2,%3};" \
        : "+f"((C)[0]), "+f"((C)[1]), "+f"((C)[2]), "+f"((C)[3]) \
        : "r"((A)[0]), "r"((A)[1]), "r"((A)[2]), "r"((A)[3]), \
          "r"((B)[0]), "r"((B)[1]))
#define MMA_F16(C, A, B) \
    asm volatile("mma.sync.aligned.m16n8k16.row.col.f32.f16.f16.f32 " \
        "{%0,%1,%2,%3}, {%4,%5,%6,%7}, {%8,%9}, {%0,%1,%2,%3};" \
        : "+f"((C)[0]), "+f"((C)[1]), "+f"((C)[2]), "+f"((C)[3]) \
        : "r"((A)[0]), "r"((A)[1]), "r"((A)[2]), "r"((A)[3]), \
          "r"((B)[0]), "r"((B)[1]))

// ---------------- W prep: g_Wt[l][n][k] = tf32(W[l][k][n]), zero-pad n>=300 ----
__global__ void k_wprep(const float* __restrict__ W) {
    int n = blockIdx.x, l = blockIdx.y, k = threadIdx.x;
    float v = 0.f;
    if (n < EE) v = W[(size_t)l*SS*EE + k*EE + n];
    g_Wt[(l*320 + n)*SS + k] = __uint_as_float(to_tf32(v));
}

// ---------------- embedding gather + masks + fused mean(slot0) ----------------
__global__ __launch_bounds__(256) void k_gather(const int* __restrict__ seq1,
                                                const int* __restrict__ seq2,
                                                const float* __restrict__ emb) {
    __shared__ float msum[2][EE];
    int b = blockIdx.x;
    int tid = threadIdx.x;
    int warp = tid >> 5, lane = tid & 31;
    for (int i = tid; i < 2*EE; i += 256) ((float*)msum)[i] = 0.f;
    for (int i = tid; i < SS; i += 256) {
        g_v1[b*SS+i] = (seq1[b*SS+i] != 0) ? 1.f : 0.f;
        g_v2[b*SS+i] = (seq2[b*SS+i] != 0) ? 1.f : 0.f;
    }
    __syncthreads();
    int sel = warp & 1;
    float4 acc[3];
#pragma unroll
    for (int jj = 0; jj < 3; jj++) acc[jj] = make_float4(0.f,0.f,0.f,0.f);
    for (int idx = warp; idx < 2*SS; idx += 8) {
        int s = idx >> 1;
        int tok = sel ? seq2[b*SS+s] : seq1[b*SS+s];
        const float4* src = (const float4*)(emb + (long)tok*EE);
        float4* dst = (float4*)((sel ? g_s2 : g_s1) + (b*SS+s)*EE);
#pragma unroll
        for (int jj = 0; jj < 3; jj++) {
            int j = lane + 32*jj;
            if (j < EE/4) {
                float4 v = src[j];
                dst[j] = v;
                acc[jj].x += v.x; acc[jj].y += v.y; acc[jj].z += v.z; acc[jj].w += v.w;
            }
        }
    }
#pragma unroll
    for (int jj = 0; jj < 3; jj++) {
        int j = lane + 32*jj;
        if (j < EE/4) {
            atomicAdd(&msum[sel][4*j+0], acc[jj].x);
            atomicAdd(&msum[sel][4*j+1], acc[jj].y);
            atomicAdd(&msum[sel][4*j+2], acc[jj].z);
            atomicAdd(&msum[sel][4*j+3], acc[jj].w);
        }
    }
    __syncthreads();
    for (int e = tid; e < EE; e += 256) {
        g_x[b*FCIN + e]        = msum[0][e]*(1.f/SS);
        g_x[b*FCIN + 3*EE + e] = msum[1][e]*(1.f/SS);
    }
}

// ---------------- match-score, fp16 tensor cores, SPLIT grid (B,2) ------------
// CTA h owns X rows [64h, 64h+64) vs all 128 Y rows. Warp tile 32x32.
// mode=0: store A slice (tf32-rounded) + zero g_w2/g_x slots for layer
// mode=1: w1 direct (own rows), w2 atomicAdd (pre-zeroed by mode 0)
#define MPAD 20     // half2 words per 32-k chunk (16) + pad 4
#define MCH 10      // ceil(300/32)
__global__ __launch_bounds__(256, 2) void k_match(int mode, int layer) {
    extern __shared__ float sm[];
    uint32_t* Xs = (uint32_t*)sm;           // [2][64][20] half2 words
    uint32_t* Ys = Xs + 2*64*MPAD;          // [2][128][20]
    float* n1s = (float*)(Ys + 2*SS*MPAD);  // [64]
    float* n2s = n1s + 64;                  // [128]
    float* rowbuf = n2s + SS;               // [4][64]
    float* colbuf = rowbuf + 4*64;          // [2][128]

    int b = blockIdx.x, h = blockIdx.y;
    const float* X = (mode ? g_o1 : g_s1) + b*SS*EE + h*64*EE;
    const float* Y = (mode ? g_o2 : g_s2) + b*SS*EE;
    int tid = threadIdx.x;
    int lane = tid & 31, wid = tid >> 5;
    int g = lane >> 2, tig = lane & 3;
    int wm = wid & 1, wn = wid >> 1;   // wm: 32-row block; wn: 32-col block (0..3)

    int rX = tid >> 2, qx = tid & 3;   // X loader: row 0..63, 8-col quarter
    int rY = tid >> 1, hy = tid & 1;   // Y loader: row 0..127, 16-col half
    const float* Xr = X + rX*EE + qx*8;
    const float* Yr = Y + rY*EE + hy*16;
    float mvx = g_v1[b*SS + h*64 + rX];
    float mvy = g_v2[b*SS + rY];
    float nx = 0.f, ny = 0.f;
    float4 vx[2], vy[4];

#define FETCH(c) do { \
    int kb = (c)*32; \
    _Pragma("unroll") for (int j = 0; j < 2; j++) { \
        int k = kb + qx*8 + 4*j; \
        vx[j] = (k < EE) ? *(const float4*)(Xr + kb + 4*j) : make_float4(0.f,0.f,0.f,0.f); \
    } \
    _Pragma("unroll") for (int j = 0; j < 4; j++) { \
        int k = kb + hy*16 + 4*j; \
        vy[j] = (k < EE) ? *(const float4*)(Yr + kb + 4*j) : make_float4(0.f,0.f,0.f,0.f); \
    } } while(0)

#define STBUF(buf) do { \
    uint32_t* xd = Xs + (buf)*64*MPAD + rX*MPAD + qx*4; \
    uint32_t* yd = Ys + (buf)*SS*MPAD + rY*MPAD + hy*8; \
    _Pragma("unroll") for (int j = 0; j < 2; j++) { \
        float x0=vx[j].x*mvx, x1=vx[j].y*mvx, x2=vx[j].z*mvx, x3=vx[j].w*mvx; \
        nx += x0*x0+x1*x1+x2*x2+x3*x3; \
        xd[2*j+0] = pack_h2(x0, x1); \
        xd[2*j+1] = pack_h2(x2, x3); \
    } \
    _Pragma("unroll") for (int j = 0; j < 4; j++) { \
        float y0=vy[j].x*mvy, y1=vy[j].y*mvy, y2=vy[j].z*mvy, y3=vy[j].w*mvy; \
        ny += y0*y0+y1*y1+y2*y2+y3*y3; \
        yd[2*j+0] = pack_h2(y0, y1); \
        yd[2*j+1] = pack_h2(y2, y3); \
    } } while(0)

    float acc[2][4][4];
#pragma unroll
    for (int mt = 0; mt < 2; mt++)
#pragma unroll
        for (int nt = 0; nt < 4; nt++)
#pragma unroll
            for (int q = 0; q < 4; q++) acc[mt][nt][q] = 0.f;

    FETCH(0); STBUF(0);
    __syncthreads();

    for (int c = 0; c < MCH; c++) {
        int cur = c & 1;
        if (c + 1 < MCH) FETCH(c+1);
        const uint32_t* xb = Xs + cur*64*MPAD;
        const uint32_t* yb = Ys + cur*SS*MPAD;
#pragma unroll
        for (int ks = 0; ks < 2; ks++) {
            int ws = ks*8;   // word base within the 16-word chunk
            uint32_t a[2][4], bf[4][2];
#pragma unroll
            for (int mt = 0; mt < 2; mt++) {
                int row = wm*32 + mt*16 + g;
                a[mt][0] = xb[row*MPAD + ws + tig];
                a[mt][1] = xb[(row+8)*MPAD + ws + tig];
                a[mt][2] = xb[row*MPAD + ws + tig + 4];
                a[mt][3] = xb[(row+8)*MPAD + ws + tig + 4];
            }
#pragma unroll
            for (int nt = 0; nt < 4; nt++) {
                int cr = wn*32 + nt*8 + g;
                bf[nt][0] = yb[cr*MPAD + ws + tig];
                bf[nt][1] = yb[cr*MPAD + ws + tig + 4];
            }
#pragma unroll
            for (int mt = 0; mt < 2; mt++)
#pragma unroll
                for (int nt = 0; nt < 4; nt++)
                    MMA_F16(acc[mt][nt], a[mt], bf[nt]);
        }
        if (c + 1 < MCH) STBUF(cur ^ 1);
        __syncthreads();
    }

    // norms (from unrounded fp32 values)
    nx += __shfl_xor_sync(0xffffffffu, nx, 1);
    nx += __shfl_xor_sync(0xffffffffu, nx, 2);
    if (qx == 0) n1s[rX] = nx;
    ny += __shfl_xor_sync(0xffffffffu, ny, 1);
    if (hy == 0) n2s[rY] = ny;
    __syncthreads();

    if (mode == 0) {
        float* Ao = g_A + b*SS*SS + h*64*SS;
#pragma unroll
        for (int mt = 0; mt < 2; mt++) {
            int row = wm*32 + mt*16 + g;
            float nr0 = n1s[row], nr1 = n1s[row+8];
#pragma unroll
            for (int nt = 0; nt < 4; nt++) {
                int col = wn*32 + nt*8 + 2*tig;
                float nc0 = n2s[col], nc1 = n2s[col+1];
                float d00 = sqrtf(fmaxf(nr0 + nc0 - 2.f*acc[mt][nt][0], 0.f));
                float d01 = sqrtf(fmaxf(nr0 + nc1 - 2.f*acc[mt][nt][1], 0.f));
                float d10 = sqrtf(fmaxf(nr1 + nc0 - 2.f*acc[mt][nt][2], 0.f));
                float d11 = sqrtf(fmaxf(nr1 + nc1 - 2.f*acc[mt][nt][3], 0.f));
                *(float2*)(Ao + row*SS + col) = make_float2(
                    __uint_as_float(to_tf32(1.f/(1.f+d00))),
                    __uint_as_float(to_tf32(1.f/(1.f+d01))));
                *(float2*)(Ao + (row+8)*SS + col) = make_float2(
                    __uint_as_float(to_tf32(1.f/(1.f+d10))),
                    __uint_as_float(to_tf32(1.f/(1.f+d11))));
            }
        }
        // fused zeroing (replaces k_zx): g_w2 (h==0) + g_x mean slot for this pair
        if (h == 0 && tid < SS) g_w2[b*SS + tid] = 0.f;
        int slot = (h ? 4 : 1) + layer;
        for (int e = tid; e < EE; e += 256) g_x[b*FCIN + slot*EE + e] = 0.f;
    } else {
        float cs0[4], cs1[4];
#pragma unroll
        for (int nt = 0; nt < 4; nt++) { cs0[nt] = 0.f; cs1[nt] = 0.f; }
#pragma unroll
        for (int mt = 0; mt < 2; mt++) {
            int row = wm*32 + mt*16 + g;
            float nr0 = n1s[row], nr1 = n1s[row+8];
            float rlo = 0.f, rhi = 0.f;
#pragma unroll
            for (int nt = 0; nt < 4; nt++) {
                int col = wn*32 + nt*8 + 2*tig;
                float nc0 = n2s[col], nc1 = n2s[col+1];
                float a00 = 1.f/(1.f + sqrtf(fmaxf(nr0 + nc0 - 2.f*acc[mt][nt][0], 0.f)));
                float a01 = 1.f/(1.f + sqrtf(fmaxf(nr0 + nc1 - 2.f*acc[mt][nt][1], 0.f)));
                float a10 = 1.f/(1.f + sqrtf(fmaxf(nr1 + nc0 - 2.f*acc[mt][nt][2], 0.f)));
                float a11 = 1.f/(1.f + sqrtf(fmaxf(nr1 + nc1 - 2.f*acc[mt][nt][3], 0.f)));
                rlo += a00 + a01;
                rhi += a10 + a11;
                cs0[nt] += a00 + a10;
                cs1[nt] += a01 + a11;
            }
            rlo += __shfl_xor_sync(0xffffffffu, rlo, 1);
            rlo += __shfl_xor_sync(0xffffffffu, rlo, 2);
            rhi += __shfl_xor_sync(0xffffffffu, rhi, 1);
            rhi += __shfl_xor_sync(0xffffffffu, rhi, 2);
            if (tig == 0) {
                rowbuf[wn*64 + row]   = rlo;
                rowbuf[wn*64 + row+8] = rhi;
            }
        }
#pragma unroll
        for (int nt = 0; nt < 4; nt++) {
            float c0 = cs0[nt], c1 = cs1[nt];
            c0 += __shfl_xor_sync(0xffffffffu, c0, 4);
            c0 += __shfl_xor_sync(0xffffffffu, c0, 8);
            c0 += __shfl_xor_sync(0xffffffffu, c0, 16);
            c1 += __shfl_xor_sync(0xffffffffu, c1, 4);
            c1 += __shfl_xor_sync(0xffffffffu, c1, 8);
            c1 += __shfl_xor_sync(0xffffffffu, c1, 16);
            if (g == 0) {
                int col = wn*32 + nt*8 + 2*tig;
                colbuf[wm*SS + col]     = c0;
                colbuf[wm*SS + col + 1] = c1;
            }
        }
        __syncthreads();
        if (tid < 64)
            g_w1[b*SS + h*64 + tid] = rowbuf[tid] + rowbuf[64+tid] + rowbuf[128+tid] + rowbuf[192+tid];
        if (tid < SS)
            atomicAdd(&g_w2[b*SS + tid], colbuf[tid] + colbuf[SS+tid]);
    }
#undef FETCH
#undef STBUF
}

// ---------------- f1=A@W, f2=A^T@W, cp.async double-buffered K-chunks ---------
#define APAD 36
#define A2PAD 132
#define FBUF (128*APAD + 32*A2PAD + 64*APAD)   // 11136 words per buffer
__global__ __launch_bounds__(256, 2) void k_fgemm(int layer) {
    extern __shared__ float sm[];
    int b = blockIdx.x;
    int n0 = blockIdx.y * 64;
    const float* Ab = g_A + b*SS*SS;
    const float* Wt = g_Wt + (size_t)layer*320*SS;
    int tid = threadIdx.x;
    int lane = tid & 31, wid = tid >> 5;
    int g = lane >> 2, tig = lane & 3;
    int half = wid >> 2, wm = wid & 3;

#define LOADCH(c, buf) do { \
    float* base_ = sm + (buf)*FBUF; \
    float* A1_ = base_; \
    float* A2_ = base_ + 128*APAD; \
    float* Wb_ = A2_ + 32*A2PAD; \
    int k0_ = (c)*32; \
    _Pragma("unroll") for (int j = 0; j < 4; j++) { \
        int i = tid + 256*j; int r = i >> 3, hh = i & 7; \
        cpasync16(A1_ + r*APAD + hh*4, Ab + r*SS + k0_ + hh*4); \
    } \
    _Pragma("unroll") for (int j = 0; j < 4; j++) { \
        int i = tid + 256*j; int kk = i >> 5, c4 = i & 31; \
        cpasync16(A2_ + kk*A2PAD + c4*4, Ab + (k0_+kk)*SS + c4*4); \
    } \
    _Pragma("unroll") for (int j = 0; j < 2; j++) { \
        int i = tid + 256*j; int n = i >> 3, hh = i & 7; \
        cpasync16(Wb_ + n*APAD + hh*4, Wt + (n0+n)*SS + k0_ + hh*4); \
    } \
    asm volatile("cp.async.commit_group;\n" ::); \
} while (0)

    float acc[2][8][4];
#pragma unroll
    for (int mt = 0; mt < 2; mt++)
#pragma unroll
        for (int nt = 0; nt < 8; nt++)
#pragma unroll
            for (int q = 0; q < 4; q++) acc[mt][nt][q] = 0.f;

    LOADCH(0, 0);
    for (int c = 0; c < 4; c++) {
        if (c < 3) {
            LOADCH(c+1, (c+1)&1);
            asm volatile("cp.async.wait_group 1;\n" ::);
        } else {
            asm volatile("cp.async.wait_group 0;\n" ::);
        }
        __syncthreads();
        const uint32_t* base = (const uint32_t*)(sm + (c&1)*FBUF);
        const uint32_t* A1 = base;
        const uint32_t* A2 = base + 128*APAD;
        const uint32_t* Wb = A2 + 32*A2PAD;
#pragma unroll
        for (int ks = 0; ks < 4; ks++) {
            int kk = ks*8;
            uint32_t a[2][4], bf[8][2];
#pragma unroll
            for (int mt = 0; mt < 2; mt++) {
                int row = wm*32 + mt*16 + g;
                if (half == 0) {
                    a[mt][0] = A1[row*APAD + kk + tig];
                    a[mt][1] = A1[(row+8)*APAD + kk + tig];
                    a[mt][2] = A1[row*APAD + kk + tig + 4];
                    a[mt][3] = A1[(row+8)*APAD + kk + tig + 4];
                } else {
                    a[mt][0] = A2[(kk+tig)*A2PAD + row];
                    a[mt][1] = A2[(kk+tig)*A2PAD + row + 8];
                    a[mt][2] = A2[(kk+tig+4)*A2PAD + row];
                    a[mt][3] = A2[(kk+tig+4)*A2PAD + row + 8];
                }
            }
#pragma unroll
            for (int nt = 0; nt < 8; nt++) {
                int cn = nt*8 + g;
                bf[nt][0] = Wb[cn*APAD + kk + tig];
                bf[nt][1] = Wb[cn*APAD + kk + tig + 4];
            }
#pragma unroll
            for (int mt = 0; mt < 2; mt++)
#pragma unroll
                for (int nt = 0; nt < 8; nt++)
                    MMA_TF32(acc[mt][nt], a[mt], bf[nt]);
        }
        __syncthreads();
    }
#undef LOADCH

    float* out = (half ? g_f2 : g_f1) + b*SS*EE;
#pragma unroll
    for (int mt = 0; mt < 2; mt++) {
        int row = wm*32 + mt*16 + g;
#pragma unroll
        for (int nt = 0; nt < 8; nt++) {
            int col = n0 + nt*8 + 2*tig;
            if (col < EE) {
                *(float2*)(out + row*EE + col)     = make_float2(acc[mt][nt][0], acc[mt][nt][1]);
                *(float2*)(out + (row+8)*EE + col) = make_float2(acc[mt][nt][2], acc[mt][nt][3]);
            }
        }
    }
}

// ---------------- conv 2in->1out 3x3 + tanh + fused mean: column-per-thread ---
__global__ __launch_bounds__(320) void k_conv(const float* __restrict__ cw,
                                              const float* __restrict__ cb,
                                              int layer, int store) {
    extern __shared__ float sm[];
    float* xs = sm;                       // [2][18][302]
    float* w  = xs + 2*(CROWS+2)*(EE+2);  // [18]

    int b = blockIdx.x, ch = blockIdx.y, pair = blockIdx.z;
    int s0 = ch * CROWS;
    const float* X0 = (pair ? g_s2 : g_s1) + b*SS*EE;
    const float* X1 = (pair ? g_f2 : g_f1) + b*SS*EE;
    float* O = (pair ? g_o2 : g_o1) + b*SS*EE;
    int tid = threadIdx.x;
    if (tid < 18) w[tid] = cw[layer*18 + tid];
    if (tid < 2*(CROWS+2)*2) {
        int c = tid / (2*(CROWS+2));
        int rem = tid % (2*(CROWS+2));
        int j = rem >> 1, side = rem & 1;
        xs[(c*(CROWS+2) + j)*(EE+2) + (side ? EE+1 : 0)] = 0.f;
    }
    for (int i = tid; i < 2*(CROWS+2)*(EE/4); i += 320) {
        int c = i / ((CROWS+2)*(EE/4));
        int rem = i % ((CROWS+2)*(EE/4));
        int j = rem / (EE/4), q = rem % (EE/4);
        int srow = s0 + j - 1;
        float4 val = make_float4(0.f,0.f,0.f,0.f);
        if (srow >= 0 && srow < SS)
            val = *(const float4*)((c ? X1 : X0) + srow*EE + q*4);
        float* dptr = &xs[(c*(CROWS+2) + j)*(EE+2) + q*4 + 1];
        dptr[0]=val.x; dptr[1]=val.y; dptr[2]=val.z; dptr[3]=val.w;
    }
    __syncthreads();
    if (tid < EE) {
        int e = tid;
        float bias = cb[layer];
        const float* xs0 = xs;
        const float* xs1 = xs + (CROWS+2)*(EE+2);
        float sv[3][3], fv[3][3];
#pragma unroll
        for (int kh = 0; kh < 2; kh++)
#pragma unroll
            for (int kw = 0; kw < 3; kw++) {
                sv[kh][kw] = xs0[kh*(EE+2) + e + kw];
                fv[kh][kw] = xs1[kh*(EE+2) + e + kw];
            }
        float colsum = 0.f;
#pragma unroll 4
        for (int r = 0; r < CROWS; r++) {
#pragma unroll
            for (int kw = 0; kw < 3; kw++) {
                sv[2][kw] = xs0[(r+2)*(EE+2) + e + kw];
                fv[2][kw] = xs1[(r+2)*(EE+2) + e + kw];
            }
            float acc = bias;
#pragma unroll
            for (int kh = 0; kh < 3; kh++)
#pragma unroll
                for (int kw = 0; kw < 3; kw++)
                    acc += w[kh*3+kw]*sv[kh][kw] + w[9+kh*3+kw]*fv[kh][kw];
            float t = tanh_fast(acc);
            if (store) O[(s0+r)*EE + e] = t;
            colsum += t;
#pragma unroll
            for (int kw = 0; kw < 3; kw++) {
                sv[0][kw] = sv[1][kw]; sv[1][kw] = sv[2][kw];
                fv[0][kw] = fv[1][kw]; fv[1][kw] = fv[2][kw];
            }
        }
        int slot = (pair ? 4 : 1) + layer;
        atomicAdd(&g_x[b*FCIN + slot*EE + e], colsum*(1.f/SS));
    }
}

// ---------------- weighted avg-pool3 + residual update, float4 ----------------
__global__ __launch_bounds__(96) void k_pool() {
    int b = blockIdx.x, ch = blockIdx.y, pair = blockIdx.z;
    int s0 = ch * CROWS;
    const float* O = (pair ? g_o2 : g_o1) + b*SS*EE;
    float* Sx = (pair ? g_s2 : g_s1) + b*SS*EE;
    const float* wv = (pair ? g_w2 : g_w1) + b*SS;
    __shared__ float w[CROWS+2];
    if (threadIdx.x < CROWS+2) {
        int s = s0 + (int)threadIdx.x - 1;
        w[threadIdx.x] = (s >= 0 && s < SS) ? wv[s] : 0.f;
    }
    __syncthreads();
    int t = threadIdx.x;
    if (t >= 75) return;
    int e = t*4;
    float4 a = make_float4(0.f,0.f,0.f,0.f);
    if (s0 > 0) {
        float4 v = *(const float4*)(O + (s0-1)*EE + e);
        a = make_float4(v.x*w[0], v.y*w[0], v.z*w[0], v.w*w[0]);
    }
    float4 v0 = *(const float4*)(O + s0*EE + e);
    float4 bm = make_float4(v0.x*w[1], v0.y*w[1], v0.z*w[1], v0.w*w[1]);
#pragma unroll
    for (int i = 0; i < CROWS; i++) {
        int s = s0 + i;
        float4 cn = make_float4(0.f,0.f,0.f,0.f);
        if (s+1 < SS) {
            float4 v = *(const float4*)(O + (s+1)*EE + e);
            float ww = w[i+2];
            cn = make_float4(v.x*ww, v.y*ww, v.z*ww, v.w*ww);
        }
        float4 sx = *(float4*)(Sx + s*EE + e);
        sx.x += (a.x + bm.x + cn.x) * (1.f/3.f);
        sx.y += (a.y + bm.y + cn.y) * (1.f/3.f);
        sx.z += (a.z + bm.z + cn.z) * (1.f/3.f);
        sx.w += (a.w + bm.w + cn.w) * (1.f/3.f);
        *(float4*)(Sx + s*EE + e) = sx;
        a = bm; bm = cn;
    }
}

// ---------------- fc1 GEMM: [512,1800] @ [1800,300]^T -> g_h ----------------
__global__ __launch_bounds__(256) void k_fc1(const float* __restrict__ fw) {
    int m0 = blockIdx.x * 64, n0 = blockIdx.y * 64;
    __shared__ float Xs[8][68];
    __shared__ float Ws2[8][68];
    int tid = threadIdx.x, ty = tid >> 4, tx = tid & 15;
    float acc[4][4];
#pragma unroll
    for (int u = 0; u < 4; u++)
#pragma unroll
        for (int v = 0; v < 4; v++) acc[u][v] = 0.f;

    for (int k0 = 0; k0 < FCIN; k0 += 8) {
        __syncthreads();
#pragma unroll 2
        for (int i = tid; i < 512; i += 256) {
            int r = i >> 3, kk = i & 7;
            Xs[kk][r] = g_x[(m0 + r)*FCIN + k0 + kk];
            int n = n0 + r;
            Ws2[kk][r] = (n < HH) ? fw[n*FCIN + k0 + kk] : 0.f;
        }
        __syncthreads();
#pragma unroll
        for (int kk = 0; kk < 8; kk++) {
            float4 xa = *(const float4*)&Xs[kk][ty*4];
            float4 wb = *(const float4*)&Ws2[kk][tx*4];
            float xv[4] = {xa.x, xa.y, xa.z, xa.w};
            float wvv[4] = {wb.x, wb.y, wb.z, wb.w};
#pragma unroll
            for (int u = 0; u < 4; u++)
#pragma unroll
                for (int v = 0; v < 4; v++) acc[u][v] += xv[u]*wvv[v];
        }
    }
#pragma unroll
    for (int u = 0; u < 4; u++) {
        int m = m0 + ty*4 + u;
#pragma unroll
        for (int v = 0; v < 4; v++) {
            int n = n0 + tx*4 + v;
            if (n < HH) g_h[m*HH + n] = acc[u][v];
        }
    }
}

// ---------------- LN + relu + fc2 + softmax ----------------
__device__ __forceinline__ float block_reduce512(float v, float* red) {
    int tid = threadIdx.x;
    red[tid] = v;
    __syncthreads();
    for (int off = 256; off > 0; off >>= 1) {
        if (tid < off) red[tid] += red[tid + off];
        __syncthreads();
    }
    float r = red[0];
    __syncthreads();
    return r;
}

__global__ __launch_bounds__(512) void k_head(const float* __restrict__ fc1b,
                                              const float* __restrict__ lng,
                                              const float* __restrict__ lnb,
                                              const float* __restrict__ fc2w,
                                              const float* __restrict__ fc2b,
                                              float* __restrict__ out) {
    int b = blockIdx.x, tid = threadIdx.x;
    __shared__ float red[512];
    bool act = tid < HH;
    float h = act ? (g_h[b*HH + tid] + fc1b[tid]) : 0.f;
    float mu = block_reduce512(h, red) * (1.f/HH);
    float d = act ? (h - mu) : 0.f;
    float var = block_reduce512(d*d, red) * (1.f/HH);
    float hn = 0.f;
    if (act) {
        hn = d * rsqrtf(var + 1e-5f) * lng[tid] + lnb[tid];
        hn = fmaxf(hn, 0.f);
    }
    float o0 = block_reduce512(act ? hn*fc2w[tid]      : 0.f, red);
    float o1 = block_reduce512(act ? hn*fc2w[HH + tid] : 0.f, red);
    if (tid == 0) {
        o0 += fc2b[0];
        o1 += fc2b[1];
        out[b*2 + 0] = o0;
        out[b*2 + 1] = o1;
        float m = fmaxf(o0, o1);
        float e0 = expf(o0 - m), e1 = expf(o1 - m);
        float inv = 1.f/(e0 + e1);
        out[BB*2 + b*2 + 0] = e0*inv;
        out[BB*2 + b*2 + 1] = e1*inv;
    }
}

// ---------------- launch ----------------
extern "C" void kernel_launch(void* const* d_in, const int* in_sizes, int n_in,
                              void* d_out, int out_size) {
    (void)in_sizes; (void)n_in; (void)out_size;
    const int*   seq1 = (const int*)d_in[0];
    const int*   seq2 = (const int*)d_in[1];
    const float* emb  = (const float*)d_in[2];
    const float* W    = (const float*)d_in[3];
    const float* cw   = (const float*)d_in[4];
    const float* cb   = (const float*)d_in[5];
    const float* fc1w = (const float*)d_in[6];
    const float* fc1b = (const float*)d_in[7];
    const float* lng  = (const float*)d_in[8];
    const float* lnb  = (const float*)d_in[9];
    const float* fc2w = (const float*)d_in[10];
    const float* fc2b = (const float*)d_in[11];
    float* out = (float*)d_out;

    const int SM_MATCH = (2*64*MPAD + 2*SS*MPAD + 64 + SS + 4*64 + 2*SS) * 4;  // ~33.5KB
    const int SM_FGEMM = 2*FBUF*4;                                              // ~89.1KB
    const int SM_CONV  = (2*(CROWS+2)*(EE+2) + 18) * 4;                         // ~43.6KB

    cudaFuncSetAttribute(k_match, cudaFuncAttributeMaxDynamicSharedMemorySize, SM_MATCH);
    cudaFuncSetAttribute(k_fgemm, cudaFuncAttributeMaxDynamicSharedMemorySize, SM_FGEMM);
    cudaFuncSetAttribute(k_conv,  cudaFuncAttributeMaxDynamicSharedMemorySize, SM_CONV);

    k_wprep<<<dim3(320, LL), 128>>>(W);
    k_gather<<<BB, 256>>>(seq1, seq2, emb);
    for (int l = 0; l < LL; l++) {
        int last = (l == LL-1);
        k_match<<<dim3(BB, 2), 256, SM_MATCH>>>(0, l);
        k_fgemm<<<dim3(BB, 5), 256, SM_FGEMM>>>(l);
        k_conv<<<dim3(BB, 8, 2), 320, SM_CONV>>>(cw, cb, l, last ? 0 : 1);
        if (!last) {
            k_match<<<dim3(BB, 2), 256, SM_MATCH>>>(1, l);
            k_pool<<<dim3(BB, 8, 2), 96>>>();
        }
    }
    k_fc1<<<dim3(8, 5), 256>>>(fc1w);
    k_head<<<BB, 512>>>(fc1b, lng, lnb, fc2w, fc2b, out);
}

// round 13
// speedup vs baseline: 1.5428x; 1.0448x over previous
#include <cuda_runtime.h>
#include <cuda_fp16.h>
#include <math.h>
#include <stdint.h>

#define BB 512
#define SS 128
#define EE 300
#define LL 2
#define HH 300
#define FCIN 1800   // E*(1+L)*2
#define CROWS 16

// ---------------- device scratch (no allocation allowed) ----------------
__device__ float g_s1[BB*SS*EE];
__device__ float g_s2[BB*SS*EE];
__device__ float g_f1[BB*SS*EE];
__device__ float g_f2[BB*SS*EE];
__device__ float g_o1[BB*SS*EE];
__device__ float g_o2[BB*SS*EE];
__device__ __half g_Ah [BB*SS*SS];   // A  fp16
__device__ __half g_ATh[BB*SS*SS];   // A^T fp16
__device__ __half g_Wth[LL*320*SS];  // W^T fp16 [l][n][k], zero-pad n>=300
__device__ float g_w1[BB*SS];
__device__ float g_w2[BB*SS];
__device__ float g_v1[BB*SS];
__device__ float g_v2[BB*SS];
__device__ float g_x [BB*FCIN];
__device__ float g_h [BB*HH];

__device__ __forceinline__ float tanh_fast(float x) {
    float r; asm("tanh.approx.f32 %0, %1;" : "=f"(r) : "f"(x)); return r;
}
__device__ __forceinline__ uint32_t pack_h2(float a, float b) {
    __half2 h = __floats2half2_rn(a, b);
    return *(uint32_t*)&h;
}
__device__ __forceinline__ void cpasync16(void* dst, const void* src) {
    uint32_t d = (uint32_t)__cvta_generic_to_shared(dst);
    asm volatile("cp.async.ca.shared.global [%0], [%1], 16;\n" :: "r"(d), "l"(src));
}
#define MMA_F16(C, A, B) \
    asm volatile("mma.sync.aligned.m16n8k16.row.col.f32.f16.f16.f32 " \
        "{%0,%1,%2,%3}, {%4,%5,%6,%7}, {%8,%9}, {%0,%1,%2,%3};" \
        : "+f"((C)[0]), "+f"((C)[1]), "+f"((C)[2]), "+f"((C)[3]) \
        : "r"((A)[0]), "r"((A)[1]), "r"((A)[2]), "r"((A)[3]), \
          "r"((B)[0]), "r"((B)[1]))

// ---------------- W prep: g_Wth[l][n][k] = fp16(W[l][k][n]) ----------------
__global__ void k_wprep(const float* __restrict__ W) {
    int n = blockIdx.x, l = blockIdx.y, k = threadIdx.x;
    float v = 0.f;
    if (n < EE) v = W[(size_t)l*SS*EE + k*EE + n];
    g_Wth[(l*320 + n)*SS + k] = __float2half(v);
}

// ---------------- embedding gather + masks + fused mean(slot0) ----------------
__global__ __launch_bounds__(256) void k_gather(const int* __restrict__ seq1,
                                                const int* __restrict__ seq2,
                                                const float* __restrict__ emb) {
    __shared__ float msum[2][EE];
    int b = blockIdx.x;
    int tid = threadIdx.x;
    int warp = tid >> 5, lane = tid & 31;
    for (int i = tid; i < 2*EE; i += 256) ((float*)msum)[i] = 0.f;
    for (int i = tid; i < SS; i += 256) {
        g_v1[b*SS+i] = (seq1[b*SS+i] != 0) ? 1.f : 0.f;
        g_v2[b*SS+i] = (seq2[b*SS+i] != 0) ? 1.f : 0.f;
    }
    __syncthreads();
    int sel = warp & 1;
    float4 acc[3];
#pragma unroll
    for (int jj = 0; jj < 3; jj++) acc[jj] = make_float4(0.f,0.f,0.f,0.f);
    for (int idx = warp; idx < 2*SS; idx += 8) {
        int s = idx >> 1;
        int tok = sel ? seq2[b*SS+s] : seq1[b*SS+s];
        const float4* src = (const float4*)(emb + (long)tok*EE);
        float4* dst = (float4*)((sel ? g_s2 : g_s1) + (b*SS+s)*EE);
#pragma unroll
        for (int jj = 0; jj < 3; jj++) {
            int j = lane + 32*jj;
            if (j < EE/4) {
                float4 v = src[j];
                dst[j] = v;
                acc[jj].x += v.x; acc[jj].y += v.y; acc[jj].z += v.z; acc[jj].w += v.w;
            }
        }
    }
#pragma unroll
    for (int jj = 0; jj < 3; jj++) {
        int j = lane + 32*jj;
        if (j < EE/4) {
            atomicAdd(&msum[sel][4*j+0], acc[jj].x);
            atomicAdd(&msum[sel][4*j+1], acc[jj].y);
            atomicAdd(&msum[sel][4*j+2], acc[jj].z);
            atomicAdd(&msum[sel][4*j+3], acc[jj].w);
        }
    }
    __syncthreads();
    for (int e = tid; e < EE; e += 256) {
        g_x[b*FCIN + e]        = msum[0][e]*(1.f/SS);
        g_x[b*FCIN + 3*EE + e] = msum[1][e]*(1.f/SS);
    }
}

// ---------------- match-score, fp16 tensor cores, SPLIT grid (B,2) ------------
// mode=0: store A (fp16) + A^T (fp16, smem-transposed) + zero g_w2/g_x slots
// mode=1: w1 direct (own rows), w2 atomicAdd (pre-zeroed by mode 0)
#define MPAD 20     // half2 words per 32-k chunk (16) + pad 4
#define MCH 10      // ceil(300/32)
__global__ __launch_bounds__(256, 2) void k_match(int mode, int layer) {
    extern __shared__ float sm[];
    uint32_t* Xs = (uint32_t*)sm;           // [2][64][20] half2 words
    uint32_t* Ys = Xs + 2*64*MPAD;          // [2][128][20]
    float* n1s = (float*)(Ys + 2*SS*MPAD);  // [64]
    float* n2s = n1s + 64;                  // [128]
    float* rowbuf = n2s + SS;               // [4][64]
    float* colbuf = rowbuf + 4*64;          // [2][128]

    int b = blockIdx.x, h = blockIdx.y;
    const float* X = (mode ? g_o1 : g_s1) + b*SS*EE + h*64*EE;
    const float* Y = (mode ? g_o2 : g_s2) + b*SS*EE;
    int tid = threadIdx.x;
    int lane = tid & 31, wid = tid >> 5;
    int g = lane >> 2, tig = lane & 3;
    int wm = wid & 1, wn = wid >> 1;

    int rX = tid >> 2, qx = tid & 3;
    int rY = tid >> 1, hy = tid & 1;
    const float* Xr = X + rX*EE + qx*8;
    const float* Yr = Y + rY*EE + hy*16;
    float mvx = g_v1[b*SS + h*64 + rX];
    float mvy = g_v2[b*SS + rY];
    float nx = 0.f, ny = 0.f;
    float4 vx[2], vy[4];

#define FETCH(c) do { \
    int kb = (c)*32; \
    _Pragma("unroll") for (int j = 0; j < 2; j++) { \
        int k = kb + qx*8 + 4*j; \
        vx[j] = (k < EE) ? *(const float4*)(Xr + kb + 4*j) : make_float4(0.f,0.f,0.f,0.f); \
    } \
    _Pragma("unroll") for (int j = 0; j < 4; j++) { \
        int k = kb + hy*16 + 4*j; \
        vy[j] = (k < EE) ? *(const float4*)(Yr + kb + 4*j) : make_float4(0.f,0.f,0.f,0.f); \
    } } while(0)

#define STBUF(buf) do { \
    uint32_t* xd = Xs + (buf)*64*MPAD + rX*MPAD + qx*4; \
    uint32_t* yd = Ys + (buf)*SS*MPAD + rY*MPAD + hy*8; \
    _Pragma("unroll") for (int j = 0; j < 2; j++) { \
        float x0=vx[j].x*mvx, x1=vx[j].y*mvx, x2=vx[j].z*mvx, x3=vx[j].w*mvx; \
        nx += x0*x0+x1*x1+x2*x2+x3*x3; \
        xd[2*j+0] = pack_h2(x0, x1); \
        xd[2*j+1] = pack_h2(x2, x3); \
    } \
    _Pragma("unroll") for (int j = 0; j < 4; j++) { \
        float y0=vy[j].x*mvy, y1=vy[j].y*mvy, y2=vy[j].z*mvy, y3=vy[j].w*mvy; \
        ny += y0*y0+y1*y1+y2*y2+y3*y3; \
        yd[2*j+0] = pack_h2(y0, y1); \
        yd[2*j+1] = pack_h2(y2, y3); \
    } } while(0)

    float acc[2][4][4];
#pragma unroll
    for (int mt = 0; mt < 2; mt++)
#pragma unroll
        for (int nt = 0; nt < 4; nt++)
#pragma unroll
            for (int q = 0; q < 4; q++) acc[mt][nt][q] = 0.f;

    FETCH(0); STBUF(0);
    __syncthreads();

    for (int c = 0; c < MCH; c++) {
        int cur = c & 1;
        if (c + 1 < MCH) FETCH(c+1);
        const uint32_t* xb = Xs + cur*64*MPAD;
        const uint32_t* yb = Ys + cur*SS*MPAD;
#pragma unroll
        for (int ks = 0; ks < 2; ks++) {
            int ws = ks*8;
            uint32_t a[2][4], bf[4][2];
#pragma unroll
            for (int mt = 0; mt < 2; mt++) {
                int row = wm*32 + mt*16 + g;
                a[mt][0] = xb[row*MPAD + ws + tig];
                a[mt][1] = xb[(row+8)*MPAD + ws + tig];
                a[mt][2] = xb[row*MPAD + ws + tig + 4];
                a[mt][3] = xb[(row+8)*MPAD + ws + tig + 4];
            }
#pragma unroll
            for (int nt = 0; nt < 4; nt++) {
                int cr = wn*32 + nt*8 + g;
                bf[nt][0] = yb[cr*MPAD + ws + tig];
                bf[nt][1] = yb[cr*MPAD + ws + tig + 4];
            }
#pragma unroll
            for (int mt = 0; mt < 2; mt++)
#pragma unroll
                for (int nt = 0; nt < 4; nt++)
                    MMA_F16(acc[mt][nt], a[mt], bf[nt]);
        }
        if (c + 1 < MCH) STBUF(cur ^ 1);
        __syncthreads();
    }

    nx += __shfl_xor_sync(0xffffffffu, nx, 1);
    nx += __shfl_xor_sync(0xffffffffu, nx, 2);
    if (qx == 0) n1s[rX] = nx;
    ny += __shfl_xor_sync(0xffffffffu, ny, 1);
    if (hy == 0) n2s[rY] = ny;
    __syncthreads();

    if (mode == 0) {
        __half* Ao = g_Ah + (size_t)b*SS*SS + h*64*SS;
        __half* ts = (__half*)sm;   // transpose stage [128 cols][68 rows pad]
#pragma unroll
        for (int mt = 0; mt < 2; mt++) {
            int row = wm*32 + mt*16 + g;
            float nr0 = n1s[row], nr1 = n1s[row+8];
#pragma unroll
            for (int nt = 0; nt < 4; nt++) {
                int col = wn*32 + nt*8 + 2*tig;
                float nc0 = n2s[col], nc1 = n2s[col+1];
                float a00 = 1.f/(1.f + sqrtf(fmaxf(nr0 + nc0 - 2.f*acc[mt][nt][0], 0.f)));
                float a01 = 1.f/(1.f + sqrtf(fmaxf(nr0 + nc1 - 2.f*acc[mt][nt][1], 0.f)));
                float a10 = 1.f/(1.f + sqrtf(fmaxf(nr1 + nc0 - 2.f*acc[mt][nt][2], 0.f)));
                float a11 = 1.f/(1.f + sqrtf(fmaxf(nr1 + nc1 - 2.f*acc[mt][nt][3], 0.f)));
                *(__half2*)(Ao + row*SS + col)     = __floats2half2_rn(a00, a01);
                *(__half2*)(Ao + (row+8)*SS + col) = __floats2half2_rn(a10, a11);
                ts[(col+0)*68 + row]   = __float2half(a00);
                ts[(col+1)*68 + row]   = __float2half(a01);
                ts[(col+0)*68 + row+8] = __float2half(a10);
                ts[(col+1)*68 + row+8] = __float2half(a11);
            }
        }
        __syncthreads();
        __half* ATo = g_ATh + (size_t)b*SS*SS + h*64;
        for (int i = tid; i < 128*32; i += 256) {
            int col = i >> 5, rw = i & 31;
            __half2 v = *(__half2*)&ts[col*68 + 2*rw];
            *(__half2*)(ATo + col*SS + 2*rw) = v;
        }
        // fused zeroing: g_w2 (h==0) + g_x mean slot for this pair
        if (h == 0 && tid < SS) g_w2[b*SS + tid] = 0.f;
        int slot = (h ? 4 : 1) + layer;
        for (int e = tid; e < EE; e += 256) g_x[b*FCIN + slot*EE + e] = 0.f;
    } else {
        float cs0[4], cs1[4];
#pragma unroll
        for (int nt = 0; nt < 4; nt++) { cs0[nt] = 0.f; cs1[nt] = 0.f; }
#pragma unroll
        for (int mt = 0; mt < 2; mt++) {
            int row = wm*32 + mt*16 + g;
            float nr0 = n1s[row], nr1 = n1s[row+8];
            float rlo = 0.f, rhi = 0.f;
#pragma unroll
            for (int nt = 0; nt < 4; nt++) {
                int col = wn*32 + nt*8 + 2*tig;
                float nc0 = n2s[col], nc1 = n2s[col+1];
                float a00 = 1.f/(1.f + sqrtf(fmaxf(nr0 + nc0 - 2.f*acc[mt][nt][0], 0.f)));
                float a01 = 1.f/(1.f + sqrtf(fmaxf(nr0 + nc1 - 2.f*acc[mt][nt][1], 0.f)));
                float a10 = 1.f/(1.f + sqrtf(fmaxf(nr1 + nc0 - 2.f*acc[mt][nt][2], 0.f)));
                float a11 = 1.f/(1.f + sqrtf(fmaxf(nr1 + nc1 - 2.f*acc[mt][nt][3], 0.f)));
                rlo += a00 + a01;
                rhi += a10 + a11;
                cs0[nt] += a00 + a10;
                cs1[nt] += a01 + a11;
            }
            rlo += __shfl_xor_sync(0xffffffffu, rlo, 1);
            rlo += __shfl_xor_sync(0xffffffffu, rlo, 2);
            rhi += __shfl_xor_sync(0xffffffffu, rhi, 1);
            rhi += __shfl_xor_sync(0xffffffffu, rhi, 2);
            if (tig == 0) {
                rowbuf[wn*64 + row]   = rlo;
                rowbuf[wn*64 + row+8] = rhi;
            }
        }
#pragma unroll
        for (int nt = 0; nt < 4; nt++) {
            float c0 = cs0[nt], c1 = cs1[nt];
            c0 += __shfl_xor_sync(0xffffffffu, c0, 4);
            c0 += __shfl_xor_sync(0xffffffffu, c0, 8);
            c0 += __shfl_xor_sync(0xffffffffu, c0, 16);
            c1 += __shfl_xor_sync(0xffffffffu, c1, 4);
            c1 += __shfl_xor_sync(0xffffffffu, c1, 8);
            c1 += __shfl_xor_sync(0xffffffffu, c1, 16);
            if (g == 0) {
                int col = wn*32 + nt*8 + 2*tig;
                colbuf[wm*SS + col]     = c0;
                colbuf[wm*SS + col + 1] = c1;
            }
        }
        __syncthreads();
        if (tid < 64)
            g_w1[b*SS + h*64 + tid] = rowbuf[tid] + rowbuf[64+tid] + rowbuf[128+tid] + rowbuf[192+tid];
        if (tid < SS)
            atomicAdd(&g_w2[b*SS + tid], colbuf[tid] + colbuf[SS+tid]);
    }
#undef FETCH
#undef STBUF
}

// ---------------- f1=A@W, f2=A^T@W, fp16 mma, cp.async double-buffered --------
// warps 0-3: A tile (f1); warps 4-7: A^T tile (f2). Identical fragment patterns.
#define HPAD 20
#define FBUF2 (128*HPAD + 128*HPAD + 64*HPAD)   // 6400 words per buffer
__global__ __launch_bounds__(256, 2) void k_fgemm(int layer) {
    extern __shared__ float sm[];
    int b = blockIdx.x;
    int n0 = blockIdx.y * 64;
    const __half* Ah  = g_Ah  + (size_t)b*SS*SS;
    const __half* ATh = g_ATh + (size_t)b*SS*SS;
    const __half* Wth = g_Wth + (size_t)layer*320*SS;
    int tid = threadIdx.x;
    int lane = tid & 31, wid = tid >> 5;
    int g = lane >> 2, tig = lane & 3;
    int half = wid >> 2, wm = wid & 3;

#define LOADCH(c, buf) do { \
    uint32_t* base_ = (uint32_t*)sm + (buf)*FBUF2; \
    uint32_t* A1_ = base_; \
    uint32_t* AT_ = base_ + 128*HPAD; \
    uint32_t* Wb_ = AT_ + 128*HPAD; \
    int k0_ = (c)*32; \
    _Pragma("unroll") for (int j = 0; j < 2; j++) { \
        int i = tid + 256*j; int r = i >> 2, q = i & 3; \
        cpasync16(A1_ + r*HPAD + q*4, Ah + r*SS + k0_ + q*8); \
        cpasync16(AT_ + r*HPAD + q*4, ATh + r*SS + k0_ + q*8); \
    } \
    { int r = tid >> 2, q = tid & 3; \
      cpasync16(Wb_ + r*HPAD + q*4, Wth + (n0+r)*SS + k0_ + q*8); } \
    asm volatile("cp.async.commit_group;\n" ::); \
} while (0)

    float acc[2][8][4];
#pragma unroll
    for (int mt = 0; mt < 2; mt++)
#pragma unroll
        for (int nt = 0; nt < 8; nt++)
#pragma unroll
            for (int q = 0; q < 4; q++) acc[mt][nt][q] = 0.f;

    LOADCH(0, 0);
    for (int c = 0; c < 4; c++) {
        if (c < 3) {
            LOADCH(c+1, (c+1)&1);
            asm volatile("cp.async.wait_group 1;\n" ::);
        } else {
            asm volatile("cp.async.wait_group 0;\n" ::);
        }
        __syncthreads();
        const uint32_t* Abase = (uint32_t*)sm + (c&1)*FBUF2 + half*128*HPAD;
        const uint32_t* Wb    = (uint32_t*)sm + (c&1)*FBUF2 + 2*128*HPAD;
#pragma unroll
        for (int ks = 0; ks < 2; ks++) {
            int ws = ks*8;
            uint32_t a[2][4], bf[8][2];
#pragma unroll
            for (int mt = 0; mt < 2; mt++) {
                int row = wm*32 + mt*16 + g;
                a[mt][0] = Abase[row*HPAD + ws + tig];
                a[mt][1] = Abase[(row+8)*HPAD + ws + tig];
                a[mt][2] = Abase[row*HPAD + ws + tig + 4];
                a[mt][3] = Abase[(row+8)*HPAD + ws + tig + 4];
            }
#pragma unroll
            for (int nt = 0; nt < 8; nt++) {
                int cn = nt*8 + g;
                bf[nt][0] = Wb[cn*HPAD + ws + tig];
                bf[nt][1] = Wb[cn*HPAD + ws + tig + 4];
            }
#pragma unroll
            for (int mt = 0; mt < 2; mt++)
#pragma unroll
                for (int nt = 0; nt < 8; nt++)
                    MMA_F16(acc[mt][nt], a[mt], bf[nt]);
        }
        __syncthreads();
    }
#undef LOADCH

    float* out = (half ? g_f2 : g_f1) + b*SS*EE;
#pragma unroll
    for (int mt = 0; mt < 2; mt++) {
        int row = wm*32 + mt*16 + g;
#pragma unroll
        for (int nt = 0; nt < 8; nt++) {
            int col = n0 + nt*8 + 2*tig;
            if (col < EE) {
                *(float2*)(out + row*EE + col)     = make_float2(acc[mt][nt][0], acc[mt][nt][1]);
                *(float2*)(out + (row+8)*EE + col) = make_float2(acc[mt][nt][2], acc[mt][nt][3]);
            }
        }
    }
}

// ---------------- conv 2in->1out 3x3 + tanh + fused mean: column-per-thread ---
__global__ __launch_bounds__(320) void k_conv(const float* __restrict__ cw,
                                              const float* __restrict__ cb,
                                              int layer, int store) {
    extern __shared__ float sm[];
    float* xs = sm;                       // [2][18][302]
    float* w  = xs + 2*(CROWS+2)*(EE+2);  // [18]

    int b = blockIdx.x, ch = blockIdx.y, pair = blockIdx.z;
    int s0 = ch * CROWS;
    const float* X0 = (pair ? g_s2 : g_s1) + b*SS*EE;
    const float* X1 = (pair ? g_f2 : g_f1) + b*SS*EE;
    float* O = (pair ? g_o2 : g_o1) + b*SS*EE;
    int tid = threadIdx.x;
    if (tid < 18) w[tid] = cw[layer*18 + tid];
    if (tid < 2*(CROWS+2)*2) {
        int c = tid / (2*(CROWS+2));
        int rem = tid % (2*(CROWS+2));
        int j = rem >> 1, side = rem & 1;
        xs[(c*(CROWS+2) + j)*(EE+2) + (side ? EE+1 : 0)] = 0.f;
    }
    for (int i = tid; i < 2*(CROWS+2)*(EE/4); i += 320) {
        int c = i / ((CROWS+2)*(EE/4));
        int rem = i % ((CROWS+2)*(EE/4));
        int j = rem / (EE/4), q = rem % (EE/4);
        int srow = s0 + j - 1;
        float4 val = make_float4(0.f,0.f,0.f,0.f);
        if (srow >= 0 && srow < SS)
            val = *(const float4*)((c ? X1 : X0) + srow*EE + q*4);
        float* dptr = &xs[(c*(CROWS+2) + j)*(EE+2) + q*4 + 1];
        dptr[0]=val.x; dptr[1]=val.y; dptr[2]=val.z; dptr[3]=val.w;
    }
    __syncthreads();
    if (tid < EE) {
        int e = tid;
        float bias = cb[layer];
        const float* xs0 = xs;
        const float* xs1 = xs + (CROWS+2)*(EE+2);
        float sv[3][3], fv[3][3];
#pragma unroll
        for (int kh = 0; kh < 2; kh++)
#pragma unroll
            for (int kw = 0; kw < 3; kw++) {
                sv[kh][kw] = xs0[kh*(EE+2) + e + kw];
                fv[kh][kw] = xs1[kh*(EE+2) + e + kw];
            }
        float colsum = 0.f;
#pragma unroll 4
        for (int r = 0; r < CROWS; r++) {
#pragma unroll
            for (int kw = 0; kw < 3; kw++) {
                sv[2][kw] = xs0[(r+2)*(EE+2) + e + kw];
                fv[2][kw] = xs1[(r+2)*(EE+2) + e + kw];
            }
            float acc = bias;
#pragma unroll
            for (int kh = 0; kh < 3; kh++)
#pragma unroll
                for (int kw = 0; kw < 3; kw++)
                    acc += w[kh*3+kw]*sv[kh][kw] + w[9+kh*3+kw]*fv[kh][kw];
            float t = tanh_fast(acc);
            if (store) O[(s0+r)*EE + e] = t;
            colsum += t;
#pragma unroll
            for (int kw = 0; kw < 3; kw++) {
                sv[0][kw] = sv[1][kw]; sv[1][kw] = sv[2][kw];
                fv[0][kw] = fv[1][kw]; fv[1][kw] = fv[2][kw];
            }
        }
        int slot = (pair ? 4 : 1) + layer;
        atomicAdd(&g_x[b*FCIN + slot*EE + e], colsum*(1.f/SS));
    }
}

// ---------------- weighted avg-pool3 + residual update, float4 ----------------
__global__ __launch_bounds__(96) void k_pool() {
    int b = blockIdx.x, ch = blockIdx.y, pair = blockIdx.z;
    int s0 = ch * CROWS;
    const float* O = (pair ? g_o2 : g_o1) + b*SS*EE;
    float* Sx = (pair ? g_s2 : g_s1) + b*SS*EE;
    const float* wv = (pair ? g_w2 : g_w1) + b*SS;
    __shared__ float w[CROWS+2];
    if (threadIdx.x < CROWS+2) {
        int s = s0 + (int)threadIdx.x - 1;
        w[threadIdx.x] = (s >= 0 && s < SS) ? wv[s] : 0.f;
    }
    __syncthreads();
    int t = threadIdx.x;
    if (t >= 75) return;
    int e = t*4;
    float4 a = make_float4(0.f,0.f,0.f,0.f);
    if (s0 > 0) {
        float4 v = *(const float4*)(O + (s0-1)*EE + e);
        a = make_float4(v.x*w[0], v.y*w[0], v.z*w[0], v.w*w[0]);
    }
    float4 v0 = *(const float4*)(O + s0*EE + e);
    float4 bm = make_float4(v0.x*w[1], v0.y*w[1], v0.z*w[1], v0.w*w[1]);
#pragma unroll
    for (int i = 0; i < CROWS; i++) {
        int s = s0 + i;
        float4 cn = make_float4(0.f,0.f,0.f,0.f);
        if (s+1 < SS) {
            float4 v = *(const float4*)(O + (s+1)*EE + e);
            float ww = w[i+2];
            cn = make_float4(v.x*ww, v.y*ww, v.z*ww, v.w*ww);
        }
        float4 sx = *(float4*)(Sx + s*EE + e);
        sx.x += (a.x + bm.x + cn.x) * (1.f/3.f);
        sx.y += (a.y + bm.y + cn.y) * (1.f/3.f);
        sx.z += (a.z + bm.z + cn.z) * (1.f/3.f);
        sx.w += (a.w + bm.w + cn.w) * (1.f/3.f);
        *(float4*)(Sx + s*EE + e) = sx;
        a = bm; bm = cn;
    }
}

// ---------------- fc1 GEMM: [512,1800] @ [1800,300]^T -> g_h ----------------
__global__ __launch_bounds__(256) void k_fc1(const float* __restrict__ fw) {
    int m0 = blockIdx.x * 64, n0 = blockIdx.y * 64;
    __shared__ float Xs[8][68];
    __shared__ float Ws2[8][68];
    int tid = threadIdx.x, ty = tid >> 4, tx = tid & 15;
    float acc[4][4];
#pragma unroll
    for (int u = 0; u < 4; u++)
#pragma unroll
        for (int v = 0; v < 4; v++) acc[u][v] = 0.f;

    for (int k0 = 0; k0 < FCIN; k0 += 8) {
        __syncthreads();
#pragma unroll 2
        for (int i = tid; i < 512; i += 256) {
            int r = i >> 3, kk = i & 7;
            Xs[kk][r] = g_x[(m0 + r)*FCIN + k0 + kk];
            int n = n0 + r;
            Ws2[kk][r] = (n < HH) ? fw[n*FCIN + k0 + kk] : 0.f;
        }
        __syncthreads();
#pragma unroll
        for (int kk = 0; kk < 8; kk++) {
            float4 xa = *(const float4*)&Xs[kk][ty*4];
            float4 wb = *(const float4*)&Ws2[kk][tx*4];
            float xv[4] = {xa.x, xa.y, xa.z, xa.w};
            float wvv[4] = {wb.x, wb.y, wb.z, wb.w};
#pragma unroll
            for (int u = 0; u < 4; u++)
#pragma unroll
                for (int v = 0; v < 4; v++) acc[u][v] += xv[u]*wvv[v];
        }
    }
#pragma unroll
    for (int u = 0; u < 4; u++) {
        int m = m0 + ty*4 + u;
#pragma unroll
        for (int v = 0; v < 4; v++) {
            int n = n0 + tx*4 + v;
            if (n < HH) g_h[m*HH + n] = acc[u][v];
        }
    }
}

// ---------------- LN + relu + fc2 + softmax ----------------
__device__ __forceinline__ float block_reduce512(float v, float* red) {
    int tid = threadIdx.x;
    red[tid] = v;
    __syncthreads();
    for (int off = 256; off > 0; off >>= 1) {
        if (tid < off) red[tid] += red[tid + off];
        __syncthreads();
    }
    float r = red[0];
    __syncthreads();
    return r;
}

__global__ __launch_bounds__(512) void k_head(const float* __restrict__ fc1b,
                                              const float* __restrict__ lng,
                                              const float* __restrict__ lnb,
                                              const float* __restrict__ fc2w,
                                              const float* __restrict__ fc2b,
                                              float* __restrict__ out) {
    int b = blockIdx.x, tid = threadIdx.x;
    __shared__ float red[512];
    bool act = tid < HH;
    float h = act ? (g_h[b*HH + tid] + fc1b[tid]) : 0.f;
    float mu = block_reduce512(h, red) * (1.f/HH);
    float d = act ? (h - mu) : 0.f;
    float var = block_reduce512(d*d, red) * (1.f/HH);
    float hn = 0.f;
    if (act) {
        hn = d * rsqrtf(var + 1e-5f) * lng[tid] + lnb[tid];
        hn = fmaxf(hn, 0.f);
    }
    float o0 = block_reduce512(act ? hn*fc2w[tid]      : 0.f, red);
    float o1 = block_reduce512(act ? hn*fc2w[HH + tid] : 0.f, red);
    if (tid == 0) {
        o0 += fc2b[0];
        o1 += fc2b[1];
        out[b*2 + 0] = o0;
        out[b*2 + 1] = o1;
        float m = fmaxf(o0, o1);
        float e0 = expf(o0 - m), e1 = expf(o1 - m);
        float inv = 1.f/(e0 + e1);
        out[BB*2 + b*2 + 0] = e0*inv;
        out[BB*2 + b*2 + 1] = e1*inv;
    }
}

// ---------------- launch ----------------
extern "C" void kernel_launch(void* const* d_in, const int* in_sizes, int n_in,
                              void* d_out, int out_size) {
    (void)in_sizes; (void)n_in; (void)out_size;
    const int*   seq1 = (const int*)d_in[0];
    const int*   seq2 = (const int*)d_in[1];
    const float* emb  = (const float*)d_in[2];
    const float* W    = (const float*)d_in[3];
    const float* cw   = (const float*)d_in[4];
    const float* cb   = (const float*)d_in[5];
    const float* fc1w = (const float*)d_in[6];
    const float* fc1b = (const float*)d_in[7];
    const float* lng  = (const float*)d_in[8];
    const float* lnb  = (const float*)d_in[9];
    const float* fc2w = (const float*)d_in[10];
    const float* fc2b = (const float*)d_in[11];
    float* out = (float*)d_out;

    const int SM_MATCH = (2*64*MPAD + 2*SS*MPAD + 64 + SS + 4*64 + 2*SS) * 4;  // ~33.5KB
    const int SM_FGEMM = 2*FBUF2*4;                                             // ~51.2KB
    const int SM_CONV  = (2*(CROWS+2)*(EE+2) + 18) * 4;                         // ~43.6KB

    cudaFuncSetAttribute(k_match, cudaFuncAttributeMaxDynamicSharedMemorySize, SM_MATCH);
    cudaFuncSetAttribute(k_fgemm, cudaFuncAttributeMaxDynamicSharedMemorySize, SM_FGEMM);
    cudaFuncSetAttribute(k_conv,  cudaFuncAttributeMaxDynamicSharedMemorySize, SM_CONV);

    k_wprep<<<dim3(320, LL), 128>>>(W);
    k_gather<<<BB, 256>>>(seq1, seq2, emb);
    for (int l = 0; l < LL; l++) {
        int last = (l == LL-1);
        k_match<<<dim3(BB, 2), 256, SM_MATCH>>>(0, l);
        k_fgemm<<<dim3(BB, 5), 256, SM_FGEMM>>>(l);
        k_conv<<<dim3(BB, 8, 2), 320, SM_CONV>>>(cw, cb, l, last ? 0 : 1);
        if (!last) {
            k_match<<<dim3(BB, 2), 256, SM_MATCH>>>(1, l);
            k_pool<<<dim3(BB, 8, 2), 96>>>();
        }
    }
    k_fc1<<<dim3(8, 5), 256>>>(fc1w);
    k_head<<<BB, 512>>>(fc1b, lng, lnb, fc2w, fc2b, out);
}

// round 14
// speedup vs baseline: 1.6362x; 1.0605x over previous
#include <cuda_runtime.h>
#include <cuda_fp16.h>
#include <math.h>
#include <stdint.h>

#define BB 512
#define SS 128
#define EE 300
#define LL 2
#define HH 300
#define FCIN 1800   // E*(1+L)*2
#define CROWS 16

// ---------------- device scratch (no allocation allowed) ----------------
__device__ float g_s1[BB*SS*EE];
__device__ float g_s2[BB*SS*EE];
__device__ __half g_f1h[BB*SS*EE];
__device__ __half g_f2h[BB*SS*EE];
__device__ float g_o1[BB*SS*EE];
__device__ float g_o2[BB*SS*EE];
__device__ __half g_Ah [BB*SS*SS];   // A  fp16
__device__ __half g_ATh[BB*SS*SS];   // A^T fp16
__device__ __half g_Wth[LL*320*SS];  // W^T fp16 [l][n][k], zero-pad n>=300
__device__ float g_w1[BB*SS];
__device__ float g_w2[BB*SS];
__device__ float g_v1[BB*SS];
__device__ float g_v2[BB*SS];
__device__ float g_x [BB*FCIN];
__device__ float g_h [BB*HH];

__device__ __forceinline__ float tanh_fast(float x) {
    float r; asm("tanh.approx.f32 %0, %1;" : "=f"(r) : "f"(x)); return r;
}
__device__ __forceinline__ uint32_t pack_h2(float a, float b) {
    __half2 h = __floats2half2_rn(a, b);
    return *(uint32_t*)&h;
}
__device__ __forceinline__ void cpasync16(void* dst, const void* src) {
    uint32_t d = (uint32_t)__cvta_generic_to_shared(dst);
    asm volatile("cp.async.ca.shared.global [%0], [%1], 16;\n" :: "r"(d), "l"(src));
}
#define MMA_F16(C, A, B) \
    asm volatile("mma.sync.aligned.m16n8k16.row.col.f32.f16.f16.f32 " \
        "{%0,%1,%2,%3}, {%4,%5,%6,%7}, {%8,%9}, {%0,%1,%2,%3};" \
        : "+f"((C)[0]), "+f"((C)[1]), "+f"((C)[2]), "+f"((C)[3]) \
        : "r"((A)[0]), "r"((A)[1]), "r"((A)[2]), "r"((A)[3]), \
          "r"((B)[0]), "r"((B)[1]))

// ---------------- W prep: g_Wth[l][n][k] = fp16(W[l][k][n]) ----------------
__global__ void k_wprep(const float* __restrict__ W) {
    int n = blockIdx.x, l = blockIdx.y, k = threadIdx.x;
    float v = 0.f;
    if (n < EE) v = W[(size_t)l*SS*EE + k*EE + n];
    g_Wth[(l*320 + n)*SS + k] = __float2half(v);
}

// ---------------- embedding gather + masks + fused mean(slot0) ----------------
__global__ __launch_bounds__(256) void k_gather(const int* __restrict__ seq1,
                                                const int* __restrict__ seq2,
                                                const float* __restrict__ emb) {
    __shared__ float msum[2][EE];
    int b = blockIdx.x;
    int tid = threadIdx.x;
    int warp = tid >> 5, lane = tid & 31;
    for (int i = tid; i < 2*EE; i += 256) ((float*)msum)[i] = 0.f;
    for (int i = tid; i < SS; i += 256) {
        g_v1[b*SS+i] = (seq1[b*SS+i] != 0) ? 1.f : 0.f;
        g_v2[b*SS+i] = (seq2[b*SS+i] != 0) ? 1.f : 0.f;
    }
    __syncthreads();
    int sel = warp & 1;
    float4 acc[3];
#pragma unroll
    for (int jj = 0; jj < 3; jj++) acc[jj] = make_float4(0.f,0.f,0.f,0.f);
    for (int idx = warp; idx < 2*SS; idx += 8) {
        int s = idx >> 1;
        int tok = sel ? seq2[b*SS+s] : seq1[b*SS+s];
        const float4* src = (const float4*)(emb + (long)tok*EE);
        float4* dst = (float4*)((sel ? g_s2 : g_s1) + (b*SS+s)*EE);
#pragma unroll
        for (int jj = 0; jj < 3; jj++) {
            int j = lane + 32*jj;
            if (j < EE/4) {
                float4 v = src[j];
                dst[j] = v;
                acc[jj].x += v.x; acc[jj].y += v.y; acc[jj].z += v.z; acc[jj].w += v.w;
            }
        }
    }
#pragma unroll
    for (int jj = 0; jj < 3; jj++) {
        int j = lane + 32*jj;
        if (j < EE/4) {
            atomicAdd(&msum[sel][4*j+0], acc[jj].x);
            atomicAdd(&msum[sel][4*j+1], acc[jj].y);
            atomicAdd(&msum[sel][4*j+2], acc[jj].z);
            atomicAdd(&msum[sel][4*j+3], acc[jj].w);
        }
    }
    __syncthreads();
    for (int e = tid; e < EE; e += 256) {
        g_x[b*FCIN + e]        = msum[0][e]*(1.f/SS);
        g_x[b*FCIN + 3*EE + e] = msum[1][e]*(1.f/SS);
    }
}

// ---------------- match-score, fp16 tensor cores, SPLIT grid (B,2) ------------
#define MPAD 20     // half2 words per 32-k chunk (16) + pad 4
#define MCH 10      // ceil(300/32)
__global__ __launch_bounds__(256, 2) void k_match(int mode, int layer) {
    extern __shared__ float sm[];
    uint32_t* Xs = (uint32_t*)sm;           // [2][64][20] half2 words
    uint32_t* Ys = Xs + 2*64*MPAD;          // [2][128][20]
    float* n1s = (float*)(Ys + 2*SS*MPAD);  // [64]
    float* n2s = n1s + 64;                  // [128]
    float* rowbuf = n2s + SS;               // [4][64]
    float* colbuf = rowbuf + 4*64;          // [2][128]

    int b = blockIdx.x, h = blockIdx.y;
    const float* X = (mode ? g_o1 : g_s1) + b*SS*EE + h*64*EE;
    const float* Y = (mode ? g_o2 : g_s2) + b*SS*EE;
    int tid = threadIdx.x;
    int lane = tid & 31, wid = tid >> 5;
    int g = lane >> 2, tig = lane & 3;
    int wm = wid & 1, wn = wid >> 1;

    int rX = tid >> 2, qx = tid & 3;
    int rY = tid >> 1, hy = tid & 1;
    const float* Xr = X + rX*EE + qx*8;
    const float* Yr = Y + rY*EE + hy*16;
    float mvx = g_v1[b*SS + h*64 + rX];
    float mvy = g_v2[b*SS + rY];
    float nx = 0.f, ny = 0.f;
    float4 vx[2], vy[4];

#define FETCH(c) do { \
    int kb = (c)*32; \
    _Pragma("unroll") for (int j = 0; j < 2; j++) { \
        int k = kb + qx*8 + 4*j; \
        vx[j] = (k < EE) ? *(const float4*)(Xr + kb + 4*j) : make_float4(0.f,0.f,0.f,0.f); \
    } \
    _Pragma("unroll") for (int j = 0; j < 4; j++) { \
        int k = kb + hy*16 + 4*j; \
        vy[j] = (k < EE) ? *(const float4*)(Yr + kb + 4*j) : make_float4(0.f,0.f,0.f,0.f); \
    } } while(0)

#define STBUF(buf) do { \
    uint32_t* xd = Xs + (buf)*64*MPAD + rX*MPAD + qx*4; \
    uint32_t* yd = Ys + (buf)*SS*MPAD + rY*MPAD + hy*8; \
    _Pragma("unroll") for (int j = 0; j < 2; j++) { \
        float x0=vx[j].x*mvx, x1=vx[j].y*mvx, x2=vx[j].z*mvx, x3=vx[j].w*mvx; \
        nx += x0*x0+x1*x1+x2*x2+x3*x3; \
        xd[2*j+0] = pack_h2(x0, x1); \
        xd[2*j+1] = pack_h2(x2, x3); \
    } \
    _Pragma("unroll") for (int j = 0; j < 4; j++) { \
        float y0=vy[j].x*mvy, y1=vy[j].y*mvy, y2=vy[j].z*mvy, y3=vy[j].w*mvy; \
        ny += y0*y0+y1*y1+y2*y2+y3*y3; \
        yd[2*j+0] = pack_h2(y0, y1); \
        yd[2*j+1] = pack_h2(y2, y3); \
    } } while(0)

    float acc[2][4][4];
#pragma unroll
    for (int mt = 0; mt < 2; mt++)
#pragma unroll
        for (int nt = 0; nt < 4; nt++)
#pragma unroll
            for (int q = 0; q < 4; q++) acc[mt][nt][q] = 0.f;

    FETCH(0); STBUF(0);
    __syncthreads();

    for (int c = 0; c < MCH; c++) {
        int cur = c & 1;
        if (c + 1 < MCH) FETCH(c+1);
        const uint32_t* xb = Xs + cur*64*MPAD;
        const uint32_t* yb = Ys + cur*SS*MPAD;
#pragma unroll
        for (int ks = 0; ks < 2; ks++) {
            int ws = ks*8;
            uint32_t a[2][4], bf[4][2];
#pragma unroll
            for (int mt = 0; mt < 2; mt++) {
                int row = wm*32 + mt*16 + g;
                a[mt][0] = xb[row*MPAD + ws + tig];
                a[mt][1] = xb[(row+8)*MPAD + ws + tig];
                a[mt][2] = xb[row*MPAD + ws + tig + 4];
                a[mt][3] = xb[(row+8)*MPAD + ws + tig + 4];
            }
#pragma unroll
            for (int nt = 0; nt < 4; nt++) {
                int cr = wn*32 + nt*8 + g;
                bf[nt][0] = yb[cr*MPAD + ws + tig];
                bf[nt][1] = yb[cr*MPAD + ws + tig + 4];
            }
#pragma unroll
            for (int mt = 0; mt < 2; mt++)
#pragma unroll
                for (int nt = 0; nt < 4; nt++)
                    MMA_F16(acc[mt][nt], a[mt], bf[nt]);
        }
        if (c + 1 < MCH) STBUF(cur ^ 1);
        __syncthreads();
    }

    nx += __shfl_xor_sync(0xffffffffu, nx, 1);
    nx += __shfl_xor_sync(0xffffffffu, nx, 2);
    if (qx == 0) n1s[rX] = nx;
    ny += __shfl_xor_sync(0xffffffffu, ny, 1);
    if (hy == 0) n2s[rY] = ny;
    __syncthreads();

    if (mode == 0) {
        __half* Ao = g_Ah + (size_t)b*SS*SS + h*64*SS;
        __half* ts = (__half*)sm;   // transpose stage [128 cols][68 rows pad]
#pragma unroll
        for (int mt = 0; mt < 2; mt++) {
            int row = wm*32 + mt*16 + g;
            float nr0 = n1s[row], nr1 = n1s[row+8];
#pragma unroll
            for (int nt = 0; nt < 4; nt++) {
                int col = wn*32 + nt*8 + 2*tig;
                float nc0 = n2s[col], nc1 = n2s[col+1];
                float a00 = 1.f/(1.f + sqrtf(fmaxf(nr0 + nc0 - 2.f*acc[mt][nt][0], 0.f)));
                float a01 = 1.f/(1.f + sqrtf(fmaxf(nr0 + nc1 - 2.f*acc[mt][nt][1], 0.f)));
                float a10 = 1.f/(1.f + sqrtf(fmaxf(nr1 + nc0 - 2.f*acc[mt][nt][2], 0.f)));
                float a11 = 1.f/(1.f + sqrtf(fmaxf(nr1 + nc1 - 2.f*acc[mt][nt][3], 0.f)));
                *(__half2*)(Ao + row*SS + col)     = __floats2half2_rn(a00, a01);
                *(__half2*)(Ao + (row+8)*SS + col) = __floats2half2_rn(a10, a11);
                ts[(col+0)*68 + row]   = __float2half(a00);
                ts[(col+1)*68 + row]   = __float2half(a01);
                ts[(col+0)*68 + row+8] = __float2half(a10);
                ts[(col+1)*68 + row+8] = __float2half(a11);
            }
        }
        __syncthreads();
        __half* ATo = g_ATh + (size_t)b*SS*SS + h*64;
        for (int i = tid; i < 128*32; i += 256) {
            int col = i >> 5, rw = i & 31;
            __half2 v = *(__half2*)&ts[col*68 + 2*rw];
            *(__half2*)(ATo + col*SS + 2*rw) = v;
        }
        if (h == 0 && tid < SS) g_w2[b*SS + tid] = 0.f;
        int slot = (h ? 4 : 1) + layer;
        for (int e = tid; e < EE; e += 256) g_x[b*FCIN + slot*EE + e] = 0.f;
    } else {
        float cs0[4], cs1[4];
#pragma unroll
        for (int nt = 0; nt < 4; nt++) { cs0[nt] = 0.f; cs1[nt] = 0.f; }
#pragma unroll
        for (int mt = 0; mt < 2; mt++) {
            int row = wm*32 + mt*16 + g;
            float nr0 = n1s[row], nr1 = n1s[row+8];
            float rlo = 0.f, rhi = 0.f;
#pragma unroll
            for (int nt = 0; nt < 4; nt++) {
                int col = wn*32 + nt*8 + 2*tig;
                float nc0 = n2s[col], nc1 = n2s[col+1];
                float a00 = 1.f/(1.f + sqrtf(fmaxf(nr0 + nc0 - 2.f*acc[mt][nt][0], 0.f)));
                float a01 = 1.f/(1.f + sqrtf(fmaxf(nr0 + nc1 - 2.f*acc[mt][nt][1], 0.f)));
                float a10 = 1.f/(1.f + sqrtf(fmaxf(nr1 + nc0 - 2.f*acc[mt][nt][2], 0.f)));
                float a11 = 1.f/(1.f + sqrtf(fmaxf(nr1 + nc1 - 2.f*acc[mt][nt][3], 0.f)));
                rlo += a00 + a01;
                rhi += a10 + a11;
                cs0[nt] += a00 + a10;
                cs1[nt] += a01 + a11;
            }
            rlo += __shfl_xor_sync(0xffffffffu, rlo, 1);
            rlo += __shfl_xor_sync(0xffffffffu, rlo, 2);
            rhi += __shfl_xor_sync(0xffffffffu, rhi, 1);
            rhi += __shfl_xor_sync(0xffffffffu, rhi, 2);
            if (tig == 0) {
                rowbuf[wn*64 + row]   = rlo;
                rowbuf[wn*64 + row+8] = rhi;
            }
        }
#pragma unroll
        for (int nt = 0; nt < 4; nt++) {
            float c0 = cs0[nt], c1 = cs1[nt];
            c0 += __shfl_xor_sync(0xffffffffu, c0, 4);
            c0 += __shfl_xor_sync(0xffffffffu, c0, 8);
            c0 += __shfl_xor_sync(0xffffffffu, c0, 16);
            c1 += __shfl_xor_sync(0xffffffffu, c1, 4);
            c1 += __shfl_xor_sync(0xffffffffu, c1, 8);
            c1 += __shfl_xor_sync(0xffffffffu, c1, 16);
            if (g == 0) {
                int col = wn*32 + nt*8 + 2*tig;
                colbuf[wm*SS + col]     = c0;
                colbuf[wm*SS + col + 1] = c1;
            }
        }
        __syncthreads();
        if (tid < 64)
            g_w1[b*SS + h*64 + tid] = rowbuf[tid] + rowbuf[64+tid] + rowbuf[128+tid] + rowbuf[192+tid];
        if (tid < SS)
            atomicAdd(&g_w2[b*SS + tid], colbuf[tid] + colbuf[SS+tid]);
    }
#undef FETCH
#undef STBUF
}

// ---------------- f1=A@W, f2=A^T@W, fp16 mma, 3-stage cp.async, fp16 out ------
#define HPAD 20
#define FBUF2 (128*HPAD + 128*HPAD + 64*HPAD)   // 6400 words per buffer
__global__ __launch_bounds__(256, 2) void k_fgemm(int layer) {
    extern __shared__ float sm[];
    int b = blockIdx.x;
    int n0 = blockIdx.y * 64;
    const __half* Ah  = g_Ah  + (size_t)b*SS*SS;
    const __half* ATh = g_ATh + (size_t)b*SS*SS;
    const __half* Wth = g_Wth + (size_t)layer*320*SS;
    int tid = threadIdx.x;
    int lane = tid & 31, wid = tid >> 5;
    int g = lane >> 2, tig = lane & 3;
    int half = wid >> 2, wm = wid & 3;

#define LOADCH(c, buf) do { \
    uint32_t* base_ = (uint32_t*)sm + (buf)*FBUF2; \
    uint32_t* A1_ = base_; \
    uint32_t* AT_ = base_ + 128*HPAD; \
    uint32_t* Wb_ = AT_ + 128*HPAD; \
    int k0_ = (c)*32; \
    _Pragma("unroll") for (int j = 0; j < 2; j++) { \
        int i = tid + 256*j; int r = i >> 2, q = i & 3; \
        cpasync16(A1_ + r*HPAD + q*4, Ah + r*SS + k0_ + q*8); \
        cpasync16(AT_ + r*HPAD + q*4, ATh + r*SS + k0_ + q*8); \
    } \
    { int r = tid >> 2, q = tid & 3; \
      cpasync16(Wb_ + r*HPAD + q*4, Wth + (n0+r)*SS + k0_ + q*8); } \
    asm volatile("cp.async.commit_group;\n" ::); \
} while (0)

    float acc[2][8][4];
#pragma unroll
    for (int mt = 0; mt < 2; mt++)
#pragma unroll
        for (int nt = 0; nt < 8; nt++)
#pragma unroll
            for (int q = 0; q < 4; q++) acc[mt][nt][q] = 0.f;

    LOADCH(0, 0);
    LOADCH(1, 1);
    for (int c = 0; c < 4; c++) {
        if (c + 2 < 4) {
            LOADCH(c+2, (c+2)%3);
            asm volatile("cp.async.wait_group 2;\n" ::);
        } else if (c + 1 < 4) {
            asm volatile("cp.async.wait_group 1;\n" ::);
        } else {
            asm volatile("cp.async.wait_group 0;\n" ::);
        }
        __syncthreads();
        const uint32_t* Abase = (uint32_t*)sm + (c%3)*FBUF2 + half*128*HPAD;
        const uint32_t* Wb    = (uint32_t*)sm + (c%3)*FBUF2 + 2*128*HPAD;
#pragma unroll
        for (int ks = 0; ks < 2; ks++) {
            int ws = ks*8;
            uint32_t a[2][4], bf[8][2];
#pragma unroll
            for (int mt = 0; mt < 2; mt++) {
                int row = wm*32 + mt*16 + g;
                a[mt][0] = Abase[row*HPAD + ws + tig];
                a[mt][1] = Abase[(row+8)*HPAD + ws + tig];
                a[mt][2] = Abase[row*HPAD + ws + tig + 4];
                a[mt][3] = Abase[(row+8)*HPAD + ws + tig + 4];
            }
#pragma unroll
            for (int nt = 0; nt < 8; nt++) {
                int cn = nt*8 + g;
                bf[nt][0] = Wb[cn*HPAD + ws + tig];
                bf[nt][1] = Wb[cn*HPAD + ws + tig + 4];
            }
#pragma unroll
            for (int mt = 0; mt < 2; mt++)
#pragma unroll
                for (int nt = 0; nt < 8; nt++)
                    MMA_F16(acc[mt][nt], a[mt], bf[nt]);
        }
        __syncthreads();
    }
#undef LOADCH

    __half* out = (half ? g_f2h : g_f1h) + (size_t)b*SS*EE;
#pragma unroll
    for (int mt = 0; mt < 2; mt++) {
        int row = wm*32 + mt*16 + g;
#pragma unroll
        for (int nt = 0; nt < 8; nt++) {
            int col = n0 + nt*8 + 2*tig;
            if (col < EE) {
                *(__half2*)(out + row*EE + col)     = __floats2half2_rn(acc[mt][nt][0], acc[mt][nt][1]);
                *(__half2*)(out + (row+8)*EE + col) = __floats2half2_rn(acc[mt][nt][2], acc[mt][nt][3]);
            }
        }
    }
}

// ---------------- conv 2in->1out 3x3 + tanh + fused mean: column-per-thread ---
__global__ __launch_bounds__(320) void k_conv(const float* __restrict__ cw,
                                              const float* __restrict__ cb,
                                              int layer, int store) {
    extern __shared__ float sm[];
    float* xs = sm;                       // [2][18][302]
    float* w  = xs + 2*(CROWS+2)*(EE+2);  // [18]

    int b = blockIdx.x, ch = blockIdx.y, pair = blockIdx.z;
    int s0 = ch * CROWS;
    const float* X0 = (pair ? g_s2 : g_s1) + b*SS*EE;
    const __half* X1 = (pair ? g_f2h : g_f1h) + (size_t)b*SS*EE;
    float* O = (pair ? g_o2 : g_o1) + b*SS*EE;
    int tid = threadIdx.x;
    if (tid < 18) w[tid] = cw[layer*18 + tid];
    if (tid < 2*(CROWS+2)*2) {
        int c = tid / (2*(CROWS+2));
        int rem = tid % (2*(CROWS+2));
        int j = rem >> 1, side = rem & 1;
        xs[(c*(CROWS+2) + j)*(EE+2) + (side ? EE+1 : 0)] = 0.f;
    }
    // channel 0: s (fp32)
    for (int i = tid; i < (CROWS+2)*(EE/4); i += 320) {
        int j = i / (EE/4), q = i % (EE/4);
        int srow = s0 + j - 1;
        float4 val = make_float4(0.f,0.f,0.f,0.f);
        if (srow >= 0 && srow < SS)
            val = *(const float4*)(X0 + srow*EE + q*4);
        float* dptr = &xs[j*(EE+2) + q*4 + 1];
        dptr[0]=val.x; dptr[1]=val.y; dptr[2]=val.z; dptr[3]=val.w;
    }
    // channel 1: f (fp16 -> fp32)
    for (int i = tid; i < (CROWS+2)*(EE/4); i += 320) {
        int j = i / (EE/4), q = i % (EE/4);
        int srow = s0 + j - 1;
        float4 val = make_float4(0.f,0.f,0.f,0.f);
        if (srow >= 0 && srow < SS) {
            __half2 h0 = *(const __half2*)(X1 + srow*EE + q*4);
            __half2 h1 = *(const __half2*)(X1 + srow*EE + q*4 + 2);
            val = make_float4(__low2float(h0), __high2float(h0),
                              __low2float(h1), __high2float(h1));
        }
        float* dptr = &xs[((CROWS+2) + j)*(EE+2) + q*4 + 1];
        dptr[0]=val.x; dptr[1]=val.y; dptr[2]=val.z; dptr[3]=val.w;
    }
    __syncthreads();
    if (tid < EE) {
        int e = tid;
        float bias = cb[layer];
        const float* xs0 = xs;
        const float* xs1 = xs + (CROWS+2)*(EE+2);
        float sv[3][3], fv[3][3];
#pragma unroll
        for (int kh = 0; kh < 2; kh++)
#pragma unroll
            for (int kw = 0; kw < 3; kw++) {
                sv[kh][kw] = xs0[kh*(EE+2) + e + kw];
                fv[kh][kw] = xs1[kh*(EE+2) + e + kw];
            }
        float colsum = 0.f;
#pragma unroll 4
        for (int r = 0; r < CROWS; r++) {
#pragma unroll
            for (int kw = 0; kw < 3; kw++) {
                sv[2][kw] = xs0[(r+2)*(EE+2) + e + kw];
                fv[2][kw] = xs1[(r+2)*(EE+2) + e + kw];
            }
            float acc = bias;
#pragma unroll
            for (int kh = 0; kh < 3; kh++)
#pragma unroll
                for (int kw = 0; kw < 3; kw++)
                    acc += w[kh*3+kw]*sv[kh][kw] + w[9+kh*3+kw]*fv[kh][kw];
            float t = tanh_fast(acc);
            if (store) O[(s0+r)*EE + e] = t;
            colsum += t;
#pragma unroll
            for (int kw = 0; kw < 3; kw++) {
                sv[0][kw] = sv[1][kw]; sv[1][kw] = sv[2][kw];
                fv[0][kw] = fv[1][kw]; fv[1][kw] = fv[2][kw];
            }
        }
        int slot = (pair ? 4 : 1) + layer;
        atomicAdd(&g_x[b*FCIN + slot*EE + e], colsum*(1.f/SS));
    }
}

// ---------------- weighted avg-pool3 + residual update, float4 ----------------
__global__ __launch_bounds__(96) void k_pool() {
    int b = blockIdx.x, ch = blockIdx.y, pair = blockIdx.z;
    int s0 = ch * CROWS;
    const float* O = (pair ? g_o2 : g_o1) + b*SS*EE;
    float* Sx = (pair ? g_s2 : g_s1) + b*SS*EE;
    const float* wv = (pair ? g_w2 : g_w1) + b*SS;
    __shared__ float w[CROWS+2];
    if (threadIdx.x < CROWS+2) {
        int s = s0 + (int)threadIdx.x - 1;
        w[threadIdx.x] = (s >= 0 && s < SS) ? wv[s] : 0.f;
    }
    __syncthreads();
    int t = threadIdx.x;
    if (t >= 75) return;
    int e = t*4;
    float4 a = make_float4(0.f,0.f,0.f,0.f);
    if (s0 > 0) {
        float4 v = *(const float4*)(O + (s0-1)*EE + e);
        a = make_float4(v.x*w[0], v.y*w[0], v.z*w[0], v.w*w[0]);
    }
    float4 v0 = *(const float4*)(O + s0*EE + e);
    float4 bm = make_float4(v0.x*w[1], v0.y*w[1], v0.z*w[1], v0.w*w[1]);
#pragma unroll
    for (int i = 0; i < CROWS; i++) {
        int s = s0 + i;
        float4 cn = make_float4(0.f,0.f,0.f,0.f);
        if (s+1 < SS) {
            float4 v = *(const float4*)(O + (s+1)*EE + e);
            float ww = w[i+2];
            cn = make_float4(v.x*ww, v.y*ww, v.z*ww, v.w*ww);
        }
        float4 sx = *(float4*)(Sx + s*EE + e);
        sx.x += (a.x + bm.x + cn.x) * (1.f/3.f);
        sx.y += (a.y + bm.y + cn.y) * (1.f/3.f);
        sx.z += (a.z + bm.z + cn.z) * (1.f/3.f);
        sx.w += (a.w + bm.w + cn.w) * (1.f/3.f);
        *(float4*)(Sx + s*EE + e) = sx;
        a = bm; bm = cn;
    }
}

// ---------------- fc1 GEMM: [512,1800] @ [1800,300]^T -> g_h ----------------
__global__ __launch_bounds__(256) void k_fc1(const float* __restrict__ fw) {
    int m0 = blockIdx.x * 64, n0 = blockIdx.y * 64;
    __shared__ float Xs[8][68];
    __shared__ float Ws2[8][68];
    int tid = threadIdx.x, ty = tid >> 4, tx = tid & 15;
    float acc[4][4];
#pragma unroll
    for (int u = 0; u < 4; u++)
#pragma unroll
        for (int v = 0; v < 4; v++) acc[u][v] = 0.f;

    for (int k0 = 0; k0 < FCIN; k0 += 8) {
        __syncthreads();
#pragma unroll 2
        for (int i = tid; i < 512; i += 256) {
            int r = i >> 3, kk = i & 7;
            Xs[kk][r] = g_x[(m0 + r)*FCIN + k0 + kk];
            int n = n0 + r;
            Ws2[kk][r] = (n < HH) ? fw[n*FCIN + k0 + kk] : 0.f;
        }
        __syncthreads();
#pragma unroll
        for (int kk = 0; kk < 8; kk++) {
            float4 xa = *(const float4*)&Xs[kk][ty*4];
            float4 wb = *(const float4*)&Ws2[kk][tx*4];
            float xv[4] = {xa.x, xa.y, xa.z, xa.w};
            float wvv[4] = {wb.x, wb.y, wb.z, wb.w};
#pragma unroll
            for (int u = 0; u < 4; u++)
#pragma unroll
                for (int v = 0; v < 4; v++) acc[u][v] += xv[u]*wvv[v];
        }
    }
#pragma unroll
    for (int u = 0; u < 4; u++) {
        int m = m0 + ty*4 + u;
#pragma unroll
        for (int v = 0; v < 4; v++) {
            int n = n0 + tx*4 + v;
            if (n < HH) g_h[m*HH + n] = acc[u][v];
        }
    }
}

// ---------------- LN + relu + fc2 + softmax ----------------
__device__ __forceinline__ float block_reduce512(float v, float* red) {
    int tid = threadIdx.x;
    red[tid] = v;
    __syncthreads();
    for (int off = 256; off > 0; off >>= 1) {
        if (tid < off) red[tid] += red[tid + off];
        __syncthreads();
    }
    float r = red[0];
    __syncthreads();
    return r;
}

__global__ __launch_bounds__(512) void k_head(const float* __restrict__ fc1b,
                                              const float* __restrict__ lng,
                                              const float* __restrict__ lnb,
                                              const float* __restrict__ fc2w,
                                              const float* __restrict__ fc2b,
                                              float* __restrict__ out) {
    int b = blockIdx.x, tid = threadIdx.x;
    __shared__ float red[512];
    bool act = tid < HH;
    float h = act ? (g_h[b*HH + tid] + fc1b[tid]) : 0.f;
    float mu = block_reduce512(h, red) * (1.f/HH);
    float d = act ? (h - mu) : 0.f;
    float var = block_reduce512(d*d, red) * (1.f/HH);
    float hn = 0.f;
    if (act) {
        hn = d * rsqrtf(var + 1e-5f) * lng[tid] + lnb[tid];
        hn = fmaxf(hn, 0.f);
    }
    float o0 = block_reduce512(act ? hn*fc2w[tid]      : 0.f, red);
    float o1 = block_reduce512(act ? hn*fc2w[HH + tid] : 0.f, red);
    if (tid == 0) {
        o0 += fc2b[0];
        o1 += fc2b[1];
        out[b*2 + 0] = o0;
        out[b*2 + 1] = o1;
        float m = fmaxf(o0, o1);
        float e0 = expf(o0 - m), e1 = expf(o1 - m);
        float inv = 1.f/(e0 + e1);
        out[BB*2 + b*2 + 0] = e0*inv;
        out[BB*2 + b*2 + 1] = e1*inv;
    }
}

// ---------------- launch ----------------
extern "C" void kernel_launch(void* const* d_in, const int* in_sizes, int n_in,
                              void* d_out, int out_size) {
    (void)in_sizes; (void)n_in; (void)out_size;
    const int*   seq1 = (const int*)d_in[0];
    const int*   seq2 = (const int*)d_in[1];
    const float* emb  = (const float*)d_in[2];
    const float* W    = (const float*)d_in[3];
    const float* cw   = (const float*)d_in[4];
    const float* cb   = (const float*)d_in[5];
    const float* fc1w = (const float*)d_in[6];
    const float* fc1b = (const float*)d_in[7];
    const float* lng  = (const float*)d_in[8];
    const float* lnb  = (const float*)d_in[9];
    const float* fc2w = (const float*)d_in[10];
    const float* fc2b = (const float*)d_in[11];
    float* out = (float*)d_out;

    const int SM_MATCH = (2*64*MPAD + 2*SS*MPAD + 64 + SS + 4*64 + 2*SS) * 4;  // ~33.5KB
    const int SM_FGEMM = 3*FBUF2*4;                                             // ~76.8KB
    const int SM_CONV  = (2*(CROWS+2)*(EE+2) + 18) * 4;                         // ~43.6KB

    cudaFuncSetAttribute(k_match, cudaFuncAttributeMaxDynamicSharedMemorySize, SM_MATCH);
    cudaFuncSetAttribute(k_fgemm, cudaFuncAttributeMaxDynamicSharedMemorySize, SM_FGEMM);
    cudaFuncSetAttribute(k_conv,  cudaFuncAttributeMaxDynamicSharedMemorySize, SM_CONV);

    k_wprep<<<dim3(320, LL), 128>>>(W);
    k_gather<<<BB, 256>>>(seq1, seq2, emb);
    for (int l = 0; l < LL; l++) {
        int last = (l == LL-1);
        k_match<<<dim3(BB, 2), 256, SM_MATCH>>>(0, l);
        k_fgemm<<<dim3(BB, 5), 256, SM_FGEMM>>>(l);
        k_conv<<<dim3(BB, 8, 2), 320, SM_CONV>>>(cw, cb, l, last ? 0 : 1);
        if (!last) {
            k_match<<<dim3(BB, 2), 256, SM_MATCH>>>(1, l);
            k_pool<<<dim3(BB, 8, 2), 96>>>();
        }
    }
    k_fc1<<<dim3(8, 5), 256>>>(fc1w);
    k_head<<<BB, 512>>>(fc1b, lng, lnb, fc2w, fc2b, out);
}

// round 15
// speedup vs baseline: 1.6680x; 1.0194x over previous
#include <cuda_runtime.h>
#include <cuda_fp16.h>
#include <math.h>
#include <stdint.h>

#define BB 512
#define SS 128
#define EE 300
#define LL 2
#define HH 300
#define FCIN 1800   // E*(1+L)*2
#define CROWS 16

// ---------------- device scratch (no allocation allowed) ----------------
__device__ float g_s1[BB*SS*EE];
__device__ float g_s2[BB*SS*EE];
__device__ __half g_f1h[BB*SS*EE];
__device__ __half g_f2h[BB*SS*EE];
__device__ __half g_o1h[BB*SS*EE];
__device__ __half g_o2h[BB*SS*EE];
__device__ __half g_Ah [BB*SS*SS];   // A  fp16
__device__ __half g_ATh[BB*SS*SS];   // A^T fp16
__device__ __half g_Wth[LL*320*SS];  // W^T fp16 [l][n][k], zero-pad n>=300
__device__ float g_w1[BB*SS];
__device__ float g_w2[BB*SS];
__device__ float g_v1[BB*SS];
__device__ float g_v2[BB*SS];
__device__ float g_x [BB*FCIN];
__device__ float g_h [BB*HH];

__device__ __forceinline__ float tanh_fast(float x) {
    float r; asm("tanh.approx.f32 %0, %1;" : "=f"(r) : "f"(x)); return r;
}
__device__ __forceinline__ uint32_t pack_h2(float a, float b) {
    __half2 h = __floats2half2_rn(a, b);
    return *(uint32_t*)&h;
}
__device__ __forceinline__ float4 ld4h(const __half* p) {
    uint2 u = *(const uint2*)p;
    __half2 h0 = *(__half2*)&u.x;
    __half2 h1 = *(__half2*)&u.y;
    return make_float4(__low2float(h0), __high2float(h0),
                       __low2float(h1), __high2float(h1));
}
__device__ __forceinline__ void cpasync16(void* dst, const void* src) {
    uint32_t d = (uint32_t)__cvta_generic_to_shared(dst);
    asm volatile("cp.async.ca.shared.global [%0], [%1], 16;\n" :: "r"(d), "l"(src));
}
#define MMA_F16(C, A, B) \
    asm volatile("mma.sync.aligned.m16n8k16.row.col.f32.f16.f16.f32 " \
        "{%0,%1,%2,%3}, {%4,%5,%6,%7}, {%8,%9}, {%0,%1,%2,%3};" \
        : "+f"((C)[0]), "+f"((C)[1]), "+f"((C)[2]), "+f"((C)[3]) \
        : "r"((A)[0]), "r"((A)[1]), "r"((A)[2]), "r"((A)[3]), \
          "r"((B)[0]), "r"((B)[1]))

// ---------------- W prep: g_Wth[l][n][k] = fp16(W[l][k][n]) ----------------
__global__ void k_wprep(const float* __restrict__ W) {
    int n = blockIdx.x, l = blockIdx.y, k = threadIdx.x;
    float v = 0.f;
    if (n < EE) v = W[(size_t)l*SS*EE + k*EE + n];
    g_Wth[(l*320 + n)*SS + k] = __float2half(v);
}

// ---------------- embedding gather + masks + fused mean(slot0) ----------------
__global__ __launch_bounds__(256) void k_gather(const int* __restrict__ seq1,
                                                const int* __restrict__ seq2,
                                                const float* __restrict__ emb) {
    __shared__ float msum[2][EE];
    int b = blockIdx.x;
    int tid = threadIdx.x;
    int warp = tid >> 5, lane = tid & 31;
    for (int i = tid; i < 2*EE; i += 256) ((float*)msum)[i] = 0.f;
    for (int i = tid; i < SS; i += 256) {
        g_v1[b*SS+i] = (seq1[b*SS+i] != 0) ? 1.f : 0.f;
        g_v2[b*SS+i] = (seq2[b*SS+i] != 0) ? 1.f : 0.f;
    }
    __syncthreads();
    int sel = warp & 1;
    float4 acc[3];
#pragma unroll
    for (int jj = 0; jj < 3; jj++) acc[jj] = make_float4(0.f,0.f,0.f,0.f);
    for (int idx = warp; idx < 2*SS; idx += 8) {
        int s = idx >> 1;
        int tok = sel ? seq2[b*SS+s] : seq1[b*SS+s];
        const float4* src = (const float4*)(emb + (long)tok*EE);
        float4* dst = (float4*)((sel ? g_s2 : g_s1) + (b*SS+s)*EE);
#pragma unroll
        for (int jj = 0; jj < 3; jj++) {
            int j = lane + 32*jj;
            if (j < EE/4) {
                float4 v = src[j];
                dst[j] = v;
                acc[jj].x += v.x; acc[jj].y += v.y; acc[jj].z += v.z; acc[jj].w += v.w;
            }
        }
    }
#pragma unroll
    for (int jj = 0; jj < 3; jj++) {
        int j = lane + 32*jj;
        if (j < EE/4) {
            atomicAdd(&msum[sel][4*j+0], acc[jj].x);
            atomicAdd(&msum[sel][4*j+1], acc[jj].y);
            atomicAdd(&msum[sel][4*j+2], acc[jj].z);
            atomicAdd(&msum[sel][4*j+3], acc[jj].w);
        }
    }
    __syncthreads();
    for (int e = tid; e < EE; e += 256) {
        g_x[b*FCIN + e]        = msum[0][e]*(1.f/SS);
        g_x[b*FCIN + 3*EE + e] = msum[1][e]*(1.f/SS);
    }
}

// ---------------- match-score, fp16 tensor cores, SPLIT grid (B,2) ------------
// mode=0: inputs s (fp32) -> store A/AT fp16 + zero g_w2/g_x slots
// mode=1: inputs o (fp16) -> w1 direct, w2 atomicAdd
#define MPAD 20     // half2 words per 32-k chunk (16) + pad 4
#define MCH 10      // ceil(300/32)
__global__ __launch_bounds__(256, 2) void k_match(int mode, int layer) {
    extern __shared__ float sm[];
    uint32_t* Xs = (uint32_t*)sm;           // [2][64][20] half2 words
    uint32_t* Ys = Xs + 2*64*MPAD;          // [2][128][20]
    float* n1s = (float*)(Ys + 2*SS*MPAD);  // [64]
    float* n2s = n1s + 64;                  // [128]
    float* rowbuf = n2s + SS;               // [4][64]
    float* colbuf = rowbuf + 4*64;          // [2][128]

    int b = blockIdx.x, h = blockIdx.y;
    int tid = threadIdx.x;
    int lane = tid & 31, wid = tid >> 5;
    int g = lane >> 2, tig = lane & 3;
    int wm = wid & 1, wn = wid >> 1;

    int rX = tid >> 2, qx = tid & 3;
    int rY = tid >> 1, hy = tid & 1;
    const float* Xr = g_s1 + b*SS*EE + (h*64 + rX)*EE + qx*8;
    const float* Yr = g_s2 + b*SS*EE + rY*EE + hy*16;
    const __half* Xrh = g_o1h + (size_t)b*SS*EE + (h*64 + rX)*EE + qx*8;
    const __half* Yrh = g_o2h + (size_t)b*SS*EE + rY*EE + hy*16;
    float mvx = g_v1[b*SS + h*64 + rX];
    float mvy = g_v2[b*SS + rY];
    float nx = 0.f, ny = 0.f;
    float4 vx[2], vy[4];

#define FETCH32(c) do { \
    int kb = (c)*32; \
    _Pragma("unroll") for (int j = 0; j < 2; j++) { \
        int k = kb + qx*8 + 4*j; \
        vx[j] = (k < EE) ? *(const float4*)(Xr + kb + 4*j) : make_float4(0.f,0.f,0.f,0.f); \
    } \
    _Pragma("unroll") for (int j = 0; j < 4; j++) { \
        int k = kb + hy*16 + 4*j; \
        vy[j] = (k < EE) ? *(const float4*)(Yr + kb + 4*j) : make_float4(0.f,0.f,0.f,0.f); \
    } } while(0)

#define FETCH16(c) do { \
    int kb = (c)*32; \
    _Pragma("unroll") for (int j = 0; j < 2; j++) { \
        int k = kb + qx*8 + 4*j; \
        vx[j] = (k < EE) ? ld4h(Xrh + kb + 4*j) : make_float4(0.f,0.f,0.f,0.f); \
    } \
    _Pragma("unroll") for (int j = 0; j < 4; j++) { \
        int k = kb + hy*16 + 4*j; \
        vy[j] = (k < EE) ? ld4h(Yrh + kb + 4*j) : make_float4(0.f,0.f,0.f,0.f); \
    } } while(0)

#define STBUF(buf) do { \
    uint32_t* xd = Xs + (buf)*64*MPAD + rX*MPAD + qx*4; \
    uint32_t* yd = Ys + (buf)*SS*MPAD + rY*MPAD + hy*8; \
    _Pragma("unroll") for (int j = 0; j < 2; j++) { \
        float x0=vx[j].x*mvx, x1=vx[j].y*mvx, x2=vx[j].z*mvx, x3=vx[j].w*mvx; \
        nx += x0*x0+x1*x1+x2*x2+x3*x3; \
        xd[2*j+0] = pack_h2(x0, x1); \
        xd[2*j+1] = pack_h2(x2, x3); \
    } \
    _Pragma("unroll") for (int j = 0; j < 4; j++) { \
        float y0=vy[j].x*mvy, y1=vy[j].y*mvy, y2=vy[j].z*mvy, y3=vy[j].w*mvy; \
        ny += y0*y0+y1*y1+y2*y2+y3*y3; \
        yd[2*j+0] = pack_h2(y0, y1); \
        yd[2*j+1] = pack_h2(y2, y3); \
    } } while(0)

    float acc[2][4][4];
#pragma unroll
    for (int mt = 0; mt < 2; mt++)
#pragma unroll
        for (int nt = 0; nt < 4; nt++)
#pragma unroll
            for (int q = 0; q < 4; q++) acc[mt][nt][q] = 0.f;

    if (mode == 0) FETCH32(0); else FETCH16(0);
    STBUF(0);
    __syncthreads();

    for (int c = 0; c < MCH; c++) {
        int cur = c & 1;
        if (c + 1 < MCH) { if (mode == 0) FETCH32(c+1); else FETCH16(c+1); }
        const uint32_t* xb = Xs + cur*64*MPAD;
        const uint32_t* yb = Ys + cur*SS*MPAD;
#pragma unroll
        for (int ks = 0; ks < 2; ks++) {
            int ws = ks*8;
            uint32_t a[2][4], bf[4][2];
#pragma unroll
            for (int mt = 0; mt < 2; mt++) {
                int row = wm*32 + mt*16 + g;
                a[mt][0] = xb[row*MPAD + ws + tig];
                a[mt][1] = xb[(row+8)*MPAD + ws + tig];
                a[mt][2] = xb[row*MPAD + ws + tig + 4];
                a[mt][3] = xb[(row+8)*MPAD + ws + tig + 4];
            }
#pragma unroll
            for (int nt = 0; nt < 4; nt++) {
                int cr = wn*32 + nt*8 + g;
                bf[nt][0] = yb[cr*MPAD + ws + tig];
                bf[nt][1] = yb[cr*MPAD + ws + tig + 4];
            }
#pragma unroll
            for (int mt = 0; mt < 2; mt++)
#pragma unroll
                for (int nt = 0; nt < 4; nt++)
                    MMA_F16(acc[mt][nt], a[mt], bf[nt]);
        }
        if (c + 1 < MCH) STBUF(cur ^ 1);
        __syncthreads();
    }

    nx += __shfl_xor_sync(0xffffffffu, nx, 1);
    nx += __shfl_xor_sync(0xffffffffu, nx, 2);
    if (qx == 0) n1s[rX] = nx;
    ny += __shfl_xor_sync(0xffffffffu, ny, 1);
    if (hy == 0) n2s[rY] = ny;
    __syncthreads();

    if (mode == 0) {
        __half* Ao = g_Ah + (size_t)b*SS*SS + h*64*SS;
        __half* ts = (__half*)sm;   // transpose stage [128 cols][68 rows pad]
#pragma unroll
        for (int mt = 0; mt < 2; mt++) {
            int row = wm*32 + mt*16 + g;
            float nr0 = n1s[row], nr1 = n1s[row+8];
#pragma unroll
            for (int nt = 0; nt < 4; nt++) {
                int col = wn*32 + nt*8 + 2*tig;
                float nc0 = n2s[col], nc1 = n2s[col+1];
                float a00 = 1.f/(1.f + sqrtf(fmaxf(nr0 + nc0 - 2.f*acc[mt][nt][0], 0.f)));
                float a01 = 1.f/(1.f + sqrtf(fmaxf(nr0 + nc1 - 2.f*acc[mt][nt][1], 0.f)));
                float a10 = 1.f/(1.f + sqrtf(fmaxf(nr1 + nc0 - 2.f*acc[mt][nt][2], 0.f)));
                float a11 = 1.f/(1.f + sqrtf(fmaxf(nr1 + nc1 - 2.f*acc[mt][nt][3], 0.f)));
                *(__half2*)(Ao + row*SS + col)     = __floats2half2_rn(a00, a01);
                *(__half2*)(Ao + (row+8)*SS + col) = __floats2half2_rn(a10, a11);
                ts[(col+0)*68 + row]   = __float2half(a00);
                ts[(col+1)*68 + row]   = __float2half(a01);
                ts[(col+0)*68 + row+8] = __float2half(a10);
                ts[(col+1)*68 + row+8] = __float2half(a11);
            }
        }
        __syncthreads();
        __half* ATo = g_ATh + (size_t)b*SS*SS + h*64;
        for (int i = tid; i < 128*32; i += 256) {
            int col = i >> 5, rw = i & 31;
            __half2 v = *(__half2*)&ts[col*68 + 2*rw];
            *(__half2*)(ATo + col*SS + 2*rw) = v;
        }
        if (h == 0 && tid < SS) g_w2[b*SS + tid] = 0.f;
        int slot = (h ? 4 : 1) + layer;
        for (int e = tid; e < EE; e += 256) g_x[b*FCIN + slot*EE + e] = 0.f;
    } else {
        float cs0[4], cs1[4];
#pragma unroll
        for (int nt = 0; nt < 4; nt++) { cs0[nt] = 0.f; cs1[nt] = 0.f; }
#pragma unroll
        for (int mt = 0; mt < 2; mt++) {
            int row = wm*32 + mt*16 + g;
            float nr0 = n1s[row], nr1 = n1s[row+8];
            float rlo = 0.f, rhi = 0.f;
#pragma unroll
            for (int nt = 0; nt < 4; nt++) {
                int col = wn*32 + nt*8 + 2*tig;
                float nc0 = n2s[col], nc1 = n2s[col+1];
                float a00 = 1.f/(1.f + sqrtf(fmaxf(nr0 + nc0 - 2.f*acc[mt][nt][0], 0.f)));
                float a01 = 1.f/(1.f + sqrtf(fmaxf(nr0 + nc1 - 2.f*acc[mt][nt][1], 0.f)));
                float a10 = 1.f/(1.f + sqrtf(fmaxf(nr1 + nc0 - 2.f*acc[mt][nt][2], 0.f)));
                float a11 = 1.f/(1.f + sqrtf(fmaxf(nr1 + nc1 - 2.f*acc[mt][nt][3], 0.f)));
                rlo += a00 + a01;
                rhi += a10 + a11;
                cs0[nt] += a00 + a10;
                cs1[nt] += a01 + a11;
            }
            rlo += __shfl_xor_sync(0xffffffffu, rlo, 1);
            rlo += __shfl_xor_sync(0xffffffffu, rlo, 2);
            rhi += __shfl_xor_sync(0xffffffffu, rhi, 1);
            rhi += __shfl_xor_sync(0xffffffffu, rhi, 2);
            if (tig == 0) {
                rowbuf[wn*64 + row]   = rlo;
                rowbuf[wn*64 + row+8] = rhi;
            }
        }
#pragma unroll
        for (int nt = 0; nt < 4; nt++) {
            float c0 = cs0[nt], c1 = cs1[nt];
            c0 += __shfl_xor_sync(0xffffffffu, c0, 4);
            c0 += __shfl_xor_sync(0xffffffffu, c0, 8);
            c0 += __shfl_xor_sync(0xffffffffu, c0, 16);
            c1 += __shfl_xor_sync(0xffffffffu, c1, 4);
            c1 += __shfl_xor_sync(0xffffffffu, c1, 8);
            c1 += __shfl_xor_sync(0xffffffffu, c1, 16);
            if (g == 0) {
                int col = wn*32 + nt*8 + 2*tig;
                colbuf[wm*SS + col]     = c0;
                colbuf[wm*SS + col + 1] = c1;
            }
        }
        __syncthreads();
        if (tid < 64)
            g_w1[b*SS + h*64 + tid] = rowbuf[tid] + rowbuf[64+tid] + rowbuf[128+tid] + rowbuf[192+tid];
        if (tid < SS)
            atomicAdd(&g_w2[b*SS + tid], colbuf[tid] + colbuf[SS+tid]);
    }
#undef FETCH32
#undef FETCH16
#undef STBUF
}

// ---------------- f1=A@W, f2=A^T@W, fp16 mma, 3-stage cp.async, fp16 out ------
#define HPAD 20
#define FBUF2 (128*HPAD + 128*HPAD + 64*HPAD)   // 6400 words per buffer
__global__ __launch_bounds__(256, 2) void k_fgemm(int layer) {
    extern __shared__ float sm[];
    int b = blockIdx.x;
    int n0 = blockIdx.y * 64;
    const __half* Ah  = g_Ah  + (size_t)b*SS*SS;
    const __half* ATh = g_ATh + (size_t)b*SS*SS;
    const __half* Wth = g_Wth + (size_t)layer*320*SS;
    int tid = threadIdx.x;
    int lane = tid & 31, wid = tid >> 5;
    int g = lane >> 2, tig = lane & 3;
    int half = wid >> 2, wm = wid & 3;

#define LOADCH(c, buf) do { \
    uint32_t* base_ = (uint32_t*)sm + (buf)*FBUF2; \
    uint32_t* A1_ = base_; \
    uint32_t* AT_ = base_ + 128*HPAD; \
    uint32_t* Wb_ = AT_ + 128*HPAD; \
    int k0_ = (c)*32; \
    _Pragma("unroll") for (int j = 0; j < 2; j++) { \
        int i = tid + 256*j; int r = i >> 2, q = i & 3; \
        cpasync16(A1_ + r*HPAD + q*4, Ah + r*SS + k0_ + q*8); \
        cpasync16(AT_ + r*HPAD + q*4, ATh + r*SS + k0_ + q*8); \
    } \
    { int r = tid >> 2, q = tid & 3; \
      cpasync16(Wb_ + r*HPAD + q*4, Wth + (n0+r)*SS + k0_ + q*8); } \
    asm volatile("cp.async.commit_group;\n" ::); \
} while (0)

    float acc[2][8][4];
#pragma unroll
    for (int mt = 0; mt < 2; mt++)
#pragma unroll
        for (int nt = 0; nt < 8; nt++)
#pragma unroll
            for (int q = 0; q < 4; q++) acc[mt][nt][q] = 0.f;

    LOADCH(0, 0);
    LOADCH(1, 1);
    for (int c = 0; c < 4; c++) {
        if (c + 2 < 4) {
            LOADCH(c+2, (c+2)%3);
            asm volatile("cp.async.wait_group 2;\n" ::);
        } else if (c + 1 < 4) {
            asm volatile("cp.async.wait_group 1;\n" ::);
        } else {
            asm volatile("cp.async.wait_group 0;\n" ::);
        }
        __syncthreads();
        const uint32_t* Abase = (uint32_t*)sm + (c%3)*FBUF2 + half*128*HPAD;
        const uint32_t* Wb    = (uint32_t*)sm + (c%3)*FBUF2 + 2*128*HPAD;
#pragma unroll
        for (int ks = 0; ks < 2; ks++) {
            int ws = ks*8;
            uint32_t a[2][4], bf[8][2];
#pragma unroll
            for (int mt = 0; mt < 2; mt++) {
                int row = wm*32 + mt*16 + g;
                a[mt][0] = Abase[row*HPAD + ws + tig];
                a[mt][1] = Abase[(row+8)*HPAD + ws + tig];
                a[mt][2] = Abase[row*HPAD + ws + tig + 4];
                a[mt][3] = Abase[(row+8)*HPAD + ws + tig + 4];
            }
#pragma unroll
            for (int nt = 0; nt < 8; nt++) {
                int cn = nt*8 + g;
                bf[nt][0] = Wb[cn*HPAD + ws + tig];
                bf[nt][1] = Wb[cn*HPAD + ws + tig + 4];
            }
#pragma unroll
            for (int mt = 0; mt < 2; mt++)
#pragma unroll
                for (int nt = 0; nt < 8; nt++)
                    MMA_F16(acc[mt][nt], a[mt], bf[nt]);
        }
        __syncthreads();
    }
#undef LOADCH

    __half* out = (half ? g_f2h : g_f1h) + (size_t)b*SS*EE;
#pragma unroll
    for (int mt = 0; mt < 2; mt++) {
        int row = wm*32 + mt*16 + g;
#pragma unroll
        for (int nt = 0; nt < 8; nt++) {
            int col = n0 + nt*8 + 2*tig;
            if (col < EE) {
                *(__half2*)(out + row*EE + col)     = __floats2half2_rn(acc[mt][nt][0], acc[mt][nt][1]);
                *(__half2*)(out + (row+8)*EE + col) = __floats2half2_rn(acc[mt][nt][2], acc[mt][nt][3]);
            }
        }
    }
}

// ---------------- conv 2in->1out 3x3 + tanh + fused mean: column-per-thread ---
__global__ __launch_bounds__(320) void k_conv(const float* __restrict__ cw,
                                              const float* __restrict__ cb,
                                              int layer, int store) {
    extern __shared__ float sm[];
    float* xs = sm;                       // [2][18][302]
    float* w  = xs + 2*(CROWS+2)*(EE+2);  // [18]

    int b = blockIdx.x, ch = blockIdx.y, pair = blockIdx.z;
    int s0 = ch * CROWS;
    const float* X0 = (pair ? g_s2 : g_s1) + b*SS*EE;
    const __half* X1 = (pair ? g_f2h : g_f1h) + (size_t)b*SS*EE;
    __half* O = (pair ? g_o2h : g_o1h) + (size_t)b*SS*EE;
    int tid = threadIdx.x;
    if (tid < 18) w[tid] = cw[layer*18 + tid];
    if (tid < 2*(CROWS+2)*2) {
        int c = tid / (2*(CROWS+2));
        int rem = tid % (2*(CROWS+2));
        int j = rem >> 1, side = rem & 1;
        xs[(c*(CROWS+2) + j)*(EE+2) + (side ? EE+1 : 0)] = 0.f;
    }
    // channel 0: s (fp32)
    for (int i = tid; i < (CROWS+2)*(EE/4); i += 320) {
        int j = i / (EE/4), q = i % (EE/4);
        int srow = s0 + j - 1;
        float4 val = make_float4(0.f,0.f,0.f,0.f);
        if (srow >= 0 && srow < SS)
            val = *(const float4*)(X0 + srow*EE + q*4);
        float* dptr = &xs[j*(EE+2) + q*4 + 1];
        dptr[0]=val.x; dptr[1]=val.y; dptr[2]=val.z; dptr[3]=val.w;
    }
    // channel 1: f (fp16 -> fp32)
    for (int i = tid; i < (CROWS+2)*(EE/4); i += 320) {
        int j = i / (EE/4), q = i % (EE/4);
        int srow = s0 + j - 1;
        float4 val = make_float4(0.f,0.f,0.f,0.f);
        if (srow >= 0 && srow < SS)
            val = ld4h(X1 + srow*EE + q*4);
        float* dptr = &xs[((CROWS+2) + j)*(EE+2) + q*4 + 1];
        dptr[0]=val.x; dptr[1]=val.y; dptr[2]=val.z; dptr[3]=val.w;
    }
    __syncthreads();
    if (tid < EE) {
        int e = tid;
        float bias = cb[layer];
        const float* xs0 = xs;
        const float* xs1 = xs + (CROWS+2)*(EE+2);
        float sv[3][3], fv[3][3];
#pragma unroll
        for (int kh = 0; kh < 2; kh++)
#pragma unroll
            for (int kw = 0; kw < 3; kw++) {
                sv[kh][kw] = xs0[kh*(EE+2) + e + kw];
                fv[kh][kw] = xs1[kh*(EE+2) + e + kw];
            }
        float colsum = 0.f;
#pragma unroll 4
        for (int r = 0; r < CROWS; r++) {
#pragma unroll
            for (int kw = 0; kw < 3; kw++) {
                sv[2][kw] = xs0[(r+2)*(EE+2) + e + kw];
                fv[2][kw] = xs1[(r+2)*(EE+2) + e + kw];
            }
            float acc = bias;
#pragma unroll
            for (int kh = 0; kh < 3; kh++)
#pragma unroll
                for (int kw = 0; kw < 3; kw++)
                    acc += w[kh*3+kw]*sv[kh][kw] + w[9+kh*3+kw]*fv[kh][kw];
            float t = tanh_fast(acc);
            if (store) O[(s0+r)*EE + e] = __float2half(t);
            colsum += t;
#pragma unroll
            for (int kw = 0; kw < 3; kw++) {
                sv[0][kw] = sv[1][kw]; sv[1][kw] = sv[2][kw];
                fv[0][kw] = fv[1][kw]; fv[1][kw] = fv[2][kw];
            }
        }
        int slot = (pair ? 4 : 1) + layer;
        atomicAdd(&g_x[b*FCIN + slot*EE + e], colsum*(1.f/SS));
    }
}

// ---------------- weighted avg-pool3 + residual update, fp16 o ----------------
__global__ __launch_bounds__(96) void k_pool() {
    int b = blockIdx.x, ch = blockIdx.y, pair = blockIdx.z;
    int s0 = ch * CROWS;
    const __half* O = (pair ? g_o2h : g_o1h) + (size_t)b*SS*EE;
    float* Sx = (pair ? g_s2 : g_s1) + b*SS*EE;
    const float* wv = (pair ? g_w2 : g_w1) + b*SS;
    __shared__ float w[CROWS+2];
    if (threadIdx.x < CROWS+2) {
        int s = s0 + (int)threadIdx.x - 1;
        w[threadIdx.x] = (s >= 0 && s < SS) ? wv[s] : 0.f;
    }
    __syncthreads();
    int t = threadIdx.x;
    if (t >= 75) return;
    int e = t*4;
    float4 a = make_float4(0.f,0.f,0.f,0.f);
    if (s0 > 0) {
        float4 v = ld4h(O + (s0-1)*EE + e);
        a = make_float4(v.x*w[0], v.y*w[0], v.z*w[0], v.w*w[0]);
    }
    float4 v0 = ld4h(O + s0*EE + e);
    float4 bm = make_float4(v0.x*w[1], v0.y*w[1], v0.z*w[1], v0.w*w[1]);
#pragma unroll
    for (int i = 0; i < CROWS; i++) {
        int s = s0 + i;
        float4 cn = make_float4(0.f,0.f,0.f,0.f);
        if (s+1 < SS) {
            float4 v = ld4h(O + (s+1)*EE + e);
            float ww = w[i+2];
            cn = make_float4(v.x*ww, v.y*ww, v.z*ww, v.w*ww);
        }
        float4 sx = *(float4*)(Sx + s*EE + e);
        sx.x += (a.x + bm.x + cn.x) * (1.f/3.f);
        sx.y += (a.y + bm.y + cn.y) * (1.f/3.f);
        sx.z += (a.z + bm.z + cn.z) * (1.f/3.f);
        sx.w += (a.w + bm.w + cn.w) * (1.f/3.f);
        *(float4*)(Sx + s*EE + e) = sx;
        a = bm; bm = cn;
    }
}

// ---------------- fc1 GEMM: [512,1800] @ [1800,300]^T -> g_h ----------------
__global__ __launch_bounds__(256) void k_fc1(const float* __restrict__ fw) {
    int m0 = blockIdx.x * 64, n0 = blockIdx.y * 64;
    __shared__ float Xs[8][68];
    __shared__ float Ws2[8][68];
    int tid = threadIdx.x, ty = tid >> 4, tx = tid & 15;
    float acc[4][4];
#pragma unroll
    for (int u = 0; u < 4; u++)
#pragma unroll
        for (int v = 0; v < 4; v++) acc[u][v] = 0.f;

    for (int k0 = 0; k0 < FCIN; k0 += 8) {
        __syncthreads();
#pragma unroll 2
        for (int i = tid; i < 512; i += 256) {
            int r = i >> 3, kk = i & 7;
            Xs[kk][r] = g_x[(m0 + r)*FCIN + k0 + kk];
            int n = n0 + r;
            Ws2[kk][r] = (n < HH) ? fw[n*FCIN + k0 + kk] : 0.f;
        }
        __syncthreads();
#pragma unroll
        for (int kk = 0; kk < 8; kk++) {
            float4 xa = *(const float4*)&Xs[kk][ty*4];
            float4 wb = *(const float4*)&Ws2[kk][tx*4];
            float xv[4] = {xa.x, xa.y, xa.z, xa.w};
            float wvv[4] = {wb.x, wb.y, wb.z, wb.w};
#pragma unroll
            for (int u = 0; u < 4; u++)
#pragma unroll
                for (int v = 0; v < 4; v++) acc[u][v] += xv[u]*wvv[v];
        }
    }
#pragma unroll
    for (int u = 0; u < 4; u++) {
        int m = m0 + ty*4 + u;
#pragma unroll
        for (int v = 0; v < 4; v++) {
            int n = n0 + tx*4 + v;
            if (n < HH) g_h[m*HH + n] = acc[u][v];
        }
    }
}

// ---------------- LN + relu + fc2 + softmax ----------------
__device__ __forceinline__ float block_reduce512(float v, float* red) {
    int tid = threadIdx.x;
    red[tid] = v;
    __syncthreads();
    for (int off = 256; off > 0; off >>= 1) {
        if (tid < off) red[tid] += red[tid + off];
        __syncthreads();
    }
    float r = red[0];
    __syncthreads();
    return r;
}

__global__ __launch_bounds__(512) void k_head(const float* __restrict__ fc1b,
                                              const float* __restrict__ lng,
                                              const float* __restrict__ lnb,
                                              const float* __restrict__ fc2w,
                                              const float* __restrict__ fc2b,
                                              float* __restrict__ out) {
    int b = blockIdx.x, tid = threadIdx.x;
    __shared__ float red[512];
    bool act = tid < HH;
    float h = act ? (g_h[b*HH + tid] + fc1b[tid]) : 0.f;
    float mu = block_reduce512(h, red) * (1.f/HH);
    float d = act ? (h - mu) : 0.f;
    float var = block_reduce512(d*d, red) * (1.f/HH);
    float hn = 0.f;
    if (act) {
        hn = d * rsqrtf(var + 1e-5f) * lng[tid] + lnb[tid];
        hn = fmaxf(hn, 0.f);
    }
    float o0 = block_reduce512(act ? hn*fc2w[tid]      : 0.f, red);
    float o1 = block_reduce512(act ? hn*fc2w[HH + tid] : 0.f, red);
    if (tid == 0) {
        o0 += fc2b[0];
        o1 += fc2b[1];
        out[b*2 + 0] = o0;
        out[b*2 + 1] = o1;
        float m = fmaxf(o0, o1);
        float e0 = expf(o0 - m), e1 = expf(o1 - m);
        float inv = 1.f/(e0 + e1);
        out[BB*2 + b*2 + 0] = e0*inv;
        out[BB*2 + b*2 + 1] = e1*inv;
    }
}

// ---------------- launch ----------------
extern "C" void kernel_launch(void* const* d_in, const int* in_sizes, int n_in,
                              void* d_out, int out_size) {
    (void)in_sizes; (void)n_in; (void)out_size;
    const int*   seq1 = (const int*)d_in[0];
    const int*   seq2 = (const int*)d_in[1];
    const float* emb  = (const float*)d_in[2];
    const float* W    = (const float*)d_in[3];
    const float* cw   = (const float*)d_in[4];
    const float* cb   = (const float*)d_in[5];
    const float* fc1w = (const float*)d_in[6];
    const float* fc1b = (const float*)d_in[7];
    const float* lng  = (const float*)d_in[8];
    const float* lnb  = (const float*)d_in[9];
    const float* fc2w = (const float*)d_in[10];
    const float* fc2b = (const float*)d_in[11];
    float* out = (float*)d_out;

    const int SM_MATCH = (2*64*MPAD + 2*SS*MPAD + 64 + SS + 4*64 + 2*SS) * 4;  // ~33.5KB
    const int SM_FGEMM = 3*FBUF2*4;                                             // ~76.8KB
    const int SM_CONV  = (2*(CROWS+2)*(EE+2) + 18) * 4;                         // ~43.6KB

    cudaFuncSetAttribute(k_match, cudaFuncAttributeMaxDynamicSharedMemorySize, SM_MATCH);
    cudaFuncSetAttribute(k_fgemm, cudaFuncAttributeMaxDynamicSharedMemorySize, SM_FGEMM);
    cudaFuncSetAttribute(k_conv,  cudaFuncAttributeMaxDynamicSharedMemorySize, SM_CONV);

    k_wprep<<<dim3(320, LL), 128>>>(W);
    k_gather<<<BB, 256>>>(seq1, seq2, emb);
    for (int l = 0; l < LL; l++) {
        int last = (l == LL-1);
        k_match<<<dim3(BB, 2), 256, SM_MATCH>>>(0, l);
        k_fgemm<<<dim3(BB, 5), 256, SM_FGEMM>>>(l);
        k_conv<<<dim3(BB, 8, 2), 320, SM_CONV>>>(cw, cb, l, last ? 0 : 1);
        if (!last) {
            k_match<<<dim3(BB, 2), 256, SM_MATCH>>>(1, l);
            k_pool<<<dim3(BB, 8, 2), 96>>>();
        }
    }
    k_fc1<<<dim3(8, 5), 256>>>(fc1w);
    k_head<<<BB, 512>>>(fc1b, lng, lnb, fc2w, fc2b, out);
}

// round 16
// speedup vs baseline: 1.7747x; 1.0640x over previous
#include <cuda_runtime.h>
#include <cuda_fp16.h>
#include <math.h>
#include <stdint.h>

#define BB 512
#define SS 128
#define EE 300
#define LL 2
#define HH 300
#define FCIN 1800   // E*(1+L)*2
#define CROWS 16

// ---------------- device scratch (no allocation allowed) ----------------
__device__ __half g_s1h[BB*SS*EE];
__device__ __half g_s2h[BB*SS*EE];
__device__ __half g_f1h[BB*SS*EE];
__device__ __half g_f2h[BB*SS*EE];
__device__ __half g_o1h[BB*SS*EE];
__device__ __half g_o2h[BB*SS*EE];
__device__ __half g_Ah [BB*SS*SS];   // A  fp16
__device__ __half g_ATh[BB*SS*SS];   // A^T fp16
__device__ __half g_Wth[LL*320*SS];  // W^T fp16 [l][n][k], zero-pad n>=300
__device__ float g_w1[BB*SS];
__device__ float g_w2[BB*SS];
__device__ float g_v1[BB*SS];
__device__ float g_v2[BB*SS];
__device__ float g_x [BB*FCIN];
__device__ float g_h [BB*HH];

__device__ __forceinline__ float tanh_fast(float x) {
    float r; asm("tanh.approx.f32 %0, %1;" : "=f"(r) : "f"(x)); return r;
}
__device__ __forceinline__ uint32_t pack_h2(float a, float b) {
    __half2 h = __floats2half2_rn(a, b);
    return *(uint32_t*)&h;
}
__device__ __forceinline__ float4 ld4h(const __half* p) {
    uint2 u = *(const uint2*)p;
    __half2 h0 = *(__half2*)&u.x;
    __half2 h1 = *(__half2*)&u.y;
    return make_float4(__low2float(h0), __high2float(h0),
                       __low2float(h1), __high2float(h1));
}
__device__ __forceinline__ void st4h(__half* p, float4 v) {
    *(uint2*)p = make_uint2(pack_h2(v.x, v.y), pack_h2(v.z, v.w));
}
__device__ __forceinline__ void cpasync16(void* dst, const void* src) {
    uint32_t d = (uint32_t)__cvta_generic_to_shared(dst);
    asm volatile("cp.async.ca.shared.global [%0], [%1], 16;\n" :: "r"(d), "l"(src));
}
#define MMA_F16(C, A, B) \
    asm volatile("mma.sync.aligned.m16n8k16.row.col.f32.f16.f16.f32 " \
        "{%0,%1,%2,%3}, {%4,%5,%6,%7}, {%8,%9}, {%0,%1,%2,%3};" \
        : "+f"((C)[0]), "+f"((C)[1]), "+f"((C)[2]), "+f"((C)[3]) \
        : "r"((A)[0]), "r"((A)[1]), "r"((A)[2]), "r"((A)[3]), \
          "r"((B)[0]), "r"((B)[1]))

// ---------------- W prep: g_Wth[l][n][k] = fp16(W[l][k][n]) ----------------
__global__ void k_wprep(const float* __restrict__ W) {
    int n = blockIdx.x, l = blockIdx.y, k = threadIdx.x;
    float v = 0.f;
    if (n < EE) v = W[(size_t)l*SS*EE + k*EE + n];
    g_Wth[(l*320 + n)*SS + k] = __float2half(v);
}

// ---------------- embedding gather + masks + fused mean(slot0) ----------------
__global__ __launch_bounds__(256) void k_gather(const int* __restrict__ seq1,
                                                const int* __restrict__ seq2,
                                                const float* __restrict__ emb) {
    __shared__ float msum[2][EE];
    int b = blockIdx.x;
    int tid = threadIdx.x;
    int warp = tid >> 5, lane = tid & 31;
    for (int i = tid; i < 2*EE; i += 256) ((float*)msum)[i] = 0.f;
    for (int i = tid; i < SS; i += 256) {
        g_v1[b*SS+i] = (seq1[b*SS+i] != 0) ? 1.f : 0.f;
        g_v2[b*SS+i] = (seq2[b*SS+i] != 0) ? 1.f : 0.f;
    }
    __syncthreads();
    int sel = warp & 1;
    float4 acc[3];
#pragma unroll
    for (int jj = 0; jj < 3; jj++) acc[jj] = make_float4(0.f,0.f,0.f,0.f);
    for (int idx = warp; idx < 2*SS; idx += 8) {
        int s = idx >> 1;
        int tok = sel ? seq2[b*SS+s] : seq1[b*SS+s];
        const float4* src = (const float4*)(emb + (long)tok*EE);
        __half* dst = (sel ? g_s2h : g_s1h) + (size_t)(b*SS+s)*EE;
#pragma unroll
        for (int jj = 0; jj < 3; jj++) {
            int j = lane + 32*jj;
            if (j < EE/4) {
                float4 v = src[j];
                st4h(dst + 4*j, v);
                acc[jj].x += v.x; acc[jj].y += v.y; acc[jj].z += v.z; acc[jj].w += v.w;
            }
        }
    }
#pragma unroll
    for (int jj = 0; jj < 3; jj++) {
        int j = lane + 32*jj;
        if (j < EE/4) {
            atomicAdd(&msum[sel][4*j+0], acc[jj].x);
            atomicAdd(&msum[sel][4*j+1], acc[jj].y);
            atomicAdd(&msum[sel][4*j+2], acc[jj].z);
            atomicAdd(&msum[sel][4*j+3], acc[jj].w);
        }
    }
    __syncthreads();
    for (int e = tid; e < EE; e += 256) {
        g_x[b*FCIN + e]        = msum[0][e]*(1.f/SS);
        g_x[b*FCIN + 3*EE + e] = msum[1][e]*(1.f/SS);
    }
}

// ---------------- match-score, fp16 tensor cores, SPLIT grid (B,2) ------------
// mode=0: inputs s -> store A/AT fp16 + zero g_w2/g_x slots
// mode=1: inputs o -> w1 direct, w2 atomicAdd
#define MPAD 20     // half2 words per 32-k chunk (16) + pad 4
#define MCH 10      // ceil(300/32)
__global__ __launch_bounds__(256, 2) void k_match(int mode, int layer) {
    extern __shared__ float sm[];
    uint32_t* Xs = (uint32_t*)sm;           // [2][64][20] half2 words
    uint32_t* Ys = Xs + 2*64*MPAD;          // [2][128][20]
    float* n1s = (float*)(Ys + 2*SS*MPAD);  // [64]
    float* n2s = n1s + 64;                  // [128]
    float* rowbuf = n2s + SS;               // [4][64]
    float* colbuf = rowbuf + 4*64;          // [2][128]

    int b = blockIdx.x, h = blockIdx.y;
    int tid = threadIdx.x;
    int lane = tid & 31, wid = tid >> 5;
    int g = lane >> 2, tig = lane & 3;
    int wm = wid & 1, wn = wid >> 1;

    int rX = tid >> 2, qx = tid & 3;
    int rY = tid >> 1, hy = tid & 1;
    const __half* Xrh = (mode ? g_o1h : g_s1h) + (size_t)b*SS*EE + (h*64 + rX)*EE + qx*8;
    const __half* Yrh = (mode ? g_o2h : g_s2h) + (size_t)b*SS*EE + rY*EE + hy*16;
    float mvx = g_v1[b*SS + h*64 + rX];
    float mvy = g_v2[b*SS + rY];
    float nx = 0.f, ny = 0.f;
    float4 vx[2], vy[4];

#define FETCH(c) do { \
    int kb = (c)*32; \
    _Pragma("unroll") for (int j = 0; j < 2; j++) { \
        int k = kb + qx*8 + 4*j; \
        vx[j] = (k < EE) ? ld4h(Xrh + kb + 4*j) : make_float4(0.f,0.f,0.f,0.f); \
    } \
    _Pragma("unroll") for (int j = 0; j < 4; j++) { \
        int k = kb + hy*16 + 4*j; \
        vy[j] = (k < EE) ? ld4h(Yrh + kb + 4*j) : make_float4(0.f,0.f,0.f,0.f); \
    } } while(0)

#define STBUF(buf) do { \
    uint32_t* xd = Xs + (buf)*64*MPAD + rX*MPAD + qx*4; \
    uint32_t* yd = Ys + (buf)*SS*MPAD + rY*MPAD + hy*8; \
    _Pragma("unroll") for (int j = 0; j < 2; j++) { \
        float x0=vx[j].x*mvx, x1=vx[j].y*mvx, x2=vx[j].z*mvx, x3=vx[j].w*mvx; \
        nx += x0*x0+x1*x1+x2*x2+x3*x3; \
        xd[2*j+0] = pack_h2(x0, x1); \
        xd[2*j+1] = pack_h2(x2, x3); \
    } \
    _Pragma("unroll") for (int j = 0; j < 4; j++) { \
        float y0=vy[j].x*mvy, y1=vy[j].y*mvy, y2=vy[j].z*mvy, y3=vy[j].w*mvy; \
        ny += y0*y0+y1*y1+y2*y2+y3*y3; \
        yd[2*j+0] = pack_h2(y0, y1); \
        yd[2*j+1] = pack_h2(y2, y3); \
    } } while(0)

    float acc[2][4][4];
#pragma unroll
    for (int mt = 0; mt < 2; mt++)
#pragma unroll
        for (int nt = 0; nt < 4; nt++)
#pragma unroll
            for (int q = 0; q < 4; q++) acc[mt][nt][q] = 0.f;

    FETCH(0); STBUF(0);
    __syncthreads();

    for (int c = 0; c < MCH; c++) {
        int cur = c & 1;
        if (c + 1 < MCH) FETCH(c+1);
        const uint32_t* xb = Xs + cur*64*MPAD;
        const uint32_t* yb = Ys + cur*SS*MPAD;
#pragma unroll
        for (int ks = 0; ks < 2; ks++) {
            int ws = ks*8;
            uint32_t a[2][4], bf[4][2];
#pragma unroll
            for (int mt = 0; mt < 2; mt++) {
                int row = wm*32 + mt*16 + g;
                a[mt][0] = xb[row*MPAD + ws + tig];
                a[mt][1] = xb[(row+8)*MPAD + ws + tig];
                a[mt][2] = xb[row*MPAD + ws + tig + 4];
                a[mt][3] = xb[(row+8)*MPAD + ws + tig + 4];
            }
#pragma unroll
            for (int nt = 0; nt < 4; nt++) {
                int cr = wn*32 + nt*8 + g;
                bf[nt][0] = yb[cr*MPAD + ws + tig];
                bf[nt][1] = yb[cr*MPAD + ws + tig + 4];
            }
#pragma unroll
            for (int mt = 0; mt < 2; mt++)
#pragma unroll
                for (int nt = 0; nt < 4; nt++)
                    MMA_F16(acc[mt][nt], a[mt], bf[nt]);
        }
        if (c + 1 < MCH) STBUF(cur ^ 1);
        __syncthreads();
    }

    nx += __shfl_xor_sync(0xffffffffu, nx, 1);
    nx += __shfl_xor_sync(0xffffffffu, nx, 2);
    if (qx == 0) n1s[rX] = nx;
    ny += __shfl_xor_sync(0xffffffffu, ny, 1);
    if (hy == 0) n2s[rY] = ny;
    __syncthreads();

    if (mode == 0) {
        __half* Ao = g_Ah + (size_t)b*SS*SS + h*64*SS;
        __half* ts = (__half*)sm;   // transpose stage [128 cols][68 rows pad]
#pragma unroll
        for (int mt = 0; mt < 2; mt++) {
            int row = wm*32 + mt*16 + g;
            float nr0 = n1s[row], nr1 = n1s[row+8];
#pragma unroll
            for (int nt = 0; nt < 4; nt++) {
                int col = wn*32 + nt*8 + 2*tig;
                float nc0 = n2s[col], nc1 = n2s[col+1];
                float a00 = 1.f/(1.f + sqrtf(fmaxf(nr0 + nc0 - 2.f*acc[mt][nt][0], 0.f)));
                float a01 = 1.f/(1.f + sqrtf(fmaxf(nr0 + nc1 - 2.f*acc[mt][nt][1], 0.f)));
                float a10 = 1.f/(1.f + sqrtf(fmaxf(nr1 + nc0 - 2.f*acc[mt][nt][2], 0.f)));
                float a11 = 1.f/(1.f + sqrtf(fmaxf(nr1 + nc1 - 2.f*acc[mt][nt][3], 0.f)));
                *(__half2*)(Ao + row*SS + col)     = __floats2half2_rn(a00, a01);
                *(__half2*)(Ao + (row+8)*SS + col) = __floats2half2_rn(a10, a11);
                ts[(col+0)*68 + row]   = __float2half(a00);
                ts[(col+1)*68 + row]   = __float2half(a01);
                ts[(col+0)*68 + row+8] = __float2half(a10);
                ts[(col+1)*68 + row+8] = __float2half(a11);
            }
        }
        __syncthreads();
        __half* ATo = g_ATh + (size_t)b*SS*SS + h*64;
        for (int i = tid; i < 128*32; i += 256) {
            int col = i >> 5, rw = i & 31;
            __half2 v = *(__half2*)&ts[col*68 + 2*rw];
            *(__half2*)(ATo + col*SS + 2*rw) = v;
        }
        if (h == 0 && tid < SS) g_w2[b*SS + tid] = 0.f;
        int slot = (h ? 4 : 1) + layer;
        for (int e = tid; e < EE; e += 256) g_x[b*FCIN + slot*EE + e] = 0.f;
    } else {
        float cs0[4], cs1[4];
#pragma unroll
        for (int nt = 0; nt < 4; nt++) { cs0[nt] = 0.f; cs1[nt] = 0.f; }
#pragma unroll
        for (int mt = 0; mt < 2; mt++) {
            int row = wm*32 + mt*16 + g;
            float nr0 = n1s[row], nr1 = n1s[row+8];
            float rlo = 0.f, rhi = 0.f;
#pragma unroll
            for (int nt = 0; nt < 4; nt++) {
                int col = wn*32 + nt*8 + 2*tig;
                float nc0 = n2s[col], nc1 = n2s[col+1];
                float a00 = 1.f/(1.f + sqrtf(fmaxf(nr0 + nc0 - 2.f*acc[mt][nt][0], 0.f)));
                float a01 = 1.f/(1.f + sqrtf(fmaxf(nr0 + nc1 - 2.f*acc[mt][nt][1], 0.f)));
                float a10 = 1.f/(1.f + sqrtf(fmaxf(nr1 + nc0 - 2.f*acc[mt][nt][2], 0.f)));
                float a11 = 1.f/(1.f + sqrtf(fmaxf(nr1 + nc1 - 2.f*acc[mt][nt][3], 0.f)));
                rlo += a00 + a01;
                rhi += a10 + a11;
                cs0[nt] += a00 + a10;
                cs1[nt] += a01 + a11;
            }
            rlo += __shfl_xor_sync(0xffffffffu, rlo, 1);
            rlo += __shfl_xor_sync(0xffffffffu, rlo, 2);
            rhi += __shfl_xor_sync(0xffffffffu, rhi, 1);
            rhi += __shfl_xor_sync(0xffffffffu, rhi, 2);
            if (tig == 0) {
                rowbuf[wn*64 + row]   = rlo;
                rowbuf[wn*64 + row+8] = rhi;
            }
        }
#pragma unroll
        for (int nt = 0; nt < 4; nt++) {
            float c0 = cs0[nt], c1 = cs1[nt];
            c0 += __shfl_xor_sync(0xffffffffu, c0, 4);
            c0 += __shfl_xor_sync(0xffffffffu, c0, 8);
            c0 += __shfl_xor_sync(0xffffffffu, c0, 16);
            c1 += __shfl_xor_sync(0xffffffffu, c1, 4);
            c1 += __shfl_xor_sync(0xffffffffu, c1, 8);
            c1 += __shfl_xor_sync(0xffffffffu, c1, 16);
            if (g == 0) {
                int col = wn*32 + nt*8 + 2*tig;
                colbuf[wm*SS + col]     = c0;
                colbuf[wm*SS + col + 1] = c1;
            }
        }
        __syncthreads();
        if (tid < 64)
            g_w1[b*SS + h*64 + tid] = rowbuf[tid] + rowbuf[64+tid] + rowbuf[128+tid] + rowbuf[192+tid];
        if (tid < SS)
            atomicAdd(&g_w2[b*SS + tid], colbuf[tid] + colbuf[SS+tid]);
    }
#undef FETCH
#undef STBUF
}

// ---------------- f1=A@W, f2=A^T@W, fp16 mma, 3-stage cp.async, fp16 out ------
#define HPAD 20
#define FBUF2 (128*HPAD + 128*HPAD + 64*HPAD)   // 6400 words per buffer
__global__ __launch_bounds__(256, 2) void k_fgemm(int layer) {
    extern __shared__ float sm[];
    int b = blockIdx.x;
    int n0 = blockIdx.y * 64;
    const __half* Ah  = g_Ah  + (size_t)b*SS*SS;
    const __half* ATh = g_ATh + (size_t)b*SS*SS;
    const __half* Wth = g_Wth + (size_t)layer*320*SS;
    int tid = threadIdx.x;
    int lane = tid & 31, wid = tid >> 5;
    int g = lane >> 2, tig = lane & 3;
    int half = wid >> 2, wm = wid & 3;

#define LOADCH(c, buf) do { \
    uint32_t* base_ = (uint32_t*)sm + (buf)*FBUF2; \
    uint32_t* A1_ = base_; \
    uint32_t* AT_ = base_ + 128*HPAD; \
    uint32_t* Wb_ = AT_ + 128*HPAD; \
    int k0_ = (c)*32; \
    _Pragma("unroll") for (int j = 0; j < 2; j++) { \
        int i = tid + 256*j; int r = i >> 2, q = i & 3; \
        cpasync16(A1_ + r*HPAD + q*4, Ah + r*SS + k0_ + q*8); \
        cpasync16(AT_ + r*HPAD + q*4, ATh + r*SS + k0_ + q*8); \
    } \
    { int r = tid >> 2, q = tid & 3; \
      cpasync16(Wb_ + r*HPAD + q*4, Wth + (n0+r)*SS + k0_ + q*8); } \
    asm volatile("cp.async.commit_group;\n" ::); \
} while (0)

    float acc[2][8][4];
#pragma unroll
    for (int mt = 0; mt < 2; mt++)
#pragma unroll
        for (int nt = 0; nt < 8; nt++)
#pragma unroll
            for (int q = 0; q < 4; q++) acc[mt][nt][q] = 0.f;

    LOADCH(0, 0);
    LOADCH(1, 1);
    for (int c = 0; c < 4; c++) {
        if (c + 2 < 4) {
            LOADCH(c+2, (c+2)%3);
            asm volatile("cp.async.wait_group 2;\n" ::);
        } else if (c + 1 < 4) {
            asm volatile("cp.async.wait_group 1;\n" ::);
        } else {
            asm volatile("cp.async.wait_group 0;\n" ::);
        }
        __syncthreads();
        const uint32_t* Abase = (uint32_t*)sm + (c%3)*FBUF2 + half*128*HPAD;
        const uint32_t* Wb    = (uint32_t*)sm + (c%3)*FBUF2 + 2*128*HPAD;
#pragma unroll
        for (int ks = 0; ks < 2; ks++) {
            int ws = ks*8;
            uint32_t a[2][4], bf[8][2];
#pragma unroll
            for (int mt = 0; mt < 2; mt++) {
                int row = wm*32 + mt*16 + g;
                a[mt][0] = Abase[row*HPAD + ws + tig];
                a[mt][1] = Abase[(row+8)*HPAD + ws + tig];
                a[mt][2] = Abase[row*HPAD + ws + tig + 4];
                a[mt][3] = Abase[(row+8)*HPAD + ws + tig + 4];
            }
#pragma unroll
            for (int nt = 0; nt < 8; nt++) {
                int cn = nt*8 + g;
                bf[nt][0] = Wb[cn*HPAD + ws + tig];
                bf[nt][1] = Wb[cn*HPAD + ws + tig + 4];
            }
#pragma unroll
            for (int mt = 0; mt < 2; mt++)
#pragma unroll
                for (int nt = 0; nt < 8; nt++)
                    MMA_F16(acc[mt][nt], a[mt], bf[nt]);
        }
        __syncthreads();
    }
#undef LOADCH

    __half* out = (half ? g_f2h : g_f1h) + (size_t)b*SS*EE;
#pragma unroll
    for (int mt = 0; mt < 2; mt++) {
        int row = wm*32 + mt*16 + g;
#pragma unroll
        for (int nt = 0; nt < 8; nt++) {
            int col = n0 + nt*8 + 2*tig;
            if (col < EE) {
                *(__half2*)(out + row*EE + col)     = __floats2half2_rn(acc[mt][nt][0], acc[mt][nt][1]);
                *(__half2*)(out + (row+8)*EE + col) = __floats2half2_rn(acc[mt][nt][2], acc[mt][nt][3]);
            }
        }
    }
}

// ---------------- conv 2in->1out 3x3 + tanh + fused mean: column-per-thread ---
__global__ __launch_bounds__(320) void k_conv(const float* __restrict__ cw,
                                              const float* __restrict__ cb,
                                              int layer, int store) {
    extern __shared__ float sm[];
    float* xs = sm;                       // [2][18][302]
    float* w  = xs + 2*(CROWS+2)*(EE+2);  // [18]

    int b = blockIdx.x, ch = blockIdx.y, pair = blockIdx.z;
    int s0 = ch * CROWS;
    const __half* X0 = (pair ? g_s2h : g_s1h) + (size_t)b*SS*EE;
    const __half* X1 = (pair ? g_f2h : g_f1h) + (size_t)b*SS*EE;
    __half* O = (pair ? g_o2h : g_o1h) + (size_t)b*SS*EE;
    int tid = threadIdx.x;
    if (tid < 18) w[tid] = cw[layer*18 + tid];
    if (tid < 2*(CROWS+2)*2) {
        int c = tid / (2*(CROWS+2));
        int rem = tid % (2*(CROWS+2));
        int j = rem >> 1, side = rem & 1;
        xs[(c*(CROWS+2) + j)*(EE+2) + (side ? EE+1 : 0)] = 0.f;
    }
    for (int i = tid; i < 2*(CROWS+2)*(EE/4); i += 320) {
        int c = i / ((CROWS+2)*(EE/4));
        int rem = i % ((CROWS+2)*(EE/4));
        int j = rem / (EE/4), q = rem % (EE/4);
        int srow = s0 + j - 1;
        float4 val = make_float4(0.f,0.f,0.f,0.f);
        if (srow >= 0 && srow < SS)
            val = ld4h((c ? X1 : X0) + srow*EE + q*4);
        float* dptr = &xs[(c*(CROWS+2) + j)*(EE+2) + q*4 + 1];
        dptr[0]=val.x; dptr[1]=val.y; dptr[2]=val.z; dptr[3]=val.w;
    }
    __syncthreads();
    if (tid < EE) {
        int e = tid;
        float bias = cb[layer];
        const float* xs0 = xs;
        const float* xs1 = xs + (CROWS+2)*(EE+2);
        float sv[3][3], fv[3][3];
#pragma unroll
        for (int kh = 0; kh < 2; kh++)
#pragma unroll
            for (int kw = 0; kw < 3; kw++) {
                sv[kh][kw] = xs0[kh*(EE+2) + e + kw];
                fv[kh][kw] = xs1[kh*(EE+2) + e + kw];
            }
        float colsum = 0.f;
#pragma unroll 4
        for (int r = 0; r < CROWS; r++) {
#pragma unroll
            for (int kw = 0; kw < 3; kw++) {
                sv[2][kw] = xs0[(r+2)*(EE+2) + e + kw];
                fv[2][kw] = xs1[(r+2)*(EE+2) + e + kw];
            }
            float acc = bias;
#pragma unroll
            for (int kh = 0; kh < 3; kh++)
#pragma unroll
                for (int kw = 0; kw < 3; kw++)
                    acc += w[kh*3+kw]*sv[kh][kw] + w[9+kh*3+kw]*fv[kh][kw];
            float t = tanh_fast(acc);
            if (store) O[(s0+r)*EE + e] = __float2half(t);
            colsum += t;
#pragma unroll
            for (int kw = 0; kw < 3; kw++) {
                sv[0][kw] = sv[1][kw]; sv[1][kw] = sv[2][kw];
                fv[0][kw] = fv[1][kw]; fv[1][kw] = fv[2][kw];
            }
        }
        int slot = (pair ? 4 : 1) + layer;
        atomicAdd(&g_x[b*FCIN + slot*EE + e], colsum*(1.f/SS));
    }
}

// ---------------- weighted avg-pool3 + residual update, fp16 o and s ----------
__global__ __launch_bounds__(96) void k_pool() {
    int b = blockIdx.x, ch = blockIdx.y, pair = blockIdx.z;
    int s0 = ch * CROWS;
    const __half* O = (pair ? g_o2h : g_o1h) + (size_t)b*SS*EE;
    __half* Sx = (pair ? g_s2h : g_s1h) + (size_t)b*SS*EE;
    const float* wv = (pair ? g_w2 : g_w1) + b*SS;
    __shared__ float w[CROWS+2];
    if (threadIdx.x < CROWS+2) {
        int s = s0 + (int)threadIdx.x - 1;
        w[threadIdx.x] = (s >= 0 && s < SS) ? wv[s] : 0.f;
    }
    __syncthreads();
    int t = threadIdx.x;
    if (t >= 75) return;
    int e = t*4;
    float4 a = make_float4(0.f,0.f,0.f,0.f);
    if (s0 > 0) {
        float4 v = ld4h(O + (s0-1)*EE + e);
        a = make_float4(v.x*w[0], v.y*w[0], v.z*w[0], v.w*w[0]);
    }
    float4 v0 = ld4h(O + s0*EE + e);
    float4 bm = make_float4(v0.x*w[1], v0.y*w[1], v0.z*w[1], v0.w*w[1]);
#pragma unroll
    for (int i = 0; i < CROWS; i++) {
        int s = s0 + i;
        float4 cn = make_float4(0.f,0.f,0.f,0.f);
        if (s+1 < SS) {
            float4 v = ld4h(O + (s+1)*EE + e);
            float ww = w[i+2];
            cn = make_float4(v.x*ww, v.y*ww, v.z*ww, v.w*ww);
        }
        float4 sx = ld4h(Sx + s*EE + e);
        sx.x += (a.x + bm.x + cn.x) * (1.f/3.f);
        sx.y += (a.y + bm.y + cn.y) * (1.f/3.f);
        sx.z += (a.z + bm.z + cn.z) * (1.f/3.f);
        sx.w += (a.w + bm.w + cn.w) * (1.f/3.f);
        st4h(Sx + s*EE + e, sx);
        a = bm; bm = cn;
    }
}

// ---------------- fc1 GEMM: [512,1800] @ [1800,300]^T -> g_h ----------------
__global__ __launch_bounds__(256) void k_fc1(const float* __restrict__ fw) {
    int m0 = blockIdx.x * 64, n0 = blockIdx.y * 64;
    __shared__ float Xs[8][68];
    __shared__ float Ws2[8][68];
    int tid = threadIdx.x, ty = tid >> 4, tx = tid & 15;
    float acc[4][4];
#pragma unroll
    for (int u = 0; u < 4; u++)
#pragma unroll
        for (int v = 0; v < 4; v++) acc[u][v] = 0.f;

    for (int k0 = 0; k0 < FCIN; k0 += 8) {
        __syncthreads();
#pragma unroll 2
        for (int i = tid; i < 512; i += 256) {
            int r = i >> 3, kk = i & 7;
            Xs[kk][r] = g_x[(m0 + r)*FCIN + k0 + kk];
            int n = n0 + r;
            Ws2[kk][r] = (n < HH) ? fw[n*FCIN + k0 + kk] : 0.f;
        }
        __syncthreads();
#pragma unroll
        for (int kk = 0; kk < 8; kk++) {
            float4 xa = *(const float4*)&Xs[kk][ty*4];
            float4 wb = *(const float4*)&Ws2[kk][tx*4];
            float xv[4] = {xa.x, xa.y, xa.z, xa.w};
            float wvv[4] = {wb.x, wb.y, wb.z, wb.w};
#pragma unroll
            for (int u = 0; u < 4; u++)
#pragma unroll
                for (int v = 0; v < 4; v++) acc[u][v] += xv[u]*wvv[v];
        }
    }
#pragma unroll
    for (int u = 0; u < 4; u++) {
        int m = m0 + ty*4 + u;
#pragma unroll
        for (int v = 0; v < 4; v++) {
            int n = n0 + tx*4 + v;
            if (n < HH) g_h[m*HH + n] = acc[u][v];
        }
    }
}

// ---------------- LN + relu + fc2 + softmax ----------------
__device__ __forceinline__ float block_reduce512(float v, float* red) {
    int tid = threadIdx.x;
    red[tid] = v;
    __syncthreads();
    for (int off = 256; off > 0; off >>= 1) {
        if (tid < off) red[tid] += red[tid + off];
        __syncthreads();
    }
    float r = red[0];
    __syncthreads();
    return r;
}

__global__ __launch_bounds__(512) void k_head(const float* __restrict__ fc1b,
                                              const float* __restrict__ lng,
                                              const float* __restrict__ lnb,
                                              const float* __restrict__ fc2w,
                                              const float* __restrict__ fc2b,
                                              float* __restrict__ out) {
    int b = blockIdx.x, tid = threadIdx.x;
    __shared__ float red[512];
    bool act = tid < HH;
    float h = act ? (g_h[b*HH + tid] + fc1b[tid]) : 0.f;
    float mu = block_reduce512(h, red) * (1.f/HH);
    float d = act ? (h - mu) : 0.f;
    float var = block_reduce512(d*d, red) * (1.f/HH);
    float hn = 0.f;
    if (act) {
        hn = d * rsqrtf(var + 1e-5f) * lng[tid] + lnb[tid];
        hn = fmaxf(hn, 0.f);
    }
    float o0 = block_reduce512(act ? hn*fc2w[tid]      : 0.f, red);
    float o1 = block_reduce512(act ? hn*fc2w[HH + tid] : 0.f, red);
    if (tid == 0) {
        o0 += fc2b[0];
        o1 += fc2b[1];
        out[b*2 + 0] = o0;
        out[b*2 + 1] = o1;
        float m = fmaxf(o0, o1);
        float e0 = expf(o0 - m), e1 = expf(o1 - m);
        float inv = 1.f/(e0 + e1);
        out[BB*2 + b*2 + 0] = e0*inv;
        out[BB*2 + b*2 + 1] = e1*inv;
    }
}

// ---------------- launch ----------------
extern "C" void kernel_launch(void* const* d_in, const int* in_sizes, int n_in,
                              void* d_out, int out_size) {
    (void)in_sizes; (void)n_in; (void)out_size;
    const int*   seq1 = (const int*)d_in[0];
    const int*   seq2 = (const int*)d_in[1];
    const float* emb  = (const float*)d_in[2];
    const float* W    = (const float*)d_in[3];
    const float* cw   = (const float*)d_in[4];
    const float* cb   = (const float*)d_in[5];
    const float* fc1w = (const float*)d_in[6];
    const float* fc1b = (const float*)d_in[7];
    const float* lng  = (const float*)d_in[8];
    const float* lnb  = (const float*)d_in[9];
    const float* fc2w = (const float*)d_in[10];
    const float* fc2b = (const float*)d_in[11];
    float* out = (float*)d_out;

    const int SM_MATCH = (2*64*MPAD + 2*SS*MPAD + 64 + SS + 4*64 + 2*SS) * 4;  // ~33.5KB
    const int SM_FGEMM = 3*FBUF2*4;                                             // ~76.8KB
    const int SM_CONV  = (2*(CROWS+2)*(EE+2) + 18) * 4;                         // ~43.6KB

    cudaFuncSetAttribute(k_match, cudaFuncAttributeMaxDynamicSharedMemorySize, SM_MATCH);
    cudaFuncSetAttribute(k_fgemm, cudaFuncAttributeMaxDynamicSharedMemorySize, SM_FGEMM);
    cudaFuncSetAttribute(k_conv,  cudaFuncAttributeMaxDynamicSharedMemorySize, SM_CONV);

    k_wprep<<<dim3(320, LL), 128>>>(W);
    k_gather<<<BB, 256>>>(seq1, seq2, emb);
    for (int l = 0; l < LL; l++) {
        int last = (l == LL-1);
        k_match<<<dim3(BB, 2), 256, SM_MATCH>>>(0, l);
        k_fgemm<<<dim3(BB, 5), 256, SM_FGEMM>>>(l);
        k_conv<<<dim3(BB, 8, 2), 320, SM_CONV>>>(cw, cb, l, last ? 0 : 1);
        if (!last) {
            k_match<<<dim3(BB, 2), 256, SM_MATCH>>>(1, l);
            k_pool<<<dim3(BB, 8, 2), 96>>>();
        }
    }
    k_fc1<<<dim3(8, 5), 256>>>(fc1w);
    k_head<<<BB, 512>>>(fc1b, lng, lnb, fc2w, fc2b, out);
}

// round 17
// speedup vs baseline: 1.7821x; 1.0042x over previous
#include <cuda_runtime.h>
#include <cuda_fp16.h>
#include <math.h>
#include <stdint.h>

#define BB 512
#define SS 128
#define EE 300
#define LL 2
#define HH 300
#define FCIN 1800   // E*(1+L)*2
#define CROWS 16

// ---------------- device scratch (no allocation allowed) ----------------
__device__ __half g_s1h[BB*SS*EE];
__device__ __half g_s2h[BB*SS*EE];
__device__ __half g_f1h[BB*SS*EE];
__device__ __half g_f2h[BB*SS*EE];
__device__ __half g_o1h[BB*SS*EE];
__device__ __half g_o2h[BB*SS*EE];
__device__ __half g_Ah [BB*SS*SS];   // A  fp16
__device__ __half g_ATh[BB*SS*SS];   // A^T fp16
__device__ __half g_Wth[LL*320*SS];  // W^T fp16 [l][n][k], zero-pad n>=300
__device__ float g_w1[BB*SS];
__device__ float g_w2[BB*SS];
__device__ float g_v1[BB*SS];
__device__ float g_v2[BB*SS];
__device__ float g_x [BB*FCIN];
__device__ float g_h [BB*HH];

__device__ __forceinline__ float tanh_fast(float x) {
    float r; asm("tanh.approx.f32 %0, %1;" : "=f"(r) : "f"(x)); return r;
}
__device__ __forceinline__ uint32_t pack_h2(float a, float b) {
    __half2 h = __floats2half2_rn(a, b);
    return *(uint32_t*)&h;
}
__device__ __forceinline__ float4 ld4h(const __half* p) {
    uint2 u = *(const uint2*)p;
    __half2 h0 = *(__half2*)&u.x;
    __half2 h1 = *(__half2*)&u.y;
    return make_float4(__low2float(h0), __high2float(h0),
                       __low2float(h1), __high2float(h1));
}
__device__ __forceinline__ void st4h(__half* p, float4 v) {
    *(uint2*)p = make_uint2(pack_h2(v.x, v.y), pack_h2(v.z, v.w));
}
__device__ __forceinline__ void cpasync16(void* dst, const void* src) {
    uint32_t d = (uint32_t)__cvta_generic_to_shared(dst);
    asm volatile("cp.async.ca.shared.global [%0], [%1], 16;\n" :: "r"(d), "l"(src));
}
#define MMA_F16(C, A, B) \
    asm volatile("mma.sync.aligned.m16n8k16.row.col.f32.f16.f16.f32 " \
        "{%0,%1,%2,%3}, {%4,%5,%6,%7}, {%8,%9}, {%0,%1,%2,%3};" \
        : "+f"((C)[0]), "+f"((C)[1]), "+f"((C)[2]), "+f"((C)[3]) \
        : "r"((A)[0]), "r"((A)[1]), "r"((A)[2]), "r"((A)[3]), \
          "r"((B)[0]), "r"((B)[1]))

// ---------------- W prep: g_Wth[l][n][k] = fp16(W[l][k][n]) ----------------
__global__ void k_wprep(const float* __restrict__ W) {
    int n = blockIdx.x, l = blockIdx.y, k = threadIdx.x;
    float v = 0.f;
    if (n < EE) v = W[(size_t)l*SS*EE + k*EE + n];
    g_Wth[(l*320 + n)*SS + k] = __float2half(v);
}

// ---------------- embedding gather + masks + fused mean(slot0) ----------------
__global__ __launch_bounds__(256) void k_gather(const int* __restrict__ seq1,
                                                const int* __restrict__ seq2,
                                                const float* __restrict__ emb) {
    __shared__ float msum[2][EE];
    int b = blockIdx.x;
    int tid = threadIdx.x;
    int warp = tid >> 5, lane = tid & 31;
    for (int i = tid; i < 2*EE; i += 256) ((float*)msum)[i] = 0.f;
    for (int i = tid; i < SS; i += 256) {
        g_v1[b*SS+i] = (seq1[b*SS+i] != 0) ? 1.f : 0.f;
        g_v2[b*SS+i] = (seq2[b*SS+i] != 0) ? 1.f : 0.f;
    }
    __syncthreads();
    int sel = warp & 1;
    float4 acc[3];
#pragma unroll
    for (int jj = 0; jj < 3; jj++) acc[jj] = make_float4(0.f,0.f,0.f,0.f);
    for (int idx = warp; idx < 2*SS; idx += 8) {
        int s = idx >> 1;
        int tok = sel ? seq2[b*SS+s] : seq1[b*SS+s];
        const float4* src = (const float4*)(emb + (long)tok*EE);
        __half* dst = (sel ? g_s2h : g_s1h) + (size_t)(b*SS+s)*EE;
#pragma unroll
        for (int jj = 0; jj < 3; jj++) {
            int j = lane + 32*jj;
            if (j < EE/4) {
                float4 v = src[j];
                st4h(dst + 4*j, v);
                acc[jj].x += v.x; acc[jj].y += v.y; acc[jj].z += v.z; acc[jj].w += v.w;
            }
        }
    }
#pragma unroll
    for (int jj = 0; jj < 3; jj++) {
        int j = lane + 32*jj;
        if (j < EE/4) {
            atomicAdd(&msum[sel][4*j+0], acc[jj].x);
            atomicAdd(&msum[sel][4*j+1], acc[jj].y);
            atomicAdd(&msum[sel][4*j+2], acc[jj].z);
            atomicAdd(&msum[sel][4*j+3], acc[jj].w);
        }
    }
    __syncthreads();
    for (int e = tid; e < EE; e += 256) {
        g_x[b*FCIN + e]        = msum[0][e]*(1.f/SS);
        g_x[b*FCIN + 3*EE + e] = msum[1][e]*(1.f/SS);
    }
}

// ---------------- match-score, fp16 tensor cores, SPLIT grid (B,2) ------------
// mode=0: inputs s -> store A/AT fp16 + zero g_w2/g_x slots
// mode=1: inputs o -> w1 direct, w2 atomicAdd
#define MPAD 20     // half2 words per 32-k chunk (16) + pad 4
#define MCH 10      // ceil(300/32)
__global__ __launch_bounds__(256, 2) void k_match(int mode, int layer) {
    extern __shared__ float sm[];
    uint32_t* Xs = (uint32_t*)sm;           // [2][64][20] half2 words
    uint32_t* Ys = Xs + 2*64*MPAD;          // [2][128][20]
    float* n1s = (float*)(Ys + 2*SS*MPAD);  // [64]
    float* n2s = n1s + 64;                  // [128]
    float* rowbuf = n2s + SS;               // [4][64]
    float* colbuf = rowbuf + 4*64;          // [2][128]

    int b = blockIdx.x, h = blockIdx.y;
    int tid = threadIdx.x;
    int lane = tid & 31, wid = tid >> 5;
    int g = lane >> 2, tig = lane & 3;
    int wm = wid & 1, wn = wid >> 1;

    int rX = tid >> 2, qx = tid & 3;
    int rY = tid >> 1, hy = tid & 1;
    const __half* Xrh = (mode ? g_o1h : g_s1h) + (size_t)b*SS*EE + (h*64 + rX)*EE + qx*8;
    const __half* Yrh = (mode ? g_o2h : g_s2h) + (size_t)b*SS*EE + rY*EE + hy*16;
    float mvx = g_v1[b*SS + h*64 + rX];
    float mvy = g_v2[b*SS + rY];
    float nx = 0.f, ny = 0.f;
    float4 vx[2], vy[4];

#define FETCH(c) do { \
    int kb = (c)*32; \
    _Pragma("unroll") for (int j = 0; j < 2; j++) { \
        int k = kb + qx*8 + 4*j; \
        vx[j] = (k < EE) ? ld4h(Xrh + kb + 4*j) : make_float4(0.f,0.f,0.f,0.f); \
    } \
    _Pragma("unroll") for (int j = 0; j < 4; j++) { \
        int k = kb + hy*16 + 4*j; \
        vy[j] = (k < EE) ? ld4h(Yrh + kb + 4*j) : make_float4(0.f,0.f,0.f,0.f); \
    } } while(0)

#define STBUF(buf) do { \
    uint32_t* xd = Xs + (buf)*64*MPAD + rX*MPAD + qx*4; \
    uint32_t* yd = Ys + (buf)*SS*MPAD + rY*MPAD + hy*8; \
    _Pragma("unroll") for (int j = 0; j < 2; j++) { \
        float x0=vx[j].x*mvx, x1=vx[j].y*mvx, x2=vx[j].z*mvx, x3=vx[j].w*mvx; \
        nx += x0*x0+x1*x1+x2*x2+x3*x3; \
        xd[2*j+0] = pack_h2(x0, x1); \
        xd[2*j+1] = pack_h2(x2, x3); \
    } \
    _Pragma("unroll") for (int j = 0; j < 4; j++) { \
        float y0=vy[j].x*mvy, y1=vy[j].y*mvy, y2=vy[j].z*mvy, y3=vy[j].w*mvy; \
        ny += y0*y0+y1*y1+y2*y2+y3*y3; \
        yd[2*j+0] = pack_h2(y0, y1); \
        yd[2*j+1] = pack_h2(y2, y3); \
    } } while(0)

    float acc[2][4][4];
#pragma unroll
    for (int mt = 0; mt < 2; mt++)
#pragma unroll
        for (int nt = 0; nt < 4; nt++)
#pragma unroll
            for (int q = 0; q < 4; q++) acc[mt][nt][q] = 0.f;

    FETCH(0); STBUF(0);
    __syncthreads();

    for (int c = 0; c < MCH; c++) {
        int cur = c & 1;
        if (c + 1 < MCH) FETCH(c+1);
        const uint32_t* xb = Xs + cur*64*MPAD;
        const uint32_t* yb = Ys + cur*SS*MPAD;
#pragma unroll
        for (int ks = 0; ks < 2; ks++) {
            int ws = ks*8;
            uint32_t a[2][4], bf[4][2];
#pragma unroll
            for (int mt = 0; mt < 2; mt++) {
                int row = wm*32 + mt*16 + g;
                a[mt][0] = xb[row*MPAD + ws + tig];
                a[mt][1] = xb[(row+8)*MPAD + ws + tig];
                a[mt][2] = xb[row*MPAD + ws + tig + 4];
                a[mt][3] = xb[(row+8)*MPAD + ws + tig + 4];
            }
#pragma unroll
            for (int nt = 0; nt < 4; nt++) {
                int cr = wn*32 + nt*8 + g;
                bf[nt][0] = yb[cr*MPAD + ws + tig];
                bf[nt][1] = yb[cr*MPAD + ws + tig + 4];
            }
#pragma unroll
            for (int mt = 0; mt < 2; mt++)
#pragma unroll
                for (int nt = 0; nt < 4; nt++)
                    MMA_F16(acc[mt][nt], a[mt], bf[nt]);
        }
        if (c + 1 < MCH) STBUF(cur ^ 1);
        __syncthreads();
    }

    nx += __shfl_xor_sync(0xffffffffu, nx, 1);
    nx += __shfl_xor_sync(0xffffffffu, nx, 2);
    if (qx == 0) n1s[rX] = nx;
    ny += __shfl_xor_sync(0xffffffffu, ny, 1);
    if (hy == 0) n2s[rY] = ny;
    __syncthreads();

    if (mode == 0) {
        __half* Ao = g_Ah + (size_t)b*SS*SS + h*64*SS;
        __half* ts = (__half*)sm;   // transpose stage [128 cols][68 rows pad]
#pragma unroll
        for (int mt = 0; mt < 2; mt++) {
            int row = wm*32 + mt*16 + g;
            float nr0 = n1s[row], nr1 = n1s[row+8];
#pragma unroll
            for (int nt = 0; nt < 4; nt++) {
                int col = wn*32 + nt*8 + 2*tig;
                float nc0 = n2s[col], nc1 = n2s[col+1];
                float a00 = 1.f/(1.f + sqrtf(fmaxf(nr0 + nc0 - 2.f*acc[mt][nt][0], 0.f)));
                float a01 = 1.f/(1.f + sqrtf(fmaxf(nr0 + nc1 - 2.f*acc[mt][nt][1], 0.f)));
                float a10 = 1.f/(1.f + sqrtf(fmaxf(nr1 + nc0 - 2.f*acc[mt][nt][2], 0.f)));
                float a11 = 1.f/(1.f + sqrtf(fmaxf(nr1 + nc1 - 2.f*acc[mt][nt][3], 0.f)));
                *(__half2*)(Ao + row*SS + col)     = __floats2half2_rn(a00, a01);
                *(__half2*)(Ao + (row+8)*SS + col) = __floats2half2_rn(a10, a11);
                ts[(col+0)*68 + row]   = __float2half(a00);
                ts[(col+1)*68 + row]   = __float2half(a01);
                ts[(col+0)*68 + row+8] = __float2half(a10);
                ts[(col+1)*68 + row+8] = __float2half(a11);
            }
        }
        __syncthreads();
        __half* ATo = g_ATh + (size_t)b*SS*SS + h*64;
        for (int i = tid; i < 128*32; i += 256) {
            int col = i >> 5, rw = i & 31;
            __half2 v = *(__half2*)&ts[col*68 + 2*rw];
            *(__half2*)(ATo + col*SS + 2*rw) = v;
        }
        if (h == 0 && tid < SS) g_w2[b*SS + tid] = 0.f;
        int slot = (h ? 4 : 1) + layer;
        for (int e = tid; e < EE; e += 256) g_x[b*FCIN + slot*EE + e] = 0.f;
    } else {
        float cs0[4], cs1[4];
#pragma unroll
        for (int nt = 0; nt < 4; nt++) { cs0[nt] = 0.f; cs1[nt] = 0.f; }
#pragma unroll
        for (int mt = 0; mt < 2; mt++) {
            int row = wm*32 + mt*16 + g;
            float nr0 = n1s[row], nr1 = n1s[row+8];
            float rlo = 0.f, rhi = 0.f;
#pragma unroll
            for (int nt = 0; nt < 4; nt++) {
                int col = wn*32 + nt*8 + 2*tig;
                float nc0 = n2s[col], nc1 = n2s[col+1];
                float a00 = 1.f/(1.f + sqrtf(fmaxf(nr0 + nc0 - 2.f*acc[mt][nt][0], 0.f)));
                float a01 = 1.f/(1.f + sqrtf(fmaxf(nr0 + nc1 - 2.f*acc[mt][nt][1], 0.f)));
                float a10 = 1.f/(1.f + sqrtf(fmaxf(nr1 + nc0 - 2.f*acc[mt][nt][2], 0.f)));
                float a11 = 1.f/(1.f + sqrtf(fmaxf(nr1 + nc1 - 2.f*acc[mt][nt][3], 0.f)));
                rlo += a00 + a01;
                rhi += a10 + a11;
                cs0[nt] += a00 + a10;
                cs1[nt] += a01 + a11;
            }
            rlo += __shfl_xor_sync(0xffffffffu, rlo, 1);
            rlo += __shfl_xor_sync(0xffffffffu, rlo, 2);
            rhi += __shfl_xor_sync(0xffffffffu, rhi, 1);
            rhi += __shfl_xor_sync(0xffffffffu, rhi, 2);
            if (tig == 0) {
                rowbuf[wn*64 + row]   = rlo;
                rowbuf[wn*64 + row+8] = rhi;
            }
        }
#pragma unroll
        for (int nt = 0; nt < 4; nt++) {
            float c0 = cs0[nt], c1 = cs1[nt];
            c0 += __shfl_xor_sync(0xffffffffu, c0, 4);
            c0 += __shfl_xor_sync(0xffffffffu, c0, 8);
            c0 += __shfl_xor_sync(0xffffffffu, c0, 16);
            c1 += __shfl_xor_sync(0xffffffffu, c1, 4);
            c1 += __shfl_xor_sync(0xffffffffu, c1, 8);
            c1 += __shfl_xor_sync(0xffffffffu, c1, 16);
            if (g == 0) {
                int col = wn*32 + nt*8 + 2*tig;
                colbuf[wm*SS + col]     = c0;
                colbuf[wm*SS + col + 1] = c1;
            }
        }
        __syncthreads();
        if (tid < 64)
            g_w1[b*SS + h*64 + tid] = rowbuf[tid] + rowbuf[64+tid] + rowbuf[128+tid] + rowbuf[192+tid];
        if (tid < SS)
            atomicAdd(&g_w2[b*SS + tid], colbuf[tid] + colbuf[SS+tid]);
    }
#undef FETCH
#undef STBUF
}

// ---------------- f = A@W (or A^T@W), A-resident, W double-buffered ------------
// grid (B, 2): z=0 -> A->f1, z=1 -> AT->f2.  8 warps x 16-row tiles, 5 n-blocks.
#define APADW 68    // words per 128-k row (64) + pad 4
#define WOFF  (128*APADW)              // A region words
#define WBUF  (64*APADW)               // one W buffer words
__global__ __launch_bounds__(256, 2) void k_fgemm(int layer) {
    extern __shared__ float sm[];
    uint32_t* As = (uint32_t*)sm;                  // [128][68]
    uint32_t* Wb0 = As + WOFF;                     // [2][64][68]
    int b = blockIdx.x, half = blockIdx.y;
    const __half* Ah = (half ? g_ATh : g_Ah) + (size_t)b*SS*SS;
    const __half* Wth = g_Wth + (size_t)layer*320*SS;
    int tid = threadIdx.x;
    int lane = tid & 31, wid = tid >> 5;
    int g = lane >> 2, tig = lane & 3;

    // load A (128x128 fp16) once: group with W0
    {
#pragma unroll
        for (int j = 0; j < 8; j++) {
            int i = tid + 256*j;
            int r = i >> 4, q = i & 15;
            cpasync16(As + r*APADW + q*4, Ah + r*SS + q*8);
        }
    }
#define LOADW(c, buf) do { \
    uint32_t* Wd = Wb0 + (buf)*WBUF; \
    _Pragma("unroll") for (int j = 0; j < 4; j++) { \
        int i = tid + 256*j; int r = i >> 4, q = i & 15; \
        cpasync16(Wd + r*APADW + q*4, Wth + ((c)*64 + r)*SS + q*8); \
    } \
    asm volatile("cp.async.commit_group;\n" ::); \
} while (0)

    LOADW(0, 0);   // commits A + W0 as group 0
    LOADW(1, 1);   // group 1

    __half* out = (half ? g_f2h : g_f1h) + (size_t)b*SS*EE;
    int row = wid*16 + g;

    for (int c = 0; c < 5; c++) {
        if (c + 1 < 5) {
            LOADW(c+1, (c+1)&1);      // note: issued for c+1 (buffer toggles)
        }
        // need group c complete; allow later groups pending
        if (c + 1 < 5) asm volatile("cp.async.wait_group 1;\n" ::);
        else           asm volatile("cp.async.wait_group 0;\n" ::);
        __syncthreads();

        const uint32_t* Wbuf = Wb0 + (c&1)*WBUF;
        float acc[8][4];
#pragma unroll
        for (int nt = 0; nt < 8; nt++)
#pragma unroll
            for (int q = 0; q < 4; q++) acc[nt][q] = 0.f;

#pragma unroll
        for (int ks = 0; ks < 8; ks++) {
            int ws = ks*8;
            uint32_t a[4], bf[8][2];
            a[0] = As[row*APADW + ws + tig];
            a[1] = As[(row+8)*APADW + ws + tig];
            a[2] = As[row*APADW + ws + tig + 4];
            a[3] = As[(row+8)*APADW + ws + tig + 4];
#pragma unroll
            for (int nt = 0; nt < 8; nt++) {
                int cn = nt*8 + g;
                bf[nt][0] = Wbuf[cn*APADW + ws + tig];
                bf[nt][1] = Wbuf[cn*APADW + ws + tig + 4];
            }
#pragma unroll
            for (int nt = 0; nt < 8; nt++)
                MMA_F16(acc[nt], a, bf[nt]);
        }

#pragma unroll
        for (int nt = 0; nt < 8; nt++) {
            int col = c*64 + nt*8 + 2*tig;
            if (col < EE) {
                *(__half2*)(out + row*EE + col)     = __floats2half2_rn(acc[nt][0], acc[nt][1]);
                *(__half2*)(out + (row+8)*EE + col) = __floats2half2_rn(acc[nt][2], acc[nt][3]);
            }
        }
        __syncthreads();
    }
#undef LOADW
}

// ---------------- conv 2in->1out 3x3 + tanh + fused mean: column-per-thread ---
__global__ __launch_bounds__(320) void k_conv(const float* __restrict__ cw,
                                              const float* __restrict__ cb,
                                              int layer, int store) {
    extern __shared__ float sm[];
    float* xs = sm;                       // [2][18][302]
    float* w  = xs + 2*(CROWS+2)*(EE+2);  // [18]

    int b = blockIdx.x, ch = blockIdx.y, pair = blockIdx.z;
    int s0 = ch * CROWS;
    const __half* X0 = (pair ? g_s2h : g_s1h) + (size_t)b*SS*EE;
    const __half* X1 = (pair ? g_f2h : g_f1h) + (size_t)b*SS*EE;
    __half* O = (pair ? g_o2h : g_o1h) + (size_t)b*SS*EE;
    int tid = threadIdx.x;
    if (tid < 18) w[tid] = cw[layer*18 + tid];
    if (tid < 2*(CROWS+2)*2) {
        int c = tid / (2*(CROWS+2));
        int rem = tid % (2*(CROWS+2));
        int j = rem >> 1, side = rem & 1;
        xs[(c*(CROWS+2) + j)*(EE+2) + (side ? EE+1 : 0)] = 0.f;
    }
    for (int i = tid; i < 2*(CROWS+2)*(EE/4); i += 320) {
        int c = i / ((CROWS+2)*(EE/4));
        int rem = i % ((CROWS+2)*(EE/4));
        int j = rem / (EE/4), q = rem % (EE/4);
        int srow = s0 + j - 1;
        float4 val = make_float4(0.f,0.f,0.f,0.f);
        if (srow >= 0 && srow < SS)
            val = ld4h((c ? X1 : X0) + srow*EE + q*4);
        float* dptr = &xs[(c*(CROWS+2) + j)*(EE+2) + q*4 + 1];
        dptr[0]=val.x; dptr[1]=val.y; dptr[2]=val.z; dptr[3]=val.w;
    }
    __syncthreads();
    if (tid < EE) {
        int e = tid;
        float bias = cb[layer];
        const float* xs0 = xs;
        const float* xs1 = xs + (CROWS+2)*(EE+2);
        float sv[3][3], fv[3][3];
#pragma unroll
        for (int kh = 0; kh < 2; kh++)
#pragma unroll
            for (int kw = 0; kw < 3; kw++) {
                sv[kh][kw] = xs0[kh*(EE+2) + e + kw];
                fv[kh][kw] = xs1[kh*(EE+2) + e + kw];
            }
        float colsum = 0.f;
#pragma unroll 4
        for (int r = 0; r < CROWS; r++) {
#pragma unroll
            for (int kw = 0; kw < 3; kw++) {
                sv[2][kw] = xs0[(r+2)*(EE+2) + e + kw];
                fv[2][kw] = xs1[(r+2)*(EE+2) + e + kw];
            }
            float acc = bias;
#pragma unroll
            for (int kh = 0; kh < 3; kh++)
#pragma unroll
                for (int kw = 0; kw < 3; kw++)
                    acc += w[kh*3+kw]*sv[kh][kw] + w[9+kh*3+kw]*fv[kh][kw];
            float t = tanh_fast(acc);
            if (store) O[(s0+r)*EE + e] = __float2half(t);
            colsum += t;
#pragma unroll
            for (int kw = 0; kw < 3; kw++) {
                sv[0][kw] = sv[1][kw]; sv[1][kw] = sv[2][kw];
                fv[0][kw] = fv[1][kw]; fv[1][kw] = fv[2][kw];
            }
        }
        int slot = (pair ? 4 : 1) + layer;
        atomicAdd(&g_x[b*FCIN + slot*EE + e], colsum*(1.f/SS));
    }
}

// ---------------- weighted avg-pool3 + residual update, fp16 o and s ----------
__global__ __launch_bounds__(96) void k_pool() {
    int b = blockIdx.x, ch = blockIdx.y, pair = blockIdx.z;
    int s0 = ch * CROWS;
    const __half* O = (pair ? g_o2h : g_o1h) + (size_t)b*SS*EE;
    __half* Sx = (pair ? g_s2h : g_s1h) + (size_t)b*SS*EE;
    const float* wv = (pair ? g_w2 : g_w1) + b*SS;
    __shared__ float w[CROWS+2];
    if (threadIdx.x < CROWS+2) {
        int s = s0 + (int)threadIdx.x - 1;
        w[threadIdx.x] = (s >= 0 && s < SS) ? wv[s] : 0.f;
    }
    __syncthreads();
    int t = threadIdx.x;
    if (t >= 75) return;
    int e = t*4;
    float4 a = make_float4(0.f,0.f,0.f,0.f);
    if (s0 > 0) {
        float4 v = ld4h(O + (s0-1)*EE + e);
        a = make_float4(v.x*w[0], v.y*w[0], v.z*w[0], v.w*w[0]);
    }
    float4 v0 = ld4h(O + s0*EE + e);
    float4 bm = make_float4(v0.x*w[1], v0.y*w[1], v0.z*w[1], v0.w*w[1]);
#pragma unroll
    for (int i = 0; i < CROWS; i++) {
        int s = s0 + i;
        float4 cn = make_float4(0.f,0.f,0.f,0.f);
        if (s+1 < SS) {
            float4 v = ld4h(O + (s+1)*EE + e);
            float ww = w[i+2];
            cn = make_float4(v.x*ww, v.y*ww, v.z*ww, v.w*ww);
        }
        float4 sx = ld4h(Sx + s*EE + e);
        sx.x += (a.x + bm.x + cn.x) * (1.f/3.f);
        sx.y += (a.y + bm.y + cn.y) * (1.f/3.f);
        sx.z += (a.z + bm.z + cn.z) * (1.f/3.f);
        sx.w += (a.w + bm.w + cn.w) * (1.f/3.f);
        st4h(Sx + s*EE + e, sx);
        a = bm; bm = cn;
    }
}

// ---------------- fc1 GEMM: [512,1800] @ [1800,300]^T -> g_h ----------------
__global__ __launch_bounds__(256) void k_fc1(const float* __restrict__ fw) {
    int m0 = blockIdx.x * 64, n0 = blockIdx.y * 64;
    __shared__ float Xs[8][68];
    __shared__ float Ws2[8][68];
    int tid = threadIdx.x, ty = tid >> 4, tx = tid & 15;
    float acc[4][4];
#pragma unroll
    for (int u = 0; u < 4; u++)
#pragma unroll
        for (int v = 0; v < 4; v++) acc[u][v] = 0.f;

    for (int k0 = 0; k0 < FCIN; k0 += 8) {
        __syncthreads();
#pragma unroll 2
        for (int i = tid; i < 512; i += 256) {
            int r = i >> 3, kk = i & 7;
            Xs[kk][r] = g_x[(m0 + r)*FCIN + k0 + kk];
            int n = n0 + r;
            Ws2[kk][r] = (n < HH) ? fw[n*FCIN + k0 + kk] : 0.f;
        }
        __syncthreads();
#pragma unroll
        for (int kk = 0; kk < 8; kk++) {
            float4 xa = *(const float4*)&Xs[kk][ty*4];
            float4 wb = *(const float4*)&Ws2[kk][tx*4];
            float xv[4] = {xa.x, xa.y, xa.z, xa.w};
            float wvv[4] = {wb.x, wb.y, wb.z, wb.w};
#pragma unroll
            for (int u = 0; u < 4; u++)
#pragma unroll
                for (int v = 0; v < 4; v++) acc[u][v] += xv[u]*wvv[v];
        }
    }
#pragma unroll
    for (int u = 0; u < 4; u++) {
        int m = m0 + ty*4 + u;
#pragma unroll
        for (int v = 0; v < 4; v++) {
            int n = n0 + tx*4 + v;
            if (n < HH) g_h[m*HH + n] = acc[u][v];
        }
    }
}

// ---------------- LN + relu + fc2 + softmax ----------------
__device__ __forceinline__ float block_reduce512(float v, float* red) {
    int tid = threadIdx.x;
    red[tid] = v;
    __syncthreads();
    for (int off = 256; off > 0; off >>= 1) {
        if (tid < off) red[tid] += red[tid + off];
        __syncthreads();
    }
    float r = red[0];
    __syncthreads();
    return r;
}

__global__ __launch_bounds__(512) void k_head(const float* __restrict__ fc1b,
                                              const float* __restrict__ lng,
                                              const float* __restrict__ lnb,
                                              const float* __restrict__ fc2w,
                                              const float* __restrict__ fc2b,
                                              float* __restrict__ out) {
    int b = blockIdx.x, tid = threadIdx.x;
    __shared__ float red[512];
    bool act = tid < HH;
    float h = act ? (g_h[b*HH + tid] + fc1b[tid]) : 0.f;
    float mu = block_reduce512(h, red) * (1.f/HH);
    float d = act ? (h - mu) : 0.f;
    float var = block_reduce512(d*d, red) * (1.f/HH);
    float hn = 0.f;
    if (act) {
        hn = d * rsqrtf(var + 1e-5f) * lng[tid] + lnb[tid];
        hn = fmaxf(hn, 0.f);
    }
    float o0 = block_reduce512(act ? hn*fc2w[tid]      : 0.f, red);
    float o1 = block_reduce512(act ? hn*fc2w[HH + tid] : 0.f, red);
    if (tid == 0) {
        o0 += fc2b[0];
        o1 += fc2b[1];
        out[b*2 + 0] = o0;
        out[b*2 + 1] = o1;
        float m = fmaxf(o0, o1);
        float e0 = expf(o0 - m), e1 = expf(o1 - m);
        float inv = 1.f/(e0 + e1);
        out[BB*2 + b*2 + 0] = e0*inv;
        out[BB*2 + b*2 + 1] = e1*inv;
    }
}

// ---------------- launch ----------------
extern "C" void kernel_launch(void* const* d_in, const int* in_sizes, int n_in,
                              void* d_out, int out_size) {
    (void)in_sizes; (void)n_in; (void)out_size;
    const int*   seq1 = (const int*)d_in[0];
    const int*   seq2 = (const int*)d_in[1];
    const float* emb  = (const float*)d_in[2];
    const float* W    = (const float*)d_in[3];
    const float* cw   = (const float*)d_in[4];
    const float* cb   = (const float*)d_in[5];
    const float* fc1w = (const float*)d_in[6];
    const float* fc1b = (const float*)d_in[7];
    const float* lng  = (const float*)d_in[8];
    const float* lnb  = (const float*)d_in[9];
    const float* fc2w = (const float*)d_in[10];
    const float* fc2b = (const float*)d_in[11];
    float* out = (float*)d_out;

    const int SM_MATCH = (2*64*MPAD + 2*SS*MPAD + 64 + SS + 4*64 + 2*SS) * 4;  // ~33.5KB
    const int SM_FGEMM = (WOFF + 2*WBUF) * 4;                                   // ~69.6KB
    const int SM_CONV  = (2*(CROWS+2)*(EE+2) + 18) * 4;                         // ~43.6KB

    cudaFuncSetAttribute(k_match, cudaFuncAttributeMaxDynamicSharedMemorySize, SM_MATCH);
    cudaFuncSetAttribute(k_fgemm, cudaFuncAttributeMaxDynamicSharedMemorySize, SM_FGEMM);
    cudaFuncSetAttribute(k_conv,  cudaFuncAttributeMaxDynamicSharedMemorySize, SM_CONV);

    k_wprep<<<dim3(320, LL), 128>>>(W);
    k_gather<<<BB, 256>>>(seq1, seq2, emb);
    for (int l = 0; l < LL; l++) {
        int last = (l == LL-1);
        k_match<<<dim3(BB, 2), 256, SM_MATCH>>>(0, l);
        k_fgemm<<<dim3(BB, 2), 256, SM_FGEMM>>>(l);
        k_conv<<<dim3(BB, 8, 2), 320, SM_CONV>>>(cw, cb, l, last ? 0 : 1);
        if (!last) {
            k_match<<<dim3(BB, 2), 256, SM_MATCH>>>(1, l);
            k_pool<<<dim3(BB, 8, 2), 96>>>();
        }
    }
    k_fc1<<<dim3(8, 5), 256>>>(fc1w);
    k_head<<<BB, 512>>>(fc1b, lng, lnb, fc2w, fc2b, out);
}